// round 12
// baseline (speedup 1.0000x reference)
#include <cuda_runtime.h>
#include <math.h>

#define BB 2
#define NN 10000
#define EE 100000
#define HH 128
#define DINN 8
#define DBB 16
#define LL 2
#define NBB 3
#define ROWS_TOT (BB*NN)
#define ETILES ((EE+63)/64)
#define NTILES ((NN+63)/64)
#define DELTA_GRID 592
#define FIXG 128

// -------- scratch (device globals; no allocation anywhere) --------
__device__ float g_h[ROWS_TOT*HH];
__device__ float g_msum[ROWS_TOT*HH];
__device__ float g_Ga[NBB*ROWS_TOT*HH];   // per-k slabs
__device__ float g_Gb[NBB*ROWS_TOT*HH];
__device__ float g_p[ROWS_TOT*3];
__device__ float g_pd[ROWS_TOT*3];
__device__ float g_invdeg[NBB*NN];
__device__ int   g_dirty[NN];
__device__ int   g_newDirty[NN];
__device__ int   g_acnt[NBB];
__device__ int   g_alist[NBB*EE];
__device__ int   g_dcount;
__device__ int   g_dlist[NN];
// tf32-rounded weights, 30 slabs of 128x128:
//  0..5  mW2 | 6..11 pW1 | 12..23 mW1 (lk*2+half) | 24..27 uW1 (l*2+half) | 28..29 uW2
__device__ float g_Wt[30*HH*HH];

// silu(x) = 0.5*x*(1+tanh(x/2)) — 1 MUFU
__device__ __forceinline__ float siluf(float x){
  float t;
  asm("tanh.approx.f32 %0, %1;" : "=f"(t) : "f"(0.5f*x));
  return 0.5f*x*(1.0f+t);
}

__device__ __forceinline__ float tf32r(float x){
  unsigned u;
  asm("cvt.rna.tf32.f32 %0, %1;" : "=r"(u) : "f"(x));
  return __uint_as_float(u);
}

// m16n8k8 tf32 MMA, fp32 accumulate (base PTX, sm_80+)
__device__ __forceinline__ void mma8(float c[4],
    unsigned a0, unsigned a1, unsigned a2, unsigned a3,
    unsigned b0, unsigned b1){
  asm volatile(
    "mma.sync.aligned.m16n8k8.row.col.f32.tf32.tf32.f32 "
    "{%0,%1,%2,%3}, {%4,%5,%6,%7}, {%8,%9}, {%0,%1,%2,%3};"
    : "+f"(c[0]), "+f"(c[1]), "+f"(c[2]), "+f"(c[3])
    : "r"(a0), "r"(a1), "r"(a2), "r"(a3), "r"(b0), "r"(b1));
}

__device__ __forceinline__ void redv4(float* addr, float x, float y, float z, float w){
  asm volatile("red.global.add.v4.f32 [%0], {%1, %2, %3, %4};"
               :: "l"(addr), "f"(x), "f"(y), "f"(z), "f"(w) : "memory");
}

// 64x128 += sM(64xK=128, stride 132, tf32) @ B(128x128 row-major tf32), per-warp 64x16 slab
__device__ __forceinline__ void mma_accum64(const float* __restrict__ sM,
                                            const float* __restrict__ B,
                                            int w, int gid, int tig,
                                            float c[4][2][4]){
  #pragma unroll 4
  for(int k0=0; k0<HH; k0+=8){
    unsigned a[4][4];
    #pragma unroll
    for(int rt=0;rt<4;rt++){
      int r = rt*16;
      a[rt][0] = __float_as_uint(sM[(r+gid)*132   + k0+tig]);
      a[rt][1] = __float_as_uint(sM[(r+8+gid)*132 + k0+tig]);
      a[rt][2] = __float_as_uint(sM[(r+gid)*132   + k0+tig+4]);
      a[rt][3] = __float_as_uint(sM[(r+8+gid)*132 + k0+tig+4]);
    }
    #pragma unroll
    for(int ct=0;ct<2;ct++){
      int n = w*16 + ct*8 + gid;
      unsigned b0 = __float_as_uint(__ldg(&B[(k0+tig)*HH   + n]));
      unsigned b1r = __float_as_uint(__ldg(&B[(k0+tig+4)*HH + n]));
      #pragma unroll
      for(int rt=0;rt<4;rt++)
        mma8(c[rt][ct], a[rt][0],a[rt][1],a[rt][2],a[rt][3], b0,b1r);
    }
  }
}
__device__ __forceinline__ void frag_zero(float c[4][2][4]){
  #pragma unroll
  for(int rt=0;rt<4;rt++)
    #pragma unroll
    for(int ct=0;ct<2;ct++)
      #pragma unroll
      for(int q=0;q<4;q++) c[rt][ct][q]=0.f;
}

// ------------------- weight rounding -------------------
__global__ void k_round(const float* __restrict__ mW1, const float* __restrict__ mW2,
                        const float* __restrict__ pW1, const float* __restrict__ uW1,
                        const float* __restrict__ uW2){
  int gi = blockIdx.x*blockDim.x + threadIdx.x;
  if(gi >= 30*HH*HH) return;
  int slot = gi >> 14;
  int e    = gi & 16383;
  float v;
  if      (slot < 6)  v = mW2[(size_t)slot*16384 + e];
  else if (slot < 12) v = pW1[(size_t)(slot-6)*16384 + e];
  else if (slot < 24){ int s = slot-12; v = mW1[(size_t)(s>>1)*257*HH + (size_t)(s&1)*16384 + e]; }
  else if (slot < 28){ int s = slot-24; v = uW1[(size_t)(s>>1)*2*16384 + (size_t)(s&1)*16384 + e]; }
  else                v = uW2[(size_t)(slot-28)*16384 + e];
  g_Wt[gi] = tf32r(v);
}

// ------------------- small setup kernels -------------------
__global__ void k_deg_zero(){
  int i = blockIdx.x*blockDim.x + threadIdx.x;
  if(i < NBB*NN) g_invdeg[i] = 0.f;
  if(i < NN){ g_dirty[i] = 0; g_newDirty[i] = 0; }
}
__global__ void k_deg_count(const int* __restrict__ edst){
  int i = blockIdx.x*blockDim.x + threadIdx.x;
  if(i < NBB*EE){
    int k = i / EE;
    atomicAdd(&g_invdeg[k*NN + edst[i]], 1.f);
  }
}
__global__ void k_deg_fin(const int* __restrict__ ent){
  int i = blockIdx.x*blockDim.x + threadIdx.x;
  if(i < NBB*NN) g_invdeg[i] = 1.f / fmaxf(g_invdeg[i], 1.f);
  if(i < BB) g_dirty[ent[i]] = 1;
  if(i == 0) g_dcount = 0;
}

// merge dirty flags and (re)build dlist (runs after merge / deg_fin; dcount pre-reset)
__global__ void k_build_dlist(){
  int i = blockIdx.x*blockDim.x + threadIdx.x;
  if(i < NN){
    if(g_newDirty[i]) g_dirty[i] = 1;
    if(g_dirty[i]){
      int p = atomicAdd(&g_dcount, 1);
      g_dlist[p] = i;
    }
  }
}

__global__ void k_init_h(const float* __restrict__ base, const float* __restrict__ Win,
                         const float* __restrict__ b_in){
  int n = blockIdx.x, j = threadIdx.x;
  float acc = b_in[j];
  #pragma unroll
  for(int d=0; d<DBB; d++)
    acc = fmaf(__ldg(&base[n*DBB+d]), __ldg(&Win[d*HH+j]), acc);
  g_h[n*HH+j] = acc;
  g_h[(NN+n)*HH+j] = acc;
}

__global__ void k_add_dyn(const float* __restrict__ x, const float* __restrict__ Win,
                          const int* __restrict__ ent){
  int t = threadIdx.x;
  if(t < BB*HH){
    int b = t >> 7, j = t & (HH-1);
    float acc = 0.f;
    #pragma unroll
    for(int d=0; d<DINN; d++)
      acc = fmaf(x[b*DINN+d], Win[(DBB+d)*HH+j], acc);
    g_h[((size_t)b*NN + ent[b])*HH + j] += acc;
  }
}

__global__ void k_init_p(const float* __restrict__ bp){
  int i = blockIdx.x*blockDim.x + threadIdx.x;
  if(i < NN*3){ float v = bp[i]; g_p[i] = v; g_p[NN*3+i] = v; }
}

__global__ void k_zero_layer(){
  int i = blockIdx.x*blockDim.x + threadIdx.x;
  if(i < ROWS_TOT*HH) g_msum[i] = 0.f;
  if(i < ROWS_TOT*3)  g_pd[i]   = 0.f;
  if(i < NN)          g_newDirty[i] = 0;
  if(i < NBB)         g_acnt[i] = 0;
}

// merge b0 contributions into b1; copy h for newly-dirty (still-clean) rows; reset dcount.
// Does NOT write g_dirty (k_build_dlist does that afterwards) — avoids intra-launch race.
__global__ void k_merge(){
  int i = blockIdx.x*blockDim.x + threadIdx.x;
  if(i < NN*HH){
    g_msum[(size_t)NN*HH + i] += g_msum[i];
    int n = i >> 7;
    if(g_newDirty[n] && !g_dirty[n])
      g_h[(size_t)NN*HH + i] = g_h[i];   // b1 h was bitwise == b0 h; snapshot before update
  }
  if(i < NN*3)  g_pd[NN*3 + i] += g_pd[i];
  if(i == 0) g_dcount = 0;
}

__global__ void k_padd(){
  int i = blockIdx.x*blockDim.x + threadIdx.x;
  if(i < ROWS_TOT*3) g_p[i] += g_pd[i];
}

// build affected-edge lists for all 3 neighborhoods (g_dirty is layer-stable)
__global__ void k_buildA_all(const int* __restrict__ esrc, const int* __restrict__ edst){
  int i = blockIdx.x*blockDim.x + threadIdx.x;
  if(i < NBB*EE){
    int k = i / EE;
    int e = i - k*EE;
    if(g_dirty[esrc[i]] | g_dirty[edst[i]]){
      int pos = atomicAdd(&g_acnt[k], 1);
      g_alist[k*EE + pos] = e;
    }
  }
}

// ------------------- gagb for ALL 3 neighborhoods (tf32 MMA, batch-0 rows) -------------------
__global__ void __launch_bounds__(256,2) k_gagb3(int l){
  __shared__ float sM[64*132];
  int tid = threadIdx.x;
  int w = tid >> 5, lane = tid & 31;
  int gid = lane >> 2, tig = lane & 3;
  int base = blockIdx.x*64;

  {
    int c4 = tid & 31, rs = tid >> 5;
    #pragma unroll
    for(int it=0; it<8; it++){
      int r = it*8 + rs;
      int rg = base + r;
      float4 v = make_float4(0.f,0.f,0.f,0.f);
      if(rg < NN){
        v = __ldg((const float4*)(g_h + (size_t)rg*HH) + c4);
        v.x = tf32r(v.x); v.y = tf32r(v.y); v.z = tf32r(v.z); v.w = tf32r(v.w);
      }
      *(float4*)(sM + r*132 + c4*4) = v;
    }
  }
  __syncthreads();

  float c[4][2][4];
  for(int k=0; k<NBB; k++){
    int lk = l*NBB + k;
    #pragma unroll
    for(int half=0; half<2; half++){
      frag_zero(c);
      mma_accum64(sM, g_Wt + (size_t)(12 + lk*2 + half)*16384, w, gid, tig, c);
      float* out = (half ? g_Gb : g_Ga) + (size_t)k*ROWS_TOT*HH;
      #pragma unroll
      for(int rt=0;rt<4;rt++){
        #pragma unroll
        for(int ct=0;ct<2;ct++){
          int col0 = w*16 + ct*8 + 2*tig;
          int r0 = base + rt*16 + gid, r1 = r0 + 8;
          if(r0 < NN) *(float2*)(out + (size_t)r0*HH + col0) = make_float2(c[rt][ct][0], c[rt][ct][1]);
          if(r1 < NN) *(float2*)(out + (size_t)r1*HH + col0) = make_float2(c[rt][ct][2], c[rt][ct][3]);
        }
      }
    }
  }
}

// dirty b1 rows: exact fp32 recompute for all 3 k (separate launch after k_gagb3)
__global__ void __launch_bounds__(128) k_gagb_fix3(const float* __restrict__ mW1, int l){
  __shared__ float sh[HH];
  int j = threadIdx.x;
  int cnt = g_dcount;
  for(int i = blockIdx.x; i < cnt; i += FIXG){
    int n = g_dlist[i];
    sh[j] = g_h[(size_t)(NN+n)*HH + j];
    __syncthreads();
    for(int k=0; k<NBB; k++){
      const float* W1 = mW1 + (size_t)(l*NBB + k)*257*HH;
      float a = 0.f, bv = 0.f;
      #pragma unroll 4
      for(int kk=0; kk<HH; kk++){
        float hv = sh[kk];
        a  = fmaf(hv, __ldg(&W1[kk*HH + j]), a);
        bv = fmaf(hv, __ldg(&W1[(128+kk)*HH + j]), bv);
      }
      size_t row = ((size_t)k*ROWS_TOT + NN + n)*HH;
      g_Ga[row + j] = a;
      g_Gb[row + j] = bv;
    }
    __syncthreads();
  }
}

// ------------------- tf32-MMA fused edge kernel (batch 0): 64 edges/block -------------------
__global__ void __launch_bounds__(256,2) k_edge(
    const float* __restrict__ W1r, const float* __restrict__ b1,
    const float* __restrict__ b2,  const float* __restrict__ pb1,
    const float* __restrict__ pW2, const float* __restrict__ pb2,
    const int* __restrict__ esrc,  const int* __restrict__ edst,
    int lk, int kdeg){
  __shared__ float sM[64*132];
  __shared__ int   sDst[64];
  __shared__ int   sSrc[64];
  __shared__ float sInv[64];
  __shared__ float sD2[64];
  __shared__ float sRel[64*3];
  __shared__ float sCoef[64];
  __shared__ float sB2[HH];
  __shared__ float sPB1[HH];
  __shared__ float sPW2[HH];

  const float* Ga = g_Ga + (size_t)kdeg*ROWS_TOT*HH;
  const float* Gb = g_Gb + (size_t)kdeg*ROWS_TOT*HH;

  int tid = threadIdx.x;
  int w = tid >> 5, lane = tid & 31;
  int gid = lane >> 2, tig = lane & 3;
  int base = blockIdx.x*64;

  if(tid < 64){
    int e = base + tid;
    bool v = e < EE;
    int ee = v ? e : 0;
    int ds = edst[ee], sr = esrc[ee];
    float rx = g_p[ds*3+0] - g_p[sr*3+0];
    float ry = g_p[ds*3+1] - g_p[sr*3+1];
    float rz = g_p[ds*3+2] - g_p[sr*3+2];
    sRel[tid*3+0] = rx; sRel[tid*3+1] = ry; sRel[tid*3+2] = rz;
    sD2[tid]  = rx*rx + ry*ry + rz*rz;
    sInv[tid] = v ? g_invdeg[kdeg*NN + ds] : 0.f;
    sDst[tid] = ds;
    sSrc[tid] = sr;
    sCoef[tid] = 0.f;
  }
  if(tid < HH){
    sB2[tid]  = b2[tid];
    sPB1[tid] = pb1[tid];
    sPW2[tid] = pW2[tid];
  }
  __syncthreads();

  // stage m = silu(Ga[dst] + Gb[src] + d2*W1r + b1), tf32-rounded
  {
    int c4 = tid & 31, rs = tid >> 5;
    float4 w4 = __ldg((const float4*)W1r + c4);
    float4 bb = __ldg((const float4*)b1  + c4);
    #pragma unroll
    for(int it=0; it<8; it++){
      int r = it*8 + rs;
      float4 ga = __ldg((const float4*)(Ga + (size_t)sDst[r]*HH) + c4);
      float4 gb = __ldg((const float4*)(Gb + (size_t)sSrc[r]*HH) + c4);
      float d2 = sD2[r];
      float4 o;
      o.x = tf32r(siluf(ga.x + gb.x + d2*w4.x + bb.x));
      o.y = tf32r(siluf(ga.y + gb.y + d2*w4.y + bb.y));
      o.z = tf32r(siluf(ga.z + gb.z + d2*w4.z + bb.z));
      o.w = tf32r(siluf(ga.w + gb.w + d2*w4.w + bb.w));
      *(float4*)(sM + r*132 + c4*4) = o;
    }
  }
  __syncthreads();

  // ---- GEMM1: m @ W2 ----
  float c[4][2][4];
  frag_zero(c);
  mma_accum64(sM, g_Wt + (size_t)lk*16384, w, gid, tig, c);
  __syncthreads();

  // ---- epilogue1: m2 = silu(D1 + b2); scatter m_sum (v4 red via pair shfl); m2 -> sM ----
  #pragma unroll
  for(int rt=0;rt<4;rt++){
    #pragma unroll
    for(int ct=0;ct<2;ct++){
      int col0 = w*16 + ct*8 + 2*tig;
      int r0 = rt*16 + gid, r1 = r0 + 8;
      float v00 = siluf(c[rt][ct][0] + sB2[col0]);
      float v01 = siluf(c[rt][ct][1] + sB2[col0+1]);
      float v10 = siluf(c[rt][ct][2] + sB2[col0]);
      float v11 = siluf(c[rt][ct][3] + sB2[col0+1]);
      float i0 = sInv[r0], i1 = sInv[r1];
      float s00 = v00*i0, s01 = v01*i0;
      float s10 = v10*i1, s11 = v11*i1;
      float o00 = __shfl_xor_sync(0xffffffffu, s00, 1);
      float o01 = __shfl_xor_sync(0xffffffffu, s01, 1);
      float o10 = __shfl_xor_sync(0xffffffffu, s10, 1);
      float o11 = __shfl_xor_sync(0xffffffffu, s11, 1);
      if((tig & 1) == 0){
        int cb = w*16 + ct*8 + 4*(tig>>1);
        redv4(g_msum + (size_t)sDst[r0]*HH + cb, s00, s01, o00, o01);
        redv4(g_msum + (size_t)sDst[r1]*HH + cb, s10, s11, o10, o11);
      }
      *(float2*)(sM + r0*132 + col0) = make_float2(tf32r(v00), tf32r(v01));
      *(float2*)(sM + r1*132 + col0) = make_float2(tf32r(v10), tf32r(v11));
    }
  }
  __syncthreads();

  // ---- GEMM2: m2 @ pW1 ----
  frag_zero(c);
  mma_accum64(sM, g_Wt + (size_t)(6+lk)*16384, w, gid, tig, c);

  // ---- epilogue2: coef partials = silu(D2 + pb1) . pW2 ----
  float rsum[4][2];
  #pragma unroll
  for(int rt=0;rt<4;rt++){ rsum[rt][0]=0.f; rsum[rt][1]=0.f; }
  #pragma unroll
  for(int rt=0;rt<4;rt++){
    #pragma unroll
    for(int ct=0;ct<2;ct++){
      int col0 = w*16 + ct*8 + 2*tig;
      float w0 = sPW2[col0], w1 = sPW2[col0+1];
      float p0 = sPB1[col0], p1 = sPB1[col0+1];
      rsum[rt][0] = fmaf(siluf(c[rt][ct][0]+p0), w0,
                    fmaf(siluf(c[rt][ct][1]+p1), w1, rsum[rt][0]));
      rsum[rt][1] = fmaf(siluf(c[rt][ct][2]+p0), w0,
                    fmaf(siluf(c[rt][ct][3]+p1), w1, rsum[rt][1]));
    }
  }
  #pragma unroll
  for(int off=1; off<4; off<<=1){
    #pragma unroll
    for(int rt=0;rt<4;rt++){
      rsum[rt][0] += __shfl_xor_sync(0xffffffffu, rsum[rt][0], off);
      rsum[rt][1] += __shfl_xor_sync(0xffffffffu, rsum[rt][1], off);
    }
  }
  if(tig == 0){
    #pragma unroll
    for(int rt=0;rt<4;rt++){
      atomicAdd(&sCoef[rt*16 + gid],     rsum[rt][0]);
      atomicAdd(&sCoef[rt*16 + 8 + gid], rsum[rt][1]);
    }
  }
  __syncthreads();

  if(tid < 64){
    float s = (sCoef[tid] + __ldg(pb2)) * sInv[tid];
    int row = sDst[tid];
    atomicAdd(&g_pd[row*3+0], sRel[tid*3+0]*s);
    atomicAdd(&g_pd[row*3+1], sRel[tid*3+1]*s);
    atomicAdd(&g_pd[row*3+2], sRel[tid*3+2]*s);
  }
}

// ------------------- batch-1 delta kernel (clean-node reads redirected to b0 rows) -------------------
__global__ void __launch_bounds__(128) k_delta(
    const float* __restrict__ W1r, const float* __restrict__ b1,
    const float* __restrict__ W2,  const float* __restrict__ b2,
    const float* __restrict__ pW1, const float* __restrict__ pb1,
    const float* __restrict__ pW2, const float* __restrict__ pb2,
    const int* __restrict__ esrc,  const int* __restrict__ edst, int kdeg){
  __shared__ float sm1[2][HH];
  __shared__ float sm2[2][HH];
  __shared__ float sred[8];
  const float* Ga = g_Ga + (size_t)kdeg*ROWS_TOT*HH;
  const float* Gb = g_Gb + (size_t)kdeg*ROWS_TOT*HH;
  int j = threadIdx.x;
  int cnt = g_acnt[kdeg];
  const int* alist = g_alist + (size_t)kdeg*EE;
  for(int idx = blockIdx.x; idx < cnt; idx += DELTA_GRID){
    int e = alist[idx];
    int ds = edst[e], sr = esrc[e];
    float inv = g_invdeg[kdeg*NN + ds];
    int dDirty = g_dirty[ds], sDirty = g_dirty[sr];
    float rel[2][3], d2v[2];
    #pragma unroll
    for(int b=0;b<2;b++){
      int dr = b*NN + ds, srr = b*NN + sr;
      rel[b][0] = g_p[dr*3+0] - g_p[srr*3+0];
      rel[b][1] = g_p[dr*3+1] - g_p[srr*3+1];
      rel[b][2] = g_p[dr*3+2] - g_p[srr*3+2];
      d2v[b] = rel[b][0]*rel[b][0] + rel[b][1]*rel[b][1] + rel[b][2]*rel[b][2];
      // b1 Ga/Gb rows are materialized only for dirty nodes; clean == b0 bitwise
      int ga_row = (b==1 && !dDirty) ? ds : dr;
      int gb_row = (b==1 && !sDirty) ? sr : srr;
      sm1[b][j] = siluf(Ga[(size_t)ga_row*HH+j] + Gb[(size_t)gb_row*HH+j]
                        + d2v[b]*__ldg(&W1r[j]) + __ldg(&b1[j]));
    }
    __syncthreads();
    float acc0 = 0.f, acc1 = 0.f;
    #pragma unroll 4
    for(int k=0;k<HH;k++){
      float w = __ldg(&W2[k*HH+j]);
      acc0 = fmaf(sm1[0][k], w, acc0);
      acc1 = fmaf(sm1[1][k], w, acc1);
    }
    float bb = __ldg(&b2[j]);
    float m20 = siluf(acc0 + bb);
    float m21 = siluf(acc1 + bb);
    atomicAdd(&g_msum[(size_t)(NN+ds)*HH + j], (m21 - m20)*inv);
    sm2[0][j] = m20; sm2[1][j] = m21;
    __syncthreads();
    acc0 = 0.f; acc1 = 0.f;
    #pragma unroll 4
    for(int k=0;k<HH;k++){
      float w = __ldg(&pW1[k*HH+j]);
      acc0 = fmaf(sm2[0][k], w, acc0);
      acc1 = fmaf(sm2[1][k], w, acc1);
    }
    float pb = __ldg(&pb1[j]);
    float w2 = __ldg(&pW2[j]);
    float c0 = siluf(acc0 + pb) * w2;
    float c1 = siluf(acc1 + pb) * w2;
    #pragma unroll
    for(int off=16; off; off>>=1){
      c0 += __shfl_xor_sync(0xffffffffu, c0, off);
      c1 += __shfl_xor_sync(0xffffffffu, c1, off);
    }
    int wwid = j >> 5;
    if((j & 31) == 0){ sred[wwid] = c0; sred[4+wwid] = c1; }
    __syncthreads();
    if(j == 0){
      float pb2v = __ldg(pb2);
      float coef0 = sred[0]+sred[1]+sred[2]+sred[3] + pb2v;
      float coef1 = sred[4]+sred[5]+sred[6]+sred[7] + pb2v;
      atomicAdd(&g_pd[(NN+ds)*3+0], (rel[1][0]*coef1 - rel[0][0]*coef0)*inv);
      atomicAdd(&g_pd[(NN+ds)*3+1], (rel[1][1]*coef1 - rel[0][1]*coef0)*inv);
      atomicAdd(&g_pd[(NN+ds)*3+2], (rel[1][2]*coef1 - rel[0][2]*coef0)*inv);
      g_newDirty[ds] = 1;
    }
    __syncthreads();
  }
}

// ------------------- node update (tf32 MMA, batch-0 rows) -------------------
__global__ void __launch_bounds__(256,2) k_update(
    const float* __restrict__ bu1, const float* __restrict__ bu2, int l){
  __shared__ float sM[64*132];
  __shared__ float sB1[HH];
  __shared__ float sB2v[HH];
  int tid = threadIdx.x;
  int w = tid >> 5, lane = tid & 31;
  int gid = lane >> 2, tig = lane & 3;
  int base = blockIdx.x*64;
  int c4 = tid & 31, rs = tid >> 5;

  if(tid < HH){ sB1[tid] = bu1[tid]; sB2v[tid] = bu2[tid]; }

  float c[4][2][4];
  frag_zero(c);

  #pragma unroll
  for(int it=0; it<8; it++){
    int r = it*8 + rs;
    int rg = base + r;
    float4 v = make_float4(0.f,0.f,0.f,0.f);
    if(rg < NN){
      v = __ldg((const float4*)(g_h + (size_t)rg*HH) + c4);
      v.x = tf32r(v.x); v.y = tf32r(v.y); v.z = tf32r(v.z); v.w = tf32r(v.w);
    }
    *(float4*)(sM + r*132 + c4*4) = v;
  }
  __syncthreads();
  mma_accum64(sM, g_Wt + (size_t)(24 + l*2)*16384, w, gid, tig, c);
  __syncthreads();

  #pragma unroll
  for(int it=0; it<8; it++){
    int r = it*8 + rs;
    int rg = base + r;
    float4 v = make_float4(0.f,0.f,0.f,0.f);
    if(rg < NN){
      v = __ldg((const float4*)(g_msum + (size_t)rg*HH) + c4);
      v.x = tf32r(v.x); v.y = tf32r(v.y); v.z = tf32r(v.z); v.w = tf32r(v.w);
    }
    *(float4*)(sM + r*132 + c4*4) = v;
  }
  __syncthreads();
  mma_accum64(sM, g_Wt + (size_t)(24 + l*2 + 1)*16384, w, gid, tig, c);
  __syncthreads();

  #pragma unroll
  for(int rt=0;rt<4;rt++){
    #pragma unroll
    for(int ct=0;ct<2;ct++){
      int col0 = w*16 + ct*8 + 2*tig;
      int r0 = rt*16 + gid, r1 = r0 + 8;
      *(float2*)(sM + r0*132 + col0) = make_float2(
          tf32r(siluf(c[rt][ct][0] + sB1[col0])),
          tf32r(siluf(c[rt][ct][1] + sB1[col0+1])));
      *(float2*)(sM + r1*132 + col0) = make_float2(
          tf32r(siluf(c[rt][ct][2] + sB1[col0])),
          tf32r(siluf(c[rt][ct][3] + sB1[col0+1])));
    }
  }
  __syncthreads();

  frag_zero(c);
  mma_accum64(sM, g_Wt + (size_t)(28 + l)*16384, w, gid, tig, c);

  #pragma unroll
  for(int rt=0;rt<4;rt++){
    #pragma unroll
    for(int ct=0;ct<2;ct++){
      int col0 = w*16 + ct*8 + 2*tig;
      int r0 = base + rt*16 + gid, r1 = r0 + 8;
      if(r0 < NN){
        float2 hv = *(float2*)(g_h + (size_t)r0*HH + col0);
        hv.x += c[rt][ct][0] + sB2v[col0];
        hv.y += c[rt][ct][1] + sB2v[col0+1];
        *(float2*)(g_h + (size_t)r0*HH + col0) = hv;
      }
      if(r1 < NN){
        float2 hv = *(float2*)(g_h + (size_t)r1*HH + col0);
        hv.x += c[rt][ct][2] + sB2v[col0];
        hv.y += c[rt][ct][3] + sB2v[col0+1];
        *(float2*)(g_h + (size_t)r1*HH + col0) = hv;
      }
    }
  }
}

// dirty b1 rows: exact fp32 update (h b1 dirty rows maintained; newly-dirty snapshotted in merge)
__global__ void __launch_bounds__(128) k_update_fix(
    const float* __restrict__ Wu1, const float* __restrict__ bu1,
    const float* __restrict__ Wu2, const float* __restrict__ bu2){
  __shared__ float sh[HH];
  __shared__ float sm[HH];
  __shared__ float st[HH];
  int j = threadIdx.x;
  int cnt = g_dcount;
  for(int i = blockIdx.x; i < cnt; i += FIXG){
    int n = g_dlist[i];
    size_t row = (size_t)(NN+n)*HH;
    sh[j] = g_h[row + j];
    sm[j] = g_msum[row + j];
    __syncthreads();
    float acc = __ldg(&bu1[j]);
    #pragma unroll 4
    for(int kk=0; kk<HH; kk++){
      acc = fmaf(sh[kk], __ldg(&Wu1[kk*HH + j]), acc);
      acc = fmaf(sm[kk], __ldg(&Wu1[(128+kk)*HH + j]), acc);
    }
    st[j] = siluf(acc);
    __syncthreads();
    float o = __ldg(&bu2[j]);
    #pragma unroll 4
    for(int kk=0; kk<HH; kk++)
      o = fmaf(st[kk], __ldg(&Wu2[kk*HH + j]), o);
    g_h[row + j] = sh[j] + o;
    __syncthreads();
  }
}

// ------------------- readout -------------------
__global__ void k_readout(const float* __restrict__ W1, const float* __restrict__ b1,
                          const float* __restrict__ W2, const float* __restrict__ b2,
                          const int* __restrict__ ent, float* __restrict__ out){
  __shared__ float se[HH];
  __shared__ float sred[HH];
  int j = threadIdx.x;
  for(int b=0; b<BB; b++){
    int row = b*NN + ent[b];
    se[j] = g_h[(size_t)row*HH + j];
    __syncthreads();
    float acc = b1[j];
    #pragma unroll 4
    for(int i=0;i<HH;i++) acc = fmaf(se[i], W1[i*HH+j], acc);
    sred[j] = siluf(acc) * W2[j];
    __syncthreads();
    for(int s=64; s>0; s>>=1){
      if(j<s) sred[j] += sred[j+s];
      __syncthreads();
    }
    if(j==0) out[b] = sred[0] + b2[0];
    __syncthreads();
  }
}

// ------------------- launch -------------------
extern "C" void kernel_launch(void* const* d_in, const int* in_sizes, int n_in,
                              void* d_out, int out_size){
  (void)in_sizes; (void)n_in; (void)out_size;
  const float* x     = (const float*)d_in[0];
  const float* basef = (const float*)d_in[1];
  const float* basep = (const float*)d_in[2];
  const float* Win   = (const float*)d_in[3];
  const float* b_in  = (const float*)d_in[4];
  const float* mW1   = (const float*)d_in[5];
  const float* mb1   = (const float*)d_in[6];
  const float* mW2   = (const float*)d_in[7];
  const float* mb2   = (const float*)d_in[8];
  const float* pW1   = (const float*)d_in[9];
  const float* pb1   = (const float*)d_in[10];
  const float* pW2   = (const float*)d_in[11];
  const float* pb2   = (const float*)d_in[12];
  const float* uW1   = (const float*)d_in[13];
  const float* ub1   = (const float*)d_in[14];
  const float* uW2   = (const float*)d_in[15];
  const float* ub2   = (const float*)d_in[16];
  const float* oW1   = (const float*)d_in[17];
  const float* ob1   = (const float*)d_in[18];
  const float* oW2   = (const float*)d_in[19];
  const float* ob2   = (const float*)d_in[20];
  const int*   ent   = (const int*)d_in[21];
  const int*   esrc  = (const int*)d_in[22];
  const int*   edst  = (const int*)d_in[23];
  float* out = (float*)d_out;

  k_round<<<(30*HH*HH+255)/256, 256>>>(mW1, mW2, pW1, uW1, uW2);

  k_deg_zero <<<(NBB*NN+255)/256, 256>>>();
  k_deg_count<<<(NBB*EE+255)/256, 256>>>(edst);
  k_deg_fin  <<<(NBB*NN+255)/256, 256>>>(ent);
  k_build_dlist<<<(NN+255)/256, 256>>>();

  k_init_h <<<NN, 128>>>(basef, Win, b_in);
  k_add_dyn<<<1, 256>>>(x, Win, ent);
  k_init_p <<<(NN*3+255)/256, 256>>>(basep);

  for(int l=0; l<LL; l++){
    k_zero_layer<<<(ROWS_TOT*HH+255)/256, 256>>>();
    k_buildA_all<<<(NBB*EE+255)/256, 256>>>(esrc, edst);
    k_gagb3<<<NTILES, 256>>>(l);
    k_gagb_fix3<<<FIXG, 128>>>(mW1, l);
    for(int k=0; k<NBB; k++){
      int lk = l*NBB + k;
      const float* W1lk = mW1 + (size_t)lk*257*HH;
      k_edge<<<ETILES, 256>>>(
          W1lk + 256*HH,
          mb1 + (size_t)lk*HH,
          mb2 + (size_t)lk*HH,
          pb1 + (size_t)lk*HH,
          pW2 + (size_t)lk*HH,
          pb2 + lk,
          esrc + (size_t)k*EE,
          edst + (size_t)k*EE,
          lk, k);
      k_delta<<<DELTA_GRID, 128>>>(
          W1lk + 256*HH,
          mb1 + (size_t)lk*HH,
          mW2 + (size_t)lk*HH*HH,
          mb2 + (size_t)lk*HH,
          pW1 + (size_t)lk*HH*HH,
          pb1 + (size_t)lk*HH,
          pW2 + (size_t)lk*HH,
          pb2 + lk,
          esrc + (size_t)k*EE,
          edst + (size_t)k*EE,
          k);
    }
    k_merge<<<(NN*HH+255)/256, 256>>>();
    k_build_dlist<<<(NN+255)/256, 256>>>();
    k_update<<<NTILES, 256>>>(
        ub1 + (size_t)l*HH,
        ub2 + (size_t)l*HH,
        l);
    k_update_fix<<<FIXG, 128>>>(
        uW1 + (size_t)l*2*HH*HH,
        ub1 + (size_t)l*HH,
        uW2 + (size_t)l*HH*HH,
        ub2 + (size_t)l*HH);
    k_padd<<<(ROWS_TOT*3+255)/256, 256>>>();
  }

  k_readout<<<1, 128>>>(oW1, ob1, oW2, ob2, ent, out);
}

// round 13
// speedup vs baseline: 1.0648x; 1.0648x over previous
#include <cuda_runtime.h>
#include <math.h>

#define BB 2
#define NN 10000
#define EE 100000
#define HH 128
#define DINN 8
#define DBB 16
#define LL 2
#define NBB 3
#define ROWS_TOT (BB*NN)
#define ETILES ((EE+63)/64)
#define NTILES ((NN+63)/64)
#define DELTA_GRID 592
#define FIXG 128
#define CPB ((NN*32+255)/256)

// -------- scratch (device globals; no allocation anywhere) --------
__device__ float g_h[ROWS_TOT*HH];
__device__ float g_msum[ROWS_TOT*HH];
__device__ float g_Ga[ROWS_TOT*HH];
__device__ float g_Gb[ROWS_TOT*HH];
__device__ float g_p[ROWS_TOT*3];
__device__ float g_pd[ROWS_TOT*3];
__device__ float g_invdeg[NBB*NN];
__device__ int   g_dirty[NN];
__device__ int   g_newDirty[NN];
__device__ int   g_acnt[NBB];
__device__ int   g_alist[NBB*EE];
__device__ int   g_dcount;
__device__ int   g_dlist[NN];
// tf32-rounded weights, 30 slabs of 128x128:
//  0..5  mW2 | 6..11 pW1 | 12..23 mW1 (lk*2+half) | 24..27 uW1 (l*2+half) | 28..29 uW2
__device__ float g_Wt[30*HH*HH];

// silu(x) = 0.5*x*(1+tanh(x/2)) — 1 MUFU
__device__ __forceinline__ float siluf(float x){
  float t;
  asm("tanh.approx.f32 %0, %1;" : "=f"(t) : "f"(0.5f*x));
  return 0.5f*x*(1.0f+t);
}

__device__ __forceinline__ float tf32r(float x){
  unsigned u;
  asm("cvt.rna.tf32.f32 %0, %1;" : "=r"(u) : "f"(x));
  return __uint_as_float(u);
}

// m16n8k8 tf32 MMA, fp32 accumulate (base PTX, sm_80+)
__device__ __forceinline__ void mma8(float c[4],
    unsigned a0, unsigned a1, unsigned a2, unsigned a3,
    unsigned b0, unsigned b1){
  asm volatile(
    "mma.sync.aligned.m16n8k8.row.col.f32.tf32.tf32.f32 "
    "{%0,%1,%2,%3}, {%4,%5,%6,%7}, {%8,%9}, {%0,%1,%2,%3};"
    : "+f"(c[0]), "+f"(c[1]), "+f"(c[2]), "+f"(c[3])
    : "r"(a0), "r"(a1), "r"(a2), "r"(a3), "r"(b0), "r"(b1));
}

__device__ __forceinline__ void redv4(float* addr, float x, float y, float z, float w){
  asm volatile("red.global.add.v4.f32 [%0], {%1, %2, %3, %4};"
               :: "l"(addr), "f"(x), "f"(y), "f"(z), "f"(w) : "memory");
}

// 64x128 += sM(64xK=128, stride 132, tf32) @ B(128x128 row-major tf32), per-warp 64x16 slab
__device__ __forceinline__ void mma_accum64(const float* __restrict__ sM,
                                            const float* __restrict__ B,
                                            int w, int gid, int tig,
                                            float c[4][2][4]){
  #pragma unroll 4
  for(int k0=0; k0<HH; k0+=8){
    unsigned a[4][4];
    #pragma unroll
    for(int rt=0;rt<4;rt++){
      int r = rt*16;
      a[rt][0] = __float_as_uint(sM[(r+gid)*132   + k0+tig]);
      a[rt][1] = __float_as_uint(sM[(r+8+gid)*132 + k0+tig]);
      a[rt][2] = __float_as_uint(sM[(r+gid)*132   + k0+tig+4]);
      a[rt][3] = __float_as_uint(sM[(r+8+gid)*132 + k0+tig+4]);
    }
    #pragma unroll
    for(int ct=0;ct<2;ct++){
      int n = w*16 + ct*8 + gid;
      unsigned b0 = __float_as_uint(__ldg(&B[(k0+tig)*HH   + n]));
      unsigned b1r = __float_as_uint(__ldg(&B[(k0+tig+4)*HH + n]));
      #pragma unroll
      for(int rt=0;rt<4;rt++)
        mma8(c[rt][ct], a[rt][0],a[rt][1],a[rt][2],a[rt][3], b0,b1r);
    }
  }
}
__device__ __forceinline__ void frag_zero(float c[4][2][4]){
  #pragma unroll
  for(int rt=0;rt<4;rt++)
    #pragma unroll
    for(int ct=0;ct<2;ct++)
      #pragma unroll
      for(int q=0;q<4;q++) c[rt][ct][q]=0.f;
}

// ------------------- weight rounding -------------------
__global__ void k_round(const float* __restrict__ mW1, const float* __restrict__ mW2,
                        const float* __restrict__ pW1, const float* __restrict__ uW1,
                        const float* __restrict__ uW2){
  int gi = blockIdx.x*blockDim.x + threadIdx.x;
  if(gi >= 30*HH*HH) return;
  int slot = gi >> 14;
  int e    = gi & 16383;
  float v;
  if      (slot < 6)  v = mW2[(size_t)slot*16384 + e];
  else if (slot < 12) v = pW1[(size_t)(slot-6)*16384 + e];
  else if (slot < 24){ int s = slot-12; v = mW1[(size_t)(s>>1)*257*HH + (size_t)(s&1)*16384 + e]; }
  else if (slot < 28){ int s = slot-24; v = uW1[(size_t)(s>>1)*2*16384 + (size_t)(s&1)*16384 + e]; }
  else                v = uW2[(size_t)(slot-28)*16384 + e];
  g_Wt[gi] = tf32r(v);
}

// ------------------- small setup kernels -------------------
__global__ void k_deg_zero(){
  int i = blockIdx.x*blockDim.x + threadIdx.x;
  if(i < NBB*NN) g_invdeg[i] = 0.f;
  if(i < NN) g_dirty[i] = 0;
}
__global__ void k_deg_count(const int* __restrict__ edst){
  int i = blockIdx.x*blockDim.x + threadIdx.x;
  if(i < NBB*EE){
    int k = i / EE;
    atomicAdd(&g_invdeg[k*NN + edst[i]], 1.f);
  }
}
__global__ void k_deg_fin(const int* __restrict__ ent){
  int i = blockIdx.x*blockDim.x + threadIdx.x;
  if(i < NBB*NN) g_invdeg[i] = 1.f / fmaxf(g_invdeg[i], 1.f);
  if(i < BB) g_dirty[ent[i]] = 1;
  if(i == 0) g_dcount = 0;
}

__global__ void k_build_dlist(){
  int i = blockIdx.x*blockDim.x + threadIdx.x;
  if(i < NN && g_dirty[i]){
    int p = atomicAdd(&g_dcount, 1);
    g_dlist[p] = i;
  }
}

__global__ void k_init_h(const float* __restrict__ base, const float* __restrict__ Win,
                         const float* __restrict__ b_in){
  int n = blockIdx.x, j = threadIdx.x;
  float acc = b_in[j];
  #pragma unroll
  for(int d=0; d<DBB; d++)
    acc = fmaf(__ldg(&base[n*DBB+d]), __ldg(&Win[d*HH+j]), acc);
  g_h[n*HH+j] = acc;
  g_h[(NN+n)*HH+j] = acc;
}

__global__ void k_add_dyn(const float* __restrict__ x, const float* __restrict__ Win,
                          const int* __restrict__ ent){
  int t = threadIdx.x;
  if(t < BB*HH){
    int b = t >> 7, j = t & (HH-1);
    float acc = 0.f;
    #pragma unroll
    for(int d=0; d<DINN; d++)
      acc = fmaf(x[b*DINN+d], Win[(DBB+d)*HH+j], acc);
    g_h[((size_t)b*NN + ent[b])*HH + j] += acc;
  }
}

__global__ void k_init_p(const float* __restrict__ bp){
  int i = blockIdx.x*blockDim.x + threadIdx.x;
  if(i < NN*3){ float v = bp[i]; g_p[i] = v; g_p[NN*3+i] = v; }
}

__global__ void k_zero_layer(){
  int i = blockIdx.x*blockDim.x + threadIdx.x;
  if(i < ROWS_TOT*HH) g_msum[i] = 0.f;
  if(i < ROWS_TOT*3)  g_pd[i]   = 0.f;
  if(i < NN)          g_newDirty[i] = 0;
  if(i < NBB)         g_acnt[i] = 0;
}

// merge b0 contributions into b1 regions; merge dirty flags; reset dcount
__global__ void k_merge(){
  int i = blockIdx.x*blockDim.x + threadIdx.x;
  if(i < NN*HH) g_msum[(size_t)NN*HH + i] += g_msum[i];
  if(i < NN*3)  g_pd[NN*3 + i] += g_pd[i];
  if(i < NN){ if(g_newDirty[i]) g_dirty[i] = 1; }
  if(i == 0) g_dcount = 0;
}

__global__ void k_padd(){
  int i = blockIdx.x*blockDim.x + threadIdx.x;
  if(i < ROWS_TOT*3) g_p[i] += g_pd[i];
}

// build affected-edge lists for all 3 neighborhoods (g_dirty is layer-stable)
__global__ void k_buildA_all(const int* __restrict__ esrc, const int* __restrict__ edst){
  int i = blockIdx.x*blockDim.x + threadIdx.x;
  if(i < NBB*EE){
    int k = i / EE;
    int e = i - k*EE;
    if(g_dirty[esrc[i]] | g_dirty[edst[i]]){
      int pos = atomicAdd(&g_acnt[k], 1);
      g_alist[k*EE + pos] = e;
    }
  }
}

// ------------------- gagb (tf32 MMA, batch-0 rows) — producer only -------------------
__global__ void __launch_bounds__(256,2) k_gagb(int lk){
  __shared__ float sM[64*132];
  int tid = threadIdx.x;
  int w = tid >> 5, lane = tid & 31;
  int gid = lane >> 2, tig = lane & 3;
  int base = blockIdx.x*64;

  {
    int c4 = tid & 31, rs = tid >> 5;
    #pragma unroll
    for(int it=0; it<8; it++){
      int r = it*8 + rs;
      int rg = base + r;
      float4 v = make_float4(0.f,0.f,0.f,0.f);
      if(rg < NN){
        v = __ldg((const float4*)(g_h + (size_t)rg*HH) + c4);
        v.x = tf32r(v.x); v.y = tf32r(v.y); v.z = tf32r(v.z); v.w = tf32r(v.w);
      }
      *(float4*)(sM + r*132 + c4*4) = v;
    }
  }
  __syncthreads();

  const float* Wa = g_Wt + (size_t)(12 + lk*2    )*16384;
  const float* Wb = g_Wt + (size_t)(12 + lk*2 + 1)*16384;
  float c[4][2][4];
  #pragma unroll
  for(int half=0; half<2; half++){
    frag_zero(c);
    mma_accum64(sM, half ? Wb : Wa, w, gid, tig, c);
    float* out = half ? g_Gb : g_Ga;
    #pragma unroll
    for(int rt=0;rt<4;rt++){
      #pragma unroll
      for(int ct=0;ct<2;ct++){
        int col0 = w*16 + ct*8 + 2*tig;
        int r0 = base + rt*16 + gid, r1 = r0 + 8;
        if(r0 < NN) *(float2*)(out + (size_t)r0*HH + col0) = make_float2(c[rt][ct][0], c[rt][ct][1]);
        if(r1 < NN) *(float2*)(out + (size_t)r1*HH + col0) = make_float2(c[rt][ct][2], c[rt][ct][3]);
      }
    }
  }
}

// dirty b1 rows only: exact fp32 recompute (clean b1 reads are redirected in k_delta)
__global__ void __launch_bounds__(128) k_gagb_fix(const float* __restrict__ W1){
  __shared__ float sh[HH];
  int j = threadIdx.x;
  int cnt = g_dcount;
  for(int i = blockIdx.x; i < cnt; i += FIXG){
    int n = g_dlist[i];
    sh[j] = g_h[(size_t)(NN+n)*HH + j];
    __syncthreads();
    float a = 0.f, bv = 0.f;
    #pragma unroll 4
    for(int kk=0; kk<HH; kk++){
      float hv = sh[kk];
      a  = fmaf(hv, __ldg(&W1[kk*HH + j]), a);
      bv = fmaf(hv, __ldg(&W1[(128+kk)*HH + j]), bv);
    }
    g_Ga[(size_t)(NN+n)*HH + j] = a;
    g_Gb[(size_t)(NN+n)*HH + j] = bv;
    __syncthreads();
  }
}

// ------------------- tf32-MMA fused edge kernel (batch 0): 64 edges/block -------------------
__global__ void __launch_bounds__(256,2) k_edge(
    const float* __restrict__ W1r, const float* __restrict__ b1,
    const float* __restrict__ b2,  const float* __restrict__ pb1,
    const float* __restrict__ pW2, const float* __restrict__ pb2,
    const int* __restrict__ esrc,  const int* __restrict__ edst,
    int lk, int kdeg){
  __shared__ float sM[64*132];
  __shared__ int   sDst[64];
  __shared__ int   sSrc[64];
  __shared__ float sInv[64];
  __shared__ float sD2[64];
  __shared__ float sRel[64*3];
  __shared__ float sCoef[64];
  __shared__ float sB2[HH];
  __shared__ float sPB1[HH];
  __shared__ float sPW2[HH];

  int tid = threadIdx.x;
  int w = tid >> 5, lane = tid & 31;
  int gid = lane >> 2, tig = lane & 3;
  int base = blockIdx.x*64;

  if(tid < 64){
    int e = base + tid;
    bool v = e < EE;
    int ee = v ? e : 0;
    int ds = edst[ee], sr = esrc[ee];
    float rx = g_p[ds*3+0] - g_p[sr*3+0];
    float ry = g_p[ds*3+1] - g_p[sr*3+1];
    float rz = g_p[ds*3+2] - g_p[sr*3+2];
    sRel[tid*3+0] = rx; sRel[tid*3+1] = ry; sRel[tid*3+2] = rz;
    sD2[tid]  = rx*rx + ry*ry + rz*rz;
    sInv[tid] = v ? g_invdeg[kdeg*NN + ds] : 0.f;
    sDst[tid] = ds;
    sSrc[tid] = sr;
    sCoef[tid] = 0.f;
  }
  if(tid < HH){
    sB2[tid]  = b2[tid];
    sPB1[tid] = pb1[tid];
    sPW2[tid] = pW2[tid];
  }
  __syncthreads();

  // stage m = silu(Ga[dst] + Gb[src] + d2*W1r + b1), tf32-rounded
  {
    int c4 = tid & 31, rs = tid >> 5;
    float4 w4 = __ldg((const float4*)W1r + c4);
    float4 bb = __ldg((const float4*)b1  + c4);
    #pragma unroll
    for(int it=0; it<8; it++){
      int r = it*8 + rs;
      float4 ga = __ldg((const float4*)(g_Ga + (size_t)sDst[r]*HH) + c4);
      float4 gb = __ldg((const float4*)(g_Gb + (size_t)sSrc[r]*HH) + c4);
      float d2 = sD2[r];
      float4 o;
      o.x = tf32r(siluf(ga.x + gb.x + d2*w4.x + bb.x));
      o.y = tf32r(siluf(ga.y + gb.y + d2*w4.y + bb.y));
      o.z = tf32r(siluf(ga.z + gb.z + d2*w4.z + bb.z));
      o.w = tf32r(siluf(ga.w + gb.w + d2*w4.w + bb.w));
      *(float4*)(sM + r*132 + c4*4) = o;
    }
  }
  __syncthreads();

  // ---- GEMM1: m @ W2 ----
  float c[4][2][4];
  frag_zero(c);
  mma_accum64(sM, g_Wt + (size_t)lk*16384, w, gid, tig, c);
  __syncthreads();

  // ---- epilogue1: m2 = silu(D1 + b2); scatter m_sum (v4 red via pair shfl); m2 -> sM ----
  #pragma unroll
  for(int rt=0;rt<4;rt++){
    #pragma unroll
    for(int ct=0;ct<2;ct++){
      int col0 = w*16 + ct*8 + 2*tig;
      int r0 = rt*16 + gid, r1 = r0 + 8;
      float v00 = siluf(c[rt][ct][0] + sB2[col0]);
      float v01 = siluf(c[rt][ct][1] + sB2[col0+1]);
      float v10 = siluf(c[rt][ct][2] + sB2[col0]);
      float v11 = siluf(c[rt][ct][3] + sB2[col0+1]);
      float i0 = sInv[r0], i1 = sInv[r1];
      float s00 = v00*i0, s01 = v01*i0;
      float s10 = v10*i1, s11 = v11*i1;
      float o00 = __shfl_xor_sync(0xffffffffu, s00, 1);
      float o01 = __shfl_xor_sync(0xffffffffu, s01, 1);
      float o10 = __shfl_xor_sync(0xffffffffu, s10, 1);
      float o11 = __shfl_xor_sync(0xffffffffu, s11, 1);
      if((tig & 1) == 0){
        int cb = w*16 + ct*8 + 4*(tig>>1);
        redv4(g_msum + (size_t)sDst[r0]*HH + cb, s00, s01, o00, o01);
        redv4(g_msum + (size_t)sDst[r1]*HH + cb, s10, s11, o10, o11);
      }
      *(float2*)(sM + r0*132 + col0) = make_float2(tf32r(v00), tf32r(v01));
      *(float2*)(sM + r1*132 + col0) = make_float2(tf32r(v10), tf32r(v11));
    }
  }
  __syncthreads();

  // ---- GEMM2: m2 @ pW1 ----
  frag_zero(c);
  mma_accum64(sM, g_Wt + (size_t)(6+lk)*16384, w, gid, tig, c);

  // ---- epilogue2: coef partials = silu(D2 + pb1) . pW2 ----
  float rsum[4][2];
  #pragma unroll
  for(int rt=0;rt<4;rt++){ rsum[rt][0]=0.f; rsum[rt][1]=0.f; }
  #pragma unroll
  for(int rt=0;rt<4;rt++){
    #pragma unroll
    for(int ct=0;ct<2;ct++){
      int col0 = w*16 + ct*8 + 2*tig;
      float w0 = sPW2[col0], w1 = sPW2[col0+1];
      float p0 = sPB1[col0], p1 = sPB1[col0+1];
      rsum[rt][0] = fmaf(siluf(c[rt][ct][0]+p0), w0,
                    fmaf(siluf(c[rt][ct][1]+p1), w1, rsum[rt][0]));
      rsum[rt][1] = fmaf(siluf(c[rt][ct][2]+p0), w0,
                    fmaf(siluf(c[rt][ct][3]+p1), w1, rsum[rt][1]));
    }
  }
  #pragma unroll
  for(int off=1; off<4; off<<=1){
    #pragma unroll
    for(int rt=0;rt<4;rt++){
      rsum[rt][0] += __shfl_xor_sync(0xffffffffu, rsum[rt][0], off);
      rsum[rt][1] += __shfl_xor_sync(0xffffffffu, rsum[rt][1], off);
    }
  }
  if(tig == 0){
    #pragma unroll
    for(int rt=0;rt<4;rt++){
      atomicAdd(&sCoef[rt*16 + gid],     rsum[rt][0]);
      atomicAdd(&sCoef[rt*16 + 8 + gid], rsum[rt][1]);
    }
  }
  __syncthreads();

  if(tid < 64){
    float s = (sCoef[tid] + __ldg(pb2)) * sInv[tid];
    int row = sDst[tid];
    atomicAdd(&g_pd[row*3+0], sRel[tid*3+0]*s);
    atomicAdd(&g_pd[row*3+1], sRel[tid*3+1]*s);
    atomicAdd(&g_pd[row*3+2], sRel[tid*3+2]*s);
  }
}

// ------------------- batch-1 delta kernel (clean-node b1 reads redirected to b0 rows) -------------------
__global__ void __launch_bounds__(128) k_delta(
    const float* __restrict__ W1r, const float* __restrict__ b1,
    const float* __restrict__ W2,  const float* __restrict__ b2,
    const float* __restrict__ pW1, const float* __restrict__ pb1,
    const float* __restrict__ pW2, const float* __restrict__ pb2,
    const int* __restrict__ esrc,  const int* __restrict__ edst, int kdeg){
  __shared__ float sm1[2][HH];
  __shared__ float sm2[2][HH];
  __shared__ float sred[8];
  int j = threadIdx.x;
  int cnt = g_acnt[kdeg];
  const int* alist = g_alist + (size_t)kdeg*EE;
  for(int idx = blockIdx.x; idx < cnt; idx += DELTA_GRID){
    int e = alist[idx];
    int ds = edst[e], sr = esrc[e];
    float inv = g_invdeg[kdeg*NN + ds];
    int dDirty = g_dirty[ds], sDirty = g_dirty[sr];
    float rel[2][3], d2v[2];
    #pragma unroll
    for(int b=0;b<2;b++){
      int dr = b*NN + ds, srr = b*NN + sr;
      rel[b][0] = g_p[dr*3+0] - g_p[srr*3+0];
      rel[b][1] = g_p[dr*3+1] - g_p[srr*3+1];
      rel[b][2] = g_p[dr*3+2] - g_p[srr*3+2];
      d2v[b] = rel[b][0]*rel[b][0] + rel[b][1]*rel[b][1] + rel[b][2]*rel[b][2];
      // b1 Ga/Gb rows are materialized only for dirty nodes; clean == b0 bitwise
      int ga_row = (b==1 && !dDirty) ? ds : dr;
      int gb_row = (b==1 && !sDirty) ? sr : srr;
      sm1[b][j] = siluf(g_Ga[(size_t)ga_row*HH+j] + g_Gb[(size_t)gb_row*HH+j]
                        + d2v[b]*__ldg(&W1r[j]) + __ldg(&b1[j]));
    }
    __syncthreads();
    float acc0 = 0.f, acc1 = 0.f;
    #pragma unroll 4
    for(int k=0;k<HH;k++){
      float w = __ldg(&W2[k*HH+j]);
      acc0 = fmaf(sm1[0][k], w, acc0);
      acc1 = fmaf(sm1[1][k], w, acc1);
    }
    float bb = __ldg(&b2[j]);
    float m20 = siluf(acc0 + bb);
    float m21 = siluf(acc1 + bb);
    atomicAdd(&g_msum[(size_t)(NN+ds)*HH + j], (m21 - m20)*inv);
    sm2[0][j] = m20; sm2[1][j] = m21;
    __syncthreads();
    acc0 = 0.f; acc1 = 0.f;
    #pragma unroll 4
    for(int k=0;k<HH;k++){
      float w = __ldg(&pW1[k*HH+j]);
      acc0 = fmaf(sm2[0][k], w, acc0);
      acc1 = fmaf(sm2[1][k], w, acc1);
    }
    float pb = __ldg(&pb1[j]);
    float w2 = __ldg(&pW2[j]);
    float c0 = siluf(acc0 + pb) * w2;
    float c1 = siluf(acc1 + pb) * w2;
    #pragma unroll
    for(int off=16; off; off>>=1){
      c0 += __shfl_xor_sync(0xffffffffu, c0, off);
      c1 += __shfl_xor_sync(0xffffffffu, c1, off);
    }
    int wwid = j >> 5;
    if((j & 31) == 0){ sred[wwid] = c0; sred[4+wwid] = c1; }
    __syncthreads();
    if(j == 0){
      float pb2v = __ldg(pb2);
      float coef0 = sred[0]+sred[1]+sred[2]+sred[3] + pb2v;
      float coef1 = sred[4]+sred[5]+sred[6]+sred[7] + pb2v;
      atomicAdd(&g_pd[(NN+ds)*3+0], (rel[1][0]*coef1 - rel[0][0]*coef0)*inv);
      atomicAdd(&g_pd[(NN+ds)*3+1], (rel[1][1]*coef1 - rel[0][1]*coef0)*inv);
      atomicAdd(&g_pd[(NN+ds)*3+2], (rel[1][2]*coef1 - rel[0][2]*coef0)*inv);
      g_newDirty[ds] = 1;
    }
    __syncthreads();
  }
}

// ------------------- node update (tf32 MMA, batch-0 rows) -------------------
__global__ void __launch_bounds__(256,2) k_update(
    const float* __restrict__ bu1, const float* __restrict__ bu2, int l){
  __shared__ float sM[64*132];
  __shared__ float sB1[HH];
  __shared__ float sB2v[HH];
  int tid = threadIdx.x;
  int w = tid >> 5, lane = tid & 31;
  int gid = lane >> 2, tig = lane & 3;
  int base = blockIdx.x*64;
  int c4 = tid & 31, rs = tid >> 5;

  if(tid < HH){ sB1[tid] = bu1[tid]; sB2v[tid] = bu2[tid]; }

  float c[4][2][4];
  frag_zero(c);

  #pragma unroll
  for(int it=0; it<8; it++){
    int r = it*8 + rs;
    int rg = base + r;
    float4 v = make_float4(0.f,0.f,0.f,0.f);
    if(rg < NN){
      v = __ldg((const float4*)(g_h + (size_t)rg*HH) + c4);
      v.x = tf32r(v.x); v.y = tf32r(v.y); v.z = tf32r(v.z); v.w = tf32r(v.w);
    }
    *(float4*)(sM + r*132 + c4*4) = v;
  }
  __syncthreads();
  mma_accum64(sM, g_Wt + (size_t)(24 + l*2)*16384, w, gid, tig, c);
  __syncthreads();

  #pragma unroll
  for(int it=0; it<8; it++){
    int r = it*8 + rs;
    int rg = base + r;
    float4 v = make_float4(0.f,0.f,0.f,0.f);
    if(rg < NN){
      v = __ldg((const float4*)(g_msum + (size_t)rg*HH) + c4);
      v.x = tf32r(v.x); v.y = tf32r(v.y); v.z = tf32r(v.z); v.w = tf32r(v.w);
    }
    *(float4*)(sM + r*132 + c4*4) = v;
  }
  __syncthreads();
  mma_accum64(sM, g_Wt + (size_t)(24 + l*2 + 1)*16384, w, gid, tig, c);
  __syncthreads();

  #pragma unroll
  for(int rt=0;rt<4;rt++){
    #pragma unroll
    for(int ct=0;ct<2;ct++){
      int col0 = w*16 + ct*8 + 2*tig;
      int r0 = rt*16 + gid, r1 = r0 + 8;
      *(float2*)(sM + r0*132 + col0) = make_float2(
          tf32r(siluf(c[rt][ct][0] + sB1[col0])),
          tf32r(siluf(c[rt][ct][1] + sB1[col0+1])));
      *(float2*)(sM + r1*132 + col0) = make_float2(
          tf32r(siluf(c[rt][ct][2] + sB1[col0])),
          tf32r(siluf(c[rt][ct][3] + sB1[col0+1])));
    }
  }
  __syncthreads();

  frag_zero(c);
  mma_accum64(sM, g_Wt + (size_t)(28 + l)*16384, w, gid, tig, c);

  #pragma unroll
  for(int rt=0;rt<4;rt++){
    #pragma unroll
    for(int ct=0;ct<2;ct++){
      int col0 = w*16 + ct*8 + 2*tig;
      int r0 = base + rt*16 + gid, r1 = r0 + 8;
      if(r0 < NN){
        float2 hv = *(float2*)(g_h + (size_t)r0*HH + col0);
        hv.x += c[rt][ct][0] + sB2v[col0];
        hv.y += c[rt][ct][1] + sB2v[col0+1];
        *(float2*)(g_h + (size_t)r0*HH + col0) = hv;
      }
      if(r1 < NN){
        float2 hv = *(float2*)(g_h + (size_t)r1*HH + col0);
        hv.x += c[rt][ct][2] + sB2v[col0];
        hv.y += c[rt][ct][3] + sB2v[col0+1];
        *(float2*)(g_h + (size_t)r1*HH + col0) = hv;
      }
    }
  }
}

// ------------------- fused: clean b1 h copy + dirty b1 update fix -------------------
// (separate launch AFTER k_update — copy reads prior-launch b0 h; fix reads old b1 h + msum)
__global__ void __launch_bounds__(256) k_updfix_copy(
    const float* __restrict__ Wu1, const float* __restrict__ bu1,
    const float* __restrict__ Wu2, const float* __restrict__ bu2){
  __shared__ float sh[HH];
  __shared__ float sm[HH];
  __shared__ float st[HH];
  int tid = threadIdx.x;
  int bid = blockIdx.x;
  if(bid < CPB){
    int idx = bid*256 + tid;
    if(idx < NN*32){
      int c4 = idx & 31;
      int n  = idx >> 5;
      if(!g_dirty[n])
        ((float4*)(g_h + (size_t)(NN+n)*HH))[c4] = ((const float4*)(g_h + (size_t)n*HH))[c4];
    }
  } else {
    int j = tid & 127;
    int cnt = g_dcount;
    for(int i = bid - CPB; i < cnt; i += FIXG){
      int n = g_dlist[i];
      size_t row = (size_t)(NN+n)*HH;
      if(tid < 128){ sh[j] = g_h[row + j]; sm[j] = g_msum[row + j]; }
      __syncthreads();
      if(tid < 128){
        float acc = __ldg(&bu1[j]);
        #pragma unroll 4
        for(int kk=0; kk<HH; kk++){
          acc = fmaf(sh[kk], __ldg(&Wu1[kk*HH + j]), acc);
          acc = fmaf(sm[kk], __ldg(&Wu1[(128+kk)*HH + j]), acc);
        }
        st[j] = siluf(acc);
      }
      __syncthreads();
      if(tid < 128){
        float o = __ldg(&bu2[j]);
        #pragma unroll 4
        for(int kk=0; kk<HH; kk++)
          o = fmaf(st[kk], __ldg(&Wu2[kk*HH + j]), o);
        g_h[row + j] = sh[j] + o;
      }
      __syncthreads();
    }
  }
}

// ------------------- readout -------------------
__global__ void k_readout(const float* __restrict__ W1, const float* __restrict__ b1,
                          const float* __restrict__ W2, const float* __restrict__ b2,
                          const int* __restrict__ ent, float* __restrict__ out){
  __shared__ float se[HH];
  __shared__ float sred[HH];
  int j = threadIdx.x;
  for(int b=0; b<BB; b++){
    int row = b*NN + ent[b];
    se[j] = g_h[(size_t)row*HH + j];
    __syncthreads();
    float acc = b1[j];
    #pragma unroll 4
    for(int i=0;i<HH;i++) acc = fmaf(se[i], W1[i*HH+j], acc);
    sred[j] = siluf(acc) * W2[j];
    __syncthreads();
    for(int s=64; s>0; s>>=1){
      if(j<s) sred[j] += sred[j+s];
      __syncthreads();
    }
    if(j==0) out[b] = sred[0] + b2[0];
    __syncthreads();
  }
}

// ------------------- launch -------------------
extern "C" void kernel_launch(void* const* d_in, const int* in_sizes, int n_in,
                              void* d_out, int out_size){
  (void)in_sizes; (void)n_in; (void)out_size;
  const float* x     = (const float*)d_in[0];
  const float* basef = (const float*)d_in[1];
  const float* basep = (const float*)d_in[2];
  const float* Win   = (const float*)d_in[3];
  const float* b_in  = (const float*)d_in[4];
  const float* mW1   = (const float*)d_in[5];
  const float* mb1   = (const float*)d_in[6];
  const float* mW2   = (const float*)d_in[7];
  const float* mb2   = (const float*)d_in[8];
  const float* pW1   = (const float*)d_in[9];
  const float* pb1   = (const float*)d_in[10];
  const float* pW2   = (const float*)d_in[11];
  const float* pb2   = (const float*)d_in[12];
  const float* uW1   = (const float*)d_in[13];
  const float* ub1   = (const float*)d_in[14];
  const float* uW2   = (const float*)d_in[15];
  const float* ub2   = (const float*)d_in[16];
  const float* oW1   = (const float*)d_in[17];
  const float* ob1   = (const float*)d_in[18];
  const float* oW2   = (const float*)d_in[19];
  const float* ob2   = (const float*)d_in[20];
  const int*   ent   = (const int*)d_in[21];
  const int*   esrc  = (const int*)d_in[22];
  const int*   edst  = (const int*)d_in[23];
  float* out = (float*)d_out;

  k_round<<<(30*HH*HH+255)/256, 256>>>(mW1, mW2, pW1, uW1, uW2);

  k_deg_zero <<<(NBB*NN+255)/256, 256>>>();
  k_deg_count<<<(NBB*EE+255)/256, 256>>>(edst);
  k_deg_fin  <<<(NBB*NN+255)/256, 256>>>(ent);
  k_build_dlist<<<(NN+255)/256, 256>>>();

  k_init_h <<<NN, 128>>>(basef, Win, b_in);
  k_add_dyn<<<1, 256>>>(x, Win, ent);
  k_init_p <<<(NN*3+255)/256, 256>>>(basep);

  for(int l=0; l<LL; l++){
    k_zero_layer<<<(ROWS_TOT*HH+255)/256, 256>>>();
    k_buildA_all<<<(NBB*EE+255)/256, 256>>>(esrc, edst);
    for(int k=0; k<NBB; k++){
      int lk = l*NBB + k;
      const float* W1lk = mW1 + (size_t)lk*257*HH;
      k_gagb<<<NTILES, 256>>>(lk);
      k_gagb_fix<<<FIXG, 128>>>(W1lk);
      k_edge<<<ETILES, 256>>>(
          W1lk + 256*HH,
          mb1 + (size_t)lk*HH,
          mb2 + (size_t)lk*HH,
          pb1 + (size_t)lk*HH,
          pW2 + (size_t)lk*HH,
          pb2 + lk,
          esrc + (size_t)k*EE,
          edst + (size_t)k*EE,
          lk, k);
      k_delta<<<DELTA_GRID, 128>>>(
          W1lk + 256*HH,
          mb1 + (size_t)lk*HH,
          mW2 + (size_t)lk*HH*HH,
          mb2 + (size_t)lk*HH,
          pW1 + (size_t)lk*HH*HH,
          pb1 + (size_t)lk*HH,
          pW2 + (size_t)lk*HH,
          pb2 + lk,
          esrc + (size_t)k*EE,
          edst + (size_t)k*EE,
          k);
    }
    k_merge<<<(NN*HH+255)/256, 256>>>();
    k_build_dlist<<<(NN+255)/256, 256>>>();
    k_update<<<NTILES, 256>>>(
        ub1 + (size_t)l*HH,
        ub2 + (size_t)l*HH,
        l);
    k_updfix_copy<<<CPB + FIXG, 256>>>(
        uW1 + (size_t)l*2*HH*HH,
        ub1 + (size_t)l*HH,
        uW2 + (size_t)l*HH*HH,
        ub2 + (size_t)l*HH);
    k_padd<<<(ROWS_TOT*3+255)/256, 256>>>();
  }

  k_readout<<<1, 128>>>(oW1, ob1, oW2, ob2, ent, out);
}

// round 14
// speedup vs baseline: 1.1065x; 1.0391x over previous
#include <cuda_runtime.h>
#include <math.h>

#define BB 2
#define NN 10000
#define EE 100000
#define HH 128
#define DINN 8
#define DBB 16
#define LL 2
#define NBB 3
#define ROWS_TOT (BB*NN)
#define ETILES ((EE+63)/64)
#define NTILES ((NN+63)/64)
#define DELTA_GRID 592
#define FIXG 128
#define ZBLK ((ROWS_TOT*HH+255)/256)
#define ABLK ((NBB*EE+255)/256)

// -------- scratch (device globals; no allocation anywhere) --------
__device__ float g_h[ROWS_TOT*HH];
__device__ float g_msum[ROWS_TOT*HH];
__device__ float g_Ga[ROWS_TOT*HH];
__device__ float g_Gb[ROWS_TOT*HH];
__device__ float g_p[ROWS_TOT*3];
__device__ float g_pd[ROWS_TOT*3];
__device__ float g_invdeg[NBB*NN];
__device__ int   g_dirty[NN];
__device__ int   g_newDirty[NN];
__device__ int   g_acnt[NBB];
__device__ int   g_alist[NBB*EE];
__device__ int   g_dcount;
__device__ int   g_dlist[NN];
// tf32-rounded weights, 30 slabs of 128x128:
//  0..5  mW2 | 6..11 pW1 | 12..23 mW1 (lk*2+half) | 24..27 uW1 (l*2+half) | 28..29 uW2
__device__ float g_Wt[30*HH*HH];

// silu(x) = 0.5*x*(1+tanh(x/2)) — 1 MUFU
__device__ __forceinline__ float siluf(float x){
  float t;
  asm("tanh.approx.f32 %0, %1;" : "=f"(t) : "f"(0.5f*x));
  return 0.5f*x*(1.0f+t);
}

__device__ __forceinline__ float tf32r(float x){
  unsigned u;
  asm("cvt.rna.tf32.f32 %0, %1;" : "=r"(u) : "f"(x));
  return __uint_as_float(u);
}

// m16n8k8 tf32 MMA, fp32 accumulate (base PTX, sm_80+)
__device__ __forceinline__ void mma8(float c[4],
    unsigned a0, unsigned a1, unsigned a2, unsigned a3,
    unsigned b0, unsigned b1){
  asm volatile(
    "mma.sync.aligned.m16n8k8.row.col.f32.tf32.tf32.f32 "
    "{%0,%1,%2,%3}, {%4,%5,%6,%7}, {%8,%9}, {%0,%1,%2,%3};"
    : "+f"(c[0]), "+f"(c[1]), "+f"(c[2]), "+f"(c[3])
    : "r"(a0), "r"(a1), "r"(a2), "r"(a3), "r"(b0), "r"(b1));
}

__device__ __forceinline__ void redv4(float* addr, float x, float y, float z, float w){
  asm volatile("red.global.add.v4.f32 [%0], {%1, %2, %3, %4};"
               :: "l"(addr), "f"(x), "f"(y), "f"(z), "f"(w) : "memory");
}

// 64x128 += sM(64xK=128, stride 132, tf32) @ B(128x128 row-major tf32), per-warp 64x16 slab
__device__ __forceinline__ void mma_accum64(const float* __restrict__ sM,
                                            const float* __restrict__ B,
                                            int w, int gid, int tig,
                                            float c[4][2][4]){
  #pragma unroll 4
  for(int k0=0; k0<HH; k0+=8){
    unsigned a[4][4];
    #pragma unroll
    for(int rt=0;rt<4;rt++){
      int r = rt*16;
      a[rt][0] = __float_as_uint(sM[(r+gid)*132   + k0+tig]);
      a[rt][1] = __float_as_uint(sM[(r+8+gid)*132 + k0+tig]);
      a[rt][2] = __float_as_uint(sM[(r+gid)*132   + k0+tig+4]);
      a[rt][3] = __float_as_uint(sM[(r+8+gid)*132 + k0+tig+4]);
    }
    #pragma unroll
    for(int ct=0;ct<2;ct++){
      int n = w*16 + ct*8 + gid;
      unsigned b0 = __float_as_uint(__ldg(&B[(k0+tig)*HH   + n]));
      unsigned b1r = __float_as_uint(__ldg(&B[(k0+tig+4)*HH + n]));
      #pragma unroll
      for(int rt=0;rt<4;rt++)
        mma8(c[rt][ct], a[rt][0],a[rt][1],a[rt][2],a[rt][3], b0,b1r);
    }
  }
}
__device__ __forceinline__ void frag_zero(float c[4][2][4]){
  #pragma unroll
  for(int rt=0;rt<4;rt++)
    #pragma unroll
    for(int ct=0;ct<2;ct++)
      #pragma unroll
      for(int q=0;q<4;q++) c[rt][ct][q]=0.f;
}

// ------------------- weight rounding -------------------
__global__ void k_round(const float* __restrict__ mW1, const float* __restrict__ mW2,
                        const float* __restrict__ pW1, const float* __restrict__ uW1,
                        const float* __restrict__ uW2){
  int gi = blockIdx.x*blockDim.x + threadIdx.x;
  if(gi >= 30*HH*HH) return;
  int slot = gi >> 14;
  int e    = gi & 16383;
  float v;
  if      (slot < 6)  v = mW2[(size_t)slot*16384 + e];
  else if (slot < 12) v = pW1[(size_t)(slot-6)*16384 + e];
  else if (slot < 24){ int s = slot-12; v = mW1[(size_t)(s>>1)*257*HH + (size_t)(s&1)*16384 + e]; }
  else if (slot < 28){ int s = slot-24; v = uW1[(size_t)(s>>1)*2*16384 + (size_t)(s&1)*16384 + e]; }
  else                v = uW2[(size_t)(slot-28)*16384 + e];
  g_Wt[gi] = tf32r(v);
}

// ------------------- small setup kernels -------------------
__global__ void k_deg_zero(){
  int i = blockIdx.x*blockDim.x + threadIdx.x;
  if(i < NBB*NN) g_invdeg[i] = 0.f;
  if(i < NN) g_dirty[i] = 0;
}
__global__ void k_deg_count(const int* __restrict__ edst){
  int i = blockIdx.x*blockDim.x + threadIdx.x;
  if(i < NBB*EE){
    int k = i / EE;
    atomicAdd(&g_invdeg[k*NN + edst[i]], 1.f);
  }
}
__global__ void k_deg_fin(const int* __restrict__ ent){
  int i = blockIdx.x*blockDim.x + threadIdx.x;
  if(i < NBB*NN) g_invdeg[i] = 1.f / fmaxf(g_invdeg[i], 1.f);
  if(i < BB) g_dirty[ent[i]] = 1;
  if(i < NBB) g_acnt[i] = 0;
  if(i == 0) g_dcount = 0;
}

__global__ void k_build_dlist(){
  int i = blockIdx.x*blockDim.x + threadIdx.x;
  if(i < NN && g_dirty[i]){
    int p = atomicAdd(&g_dcount, 1);
    g_dlist[p] = i;
  }
}

__global__ void k_init_h(const float* __restrict__ base, const float* __restrict__ Win,
                         const float* __restrict__ b_in){
  int n = blockIdx.x, j = threadIdx.x;
  float acc = b_in[j];
  #pragma unroll
  for(int d=0; d<DBB; d++)
    acc = fmaf(__ldg(&base[n*DBB+d]), __ldg(&Win[d*HH+j]), acc);
  g_h[n*HH+j] = acc;
  g_h[(NN+n)*HH+j] = acc;
}

__global__ void k_add_dyn(const float* __restrict__ x, const float* __restrict__ Win,
                          const int* __restrict__ ent){
  int t = threadIdx.x;
  if(t < BB*HH){
    int b = t >> 7, j = t & (HH-1);
    float acc = 0.f;
    #pragma unroll
    for(int d=0; d<DINN; d++)
      acc = fmaf(x[b*DINN+d], Win[(DBB+d)*HH+j], acc);
    g_h[((size_t)b*NN + ent[b])*HH + j] += acc;
  }
}

__global__ void k_init_p(const float* __restrict__ bp){
  int i = blockIdx.x*blockDim.x + threadIdx.x;
  if(i < NN*3){ float v = bp[i]; g_p[i] = v; g_p[NN*3+i] = v; }
}

// fused: zero msum/pd/newDirty (blocks < ZBLK) + build affected-edge lists (rest).
// acnt was zeroed by the previous launch (deg_fin or merge). Disjoint writes — race-free.
__global__ void k_zerobuild(const int* __restrict__ esrc, const int* __restrict__ edst){
  int bid = blockIdx.x, tid = threadIdx.x;
  if(bid < ZBLK){
    int i = bid*256 + tid;
    if(i < ROWS_TOT*HH) g_msum[i] = 0.f;
    if(i < ROWS_TOT*3)  g_pd[i]   = 0.f;
    if(i < NN)          g_newDirty[i] = 0;
  } else {
    int i = (bid - ZBLK)*256 + tid;
    if(i < NBB*EE){
      int k = i / EE;
      int e = i - k*EE;
      if(g_dirty[esrc[i]] | g_dirty[edst[i]]){
        int pos = atomicAdd(&g_acnt[k], 1);
        g_alist[k*EE + pos] = e;
      }
    }
  }
}

// merge b0 contributions into b1 regions; merge dirty flags; reset dcount and acnt
__global__ void k_merge(){
  int i = blockIdx.x*blockDim.x + threadIdx.x;
  if(i < NN*HH) g_msum[(size_t)NN*HH + i] += g_msum[i];
  if(i < NN*3)  g_pd[NN*3 + i] += g_pd[i];
  if(i < NN){ if(g_newDirty[i]) g_dirty[i] = 1; }
  if(i < NBB) g_acnt[i] = 0;
  if(i == 0) g_dcount = 0;
}

__global__ void k_padd(){
  int i = blockIdx.x*blockDim.x + threadIdx.x;
  if(i < ROWS_TOT*3) g_p[i] += g_pd[i];
}

// ------------------- fused gagb: MMA b0 blocks + dirty-b1 fp32 fix blocks -------------------
// Disjoint Ga/Gb writes (rows <NN vs >=NN); fix never reads Ga/Gb — race-free.
__global__ void __launch_bounds__(256,2) k_gagb_all2(int lk, const float* __restrict__ W1){
  __shared__ float sM[64*132];
  int tid = threadIdx.x;
  int bid = blockIdx.x;

  if(bid < NTILES){
    int w = tid >> 5, lane = tid & 31;
    int gid = lane >> 2, tig = lane & 3;
    int base = bid*64;
    {
      int c4 = tid & 31, rs = tid >> 5;
      #pragma unroll
      for(int it=0; it<8; it++){
        int r = it*8 + rs;
        int rg = base + r;
        float4 v = make_float4(0.f,0.f,0.f,0.f);
        if(rg < NN){
          v = __ldg((const float4*)(g_h + (size_t)rg*HH) + c4);
          v.x = tf32r(v.x); v.y = tf32r(v.y); v.z = tf32r(v.z); v.w = tf32r(v.w);
        }
        *(float4*)(sM + r*132 + c4*4) = v;
      }
    }
    __syncthreads();

    const float* Wa = g_Wt + (size_t)(12 + lk*2    )*16384;
    const float* Wb = g_Wt + (size_t)(12 + lk*2 + 1)*16384;
    float c[4][2][4];
    #pragma unroll
    for(int half=0; half<2; half++){
      frag_zero(c);
      mma_accum64(sM, half ? Wb : Wa, w, gid, tig, c);
      float* out = half ? g_Gb : g_Ga;
      #pragma unroll
      for(int rt=0;rt<4;rt++){
        #pragma unroll
        for(int ct=0;ct<2;ct++){
          int col0 = w*16 + ct*8 + 2*tig;
          int r0 = base + rt*16 + gid, r1 = r0 + 8;
          if(r0 < NN) *(float2*)(out + (size_t)r0*HH + col0) = make_float2(c[rt][ct][0], c[rt][ct][1]);
          if(r1 < NN) *(float2*)(out + (size_t)r1*HH + col0) = make_float2(c[rt][ct][2], c[rt][ct][3]);
        }
      }
    }
  } else {
    // dirty b1 rows: exact fp32 recompute (reads only g_h/dlist — prior-launch state)
    float* sh = sM;
    int j = tid & 127;
    bool act = tid < 128;
    int cnt = g_dcount;
    for(int i = bid - NTILES; i < cnt; i += FIXG){
      int n = g_dlist[i];
      if(act) sh[j] = g_h[(size_t)(NN+n)*HH + j];
      __syncthreads();
      if(act){
        float a = 0.f, bv = 0.f;
        #pragma unroll 4
        for(int kk=0; kk<HH; kk++){
          float hv = sh[kk];
          a  = fmaf(hv, __ldg(&W1[kk*HH + j]), a);
          bv = fmaf(hv, __ldg(&W1[(128+kk)*HH + j]), bv);
        }
        g_Ga[(size_t)(NN+n)*HH + j] = a;
        g_Gb[(size_t)(NN+n)*HH + j] = bv;
      }
      __syncthreads();
    }
  }
}

// ------------------- fused edge (b0, tf32 MMA) + batch-1 delta blocks -------------------
// Edge writes b0 msum/pd rows; delta writes b1 rows — disjoint. Both only read prior-launch state.
__global__ void __launch_bounds__(256,2) k_edge_delta(
    const float* __restrict__ W1r, const float* __restrict__ b1,
    const float* __restrict__ W2f, const float* __restrict__ b2,
    const float* __restrict__ pW1f,const float* __restrict__ pb1,
    const float* __restrict__ pW2, const float* __restrict__ pb2,
    const int* __restrict__ esrc,  const int* __restrict__ edst,
    int lk, int kdeg){
  __shared__ float sM[64*132];
  __shared__ int   sDst[64];
  __shared__ int   sSrc[64];
  __shared__ float sInv[64];
  __shared__ float sD2[64];
  __shared__ float sRel[64*3];
  __shared__ float sCoef[64];
  __shared__ float sB2[HH];
  __shared__ float sPB1[HH];
  __shared__ float sPW2[HH];

  int tid = threadIdx.x;
  int bid = blockIdx.x;

  if(bid < ETILES){
    // ======== edge role ========
    int w = tid >> 5, lane = tid & 31;
    int gid = lane >> 2, tig = lane & 3;
    int base = bid*64;

    if(tid < 64){
      int e = base + tid;
      bool v = e < EE;
      int ee = v ? e : 0;
      int ds = edst[ee], sr = esrc[ee];
      float rx = g_p[ds*3+0] - g_p[sr*3+0];
      float ry = g_p[ds*3+1] - g_p[sr*3+1];
      float rz = g_p[ds*3+2] - g_p[sr*3+2];
      sRel[tid*3+0] = rx; sRel[tid*3+1] = ry; sRel[tid*3+2] = rz;
      sD2[tid]  = rx*rx + ry*ry + rz*rz;
      sInv[tid] = v ? g_invdeg[kdeg*NN + ds] : 0.f;
      sDst[tid] = ds;
      sSrc[tid] = sr;
      sCoef[tid] = 0.f;
    }
    if(tid < HH){
      sB2[tid]  = b2[tid];
      sPB1[tid] = pb1[tid];
      sPW2[tid] = pW2[tid];
    }
    __syncthreads();

    {
      int c4 = tid & 31, rs = tid >> 5;
      float4 w4 = __ldg((const float4*)W1r + c4);
      float4 bb = __ldg((const float4*)b1  + c4);
      #pragma unroll
      for(int it=0; it<8; it++){
        int r = it*8 + rs;
        float4 ga = __ldg((const float4*)(g_Ga + (size_t)sDst[r]*HH) + c4);
        float4 gb = __ldg((const float4*)(g_Gb + (size_t)sSrc[r]*HH) + c4);
        float d2 = sD2[r];
        float4 o;
        o.x = tf32r(siluf(ga.x + gb.x + d2*w4.x + bb.x));
        o.y = tf32r(siluf(ga.y + gb.y + d2*w4.y + bb.y));
        o.z = tf32r(siluf(ga.z + gb.z + d2*w4.z + bb.z));
        o.w = tf32r(siluf(ga.w + gb.w + d2*w4.w + bb.w));
        *(float4*)(sM + r*132 + c4*4) = o;
      }
    }
    __syncthreads();

    float c[4][2][4];
    frag_zero(c);
    mma_accum64(sM, g_Wt + (size_t)lk*16384, w, gid, tig, c);
    __syncthreads();

    #pragma unroll
    for(int rt=0;rt<4;rt++){
      #pragma unroll
      for(int ct=0;ct<2;ct++){
        int col0 = w*16 + ct*8 + 2*tig;
        int r0 = rt*16 + gid, r1 = r0 + 8;
        float v00 = siluf(c[rt][ct][0] + sB2[col0]);
        float v01 = siluf(c[rt][ct][1] + sB2[col0+1]);
        float v10 = siluf(c[rt][ct][2] + sB2[col0]);
        float v11 = siluf(c[rt][ct][3] + sB2[col0+1]);
        float i0 = sInv[r0], i1 = sInv[r1];
        float s00 = v00*i0, s01 = v01*i0;
        float s10 = v10*i1, s11 = v11*i1;
        float o00 = __shfl_xor_sync(0xffffffffu, s00, 1);
        float o01 = __shfl_xor_sync(0xffffffffu, s01, 1);
        float o10 = __shfl_xor_sync(0xffffffffu, s10, 1);
        float o11 = __shfl_xor_sync(0xffffffffu, s11, 1);
        if((tig & 1) == 0){
          int cb = w*16 + ct*8 + 4*(tig>>1);
          redv4(g_msum + (size_t)sDst[r0]*HH + cb, s00, s01, o00, o01);
          redv4(g_msum + (size_t)sDst[r1]*HH + cb, s10, s11, o10, o11);
        }
        *(float2*)(sM + r0*132 + col0) = make_float2(tf32r(v00), tf32r(v01));
        *(float2*)(sM + r1*132 + col0) = make_float2(tf32r(v10), tf32r(v11));
      }
    }
    __syncthreads();

    frag_zero(c);
    mma_accum64(sM, g_Wt + (size_t)(6+lk)*16384, w, gid, tig, c);

    float rsum[4][2];
    #pragma unroll
    for(int rt=0;rt<4;rt++){ rsum[rt][0]=0.f; rsum[rt][1]=0.f; }
    #pragma unroll
    for(int rt=0;rt<4;rt++){
      #pragma unroll
      for(int ct=0;ct<2;ct++){
        int col0 = w*16 + ct*8 + 2*tig;
        float w0 = sPW2[col0], w1 = sPW2[col0+1];
        float p0 = sPB1[col0], p1 = sPB1[col0+1];
        rsum[rt][0] = fmaf(siluf(c[rt][ct][0]+p0), w0,
                      fmaf(siluf(c[rt][ct][1]+p1), w1, rsum[rt][0]));
        rsum[rt][1] = fmaf(siluf(c[rt][ct][2]+p0), w0,
                      fmaf(siluf(c[rt][ct][3]+p1), w1, rsum[rt][1]));
      }
    }
    #pragma unroll
    for(int off=1; off<4; off<<=1){
      #pragma unroll
      for(int rt=0;rt<4;rt++){
        rsum[rt][0] += __shfl_xor_sync(0xffffffffu, rsum[rt][0], off);
        rsum[rt][1] += __shfl_xor_sync(0xffffffffu, rsum[rt][1], off);
      }
    }
    if(tig == 0){
      #pragma unroll
      for(int rt=0;rt<4;rt++){
        atomicAdd(&sCoef[rt*16 + gid],     rsum[rt][0]);
        atomicAdd(&sCoef[rt*16 + 8 + gid], rsum[rt][1]);
      }
    }
    __syncthreads();

    if(tid < 64){
      float s = (sCoef[tid] + __ldg(pb2)) * sInv[tid];
      int row = sDst[tid];
      atomicAdd(&g_pd[row*3+0], sRel[tid*3+0]*s);
      atomicAdd(&g_pd[row*3+1], sRel[tid*3+1]*s);
      atomicAdd(&g_pd[row*3+2], sRel[tid*3+2]*s);
    }
  } else {
    // ======== delta role (clean-node b1 reads redirected to b0 rows) ========
    float (*sm1)[HH] = (float(*)[HH])sM;                  // 2*128 floats
    float (*sm2)[HH] = (float(*)[HH])(sM + 2*HH);
    float* sred = sM + 4*HH;                              // 8 floats
    int j = tid & 127;
    bool act = tid < 128;
    int cnt = g_acnt[kdeg];
    const int* alist = g_alist + (size_t)kdeg*EE;
    for(int idx = bid - ETILES; idx < cnt; idx += DELTA_GRID){
      int ds=0, sr=0; float inv=0.f;
      float rel[2][3];
      if(act){
        int e = alist[idx];
        ds = edst[e]; sr = esrc[e];
        inv = g_invdeg[kdeg*NN + ds];
        int dDirty = g_dirty[ds], sDirty = g_dirty[sr];
        #pragma unroll
        for(int b=0;b<2;b++){
          int dr = b*NN + ds, srr = b*NN + sr;
          rel[b][0] = g_p[dr*3+0] - g_p[srr*3+0];
          rel[b][1] = g_p[dr*3+1] - g_p[srr*3+1];
          rel[b][2] = g_p[dr*3+2] - g_p[srr*3+2];
          float d2 = rel[b][0]*rel[b][0] + rel[b][1]*rel[b][1] + rel[b][2]*rel[b][2];
          int ga_row = (b==1 && !dDirty) ? ds : dr;
          int gb_row = (b==1 && !sDirty) ? sr : srr;
          sm1[b][j] = siluf(g_Ga[(size_t)ga_row*HH+j] + g_Gb[(size_t)gb_row*HH+j]
                            + d2*__ldg(&W1r[j]) + __ldg(&b1[j]));
        }
      }
      __syncthreads();
      if(act){
        float acc0 = 0.f, acc1 = 0.f;
        #pragma unroll 4
        for(int k=0;k<HH;k++){
          float w = __ldg(&W2f[k*HH+j]);
          acc0 = fmaf(sm1[0][k], w, acc0);
          acc1 = fmaf(sm1[1][k], w, acc1);
        }
        float bb = __ldg(&b2[j]);
        float m20 = siluf(acc0 + bb);
        float m21 = siluf(acc1 + bb);
        atomicAdd(&g_msum[(size_t)(NN+ds)*HH + j], (m21 - m20)*inv);
        sm2[0][j] = m20; sm2[1][j] = m21;
      }
      __syncthreads();
      if(act){
        float acc0 = 0.f, acc1 = 0.f;
        #pragma unroll 4
        for(int k=0;k<HH;k++){
          float w = __ldg(&pW1f[k*HH+j]);
          acc0 = fmaf(sm2[0][k], w, acc0);
          acc1 = fmaf(sm2[1][k], w, acc1);
        }
        float pb = __ldg(&pb1[j]);
        float w2 = __ldg(&pW2[j]);
        float c0 = siluf(acc0 + pb) * w2;
        float c1 = siluf(acc1 + pb) * w2;
        #pragma unroll
        for(int off=16; off; off>>=1){
          c0 += __shfl_xor_sync(0xffffffffu, c0, off);
          c1 += __shfl_xor_sync(0xffffffffu, c1, off);
        }
        int wwid = j >> 5;
        if((j & 31) == 0){ sred[wwid] = c0; sred[4+wwid] = c1; }
      }
      __syncthreads();
      if(tid == 0){
        float pb2v = __ldg(pb2);
        float coef0 = sred[0]+sred[1]+sred[2]+sred[3] + pb2v;
        float coef1 = sred[4]+sred[5]+sred[6]+sred[7] + pb2v;
        atomicAdd(&g_pd[(NN+ds)*3+0], (rel[1][0]*coef1 - rel[0][0]*coef0)*inv);
        atomicAdd(&g_pd[(NN+ds)*3+1], (rel[1][1]*coef1 - rel[0][1]*coef0)*inv);
        atomicAdd(&g_pd[(NN+ds)*3+2], (rel[1][2]*coef1 - rel[0][2]*coef0)*inv);
        g_newDirty[ds] = 1;
      }
      __syncthreads();
    }
  }
}

// ------------------- node update (tf32 MMA, batch-0 rows) -------------------
__global__ void __launch_bounds__(256,2) k_update(
    const float* __restrict__ bu1, const float* __restrict__ bu2, int l){
  __shared__ float sM[64*132];
  __shared__ float sB1[HH];
  __shared__ float sB2v[HH];
  int tid = threadIdx.x;
  int w = tid >> 5, lane = tid & 31;
  int gid = lane >> 2, tig = lane & 3;
  int base = blockIdx.x*64;
  int c4 = tid & 31, rs = tid >> 5;

  if(tid < HH){ sB1[tid] = bu1[tid]; sB2v[tid] = bu2[tid]; }

  float c[4][2][4];
  frag_zero(c);

  #pragma unroll
  for(int it=0; it<8; it++){
    int r = it*8 + rs;
    int rg = base + r;
    float4 v = make_float4(0.f,0.f,0.f,0.f);
    if(rg < NN){
      v = __ldg((const float4*)(g_h + (size_t)rg*HH) + c4);
      v.x = tf32r(v.x); v.y = tf32r(v.y); v.z = tf32r(v.z); v.w = tf32r(v.w);
    }
    *(float4*)(sM + r*132 + c4*4) = v;
  }
  __syncthreads();
  mma_accum64(sM, g_Wt + (size_t)(24 + l*2)*16384, w, gid, tig, c);
  __syncthreads();

  #pragma unroll
  for(int it=0; it<8; it++){
    int r = it*8 + rs;
    int rg = base + r;
    float4 v = make_float4(0.f,0.f,0.f,0.f);
    if(rg < NN){
      v = __ldg((const float4*)(g_msum + (size_t)rg*HH) + c4);
      v.x = tf32r(v.x); v.y = tf32r(v.y); v.z = tf32r(v.z); v.w = tf32r(v.w);
    }
    *(float4*)(sM + r*132 + c4*4) = v;
  }
  __syncthreads();
  mma_accum64(sM, g_Wt + (size_t)(24 + l*2 + 1)*16384, w, gid, tig, c);
  __syncthreads();

  #pragma unroll
  for(int rt=0;rt<4;rt++){
    #pragma unroll
    for(int ct=0;ct<2;ct++){
      int col0 = w*16 + ct*8 + 2*tig;
      int r0 = rt*16 + gid, r1 = r0 + 8;
      *(float2*)(sM + r0*132 + col0) = make_float2(
          tf32r(siluf(c[rt][ct][0] + sB1[col0])),
          tf32r(siluf(c[rt][ct][1] + sB1[col0+1])));
      *(float2*)(sM + r1*132 + col0) = make_float2(
          tf32r(siluf(c[rt][ct][2] + sB1[col0])),
          tf32r(siluf(c[rt][ct][3] + sB1[col0+1])));
    }
  }
  __syncthreads();

  frag_zero(c);
  mma_accum64(sM, g_Wt + (size_t)(28 + l)*16384, w, gid, tig, c);

  #pragma unroll
  for(int rt=0;rt<4;rt++){
    #pragma unroll
    for(int ct=0;ct<2;ct++){
      int col0 = w*16 + ct*8 + 2*tig;
      int r0 = base + rt*16 + gid, r1 = r0 + 8;
      if(r0 < NN){
        float2 hv = *(float2*)(g_h + (size_t)r0*HH + col0);
        hv.x += c[rt][ct][0] + sB2v[col0];
        hv.y += c[rt][ct][1] + sB2v[col0+1];
        *(float2*)(g_h + (size_t)r0*HH + col0) = hv;
      }
      if(r1 < NN){
        float2 hv = *(float2*)(g_h + (size_t)r1*HH + col0);
        hv.x += c[rt][ct][2] + sB2v[col0];
        hv.y += c[rt][ct][3] + sB2v[col0+1];
        *(float2*)(g_h + (size_t)r1*HH + col0) = hv;
      }
    }
  }
}

// ------------------- fused: clean b1 h copy + dirty b1 update fix -------------------
#define CPB ((NN*32+255)/256)
__global__ void __launch_bounds__(256) k_updfix_copy(
    const float* __restrict__ Wu1, const float* __restrict__ bu1,
    const float* __restrict__ Wu2, const float* __restrict__ bu2){
  __shared__ float sh[HH];
  __shared__ float sm[HH];
  __shared__ float st[HH];
  int tid = threadIdx.x;
  int bid = blockIdx.x;
  if(bid < CPB){
    int idx = bid*256 + tid;
    if(idx < NN*32){
      int c4 = idx & 31;
      int n  = idx >> 5;
      if(!g_dirty[n])
        ((float4*)(g_h + (size_t)(NN+n)*HH))[c4] = ((const float4*)(g_h + (size_t)n*HH))[c4];
    }
  } else {
    int j = tid & 127;
    int cnt = g_dcount;
    for(int i = bid - CPB; i < cnt; i += FIXG){
      int n = g_dlist[i];
      size_t row = (size_t)(NN+n)*HH;
      if(tid < 128){ sh[j] = g_h[row + j]; sm[j] = g_msum[row + j]; }
      __syncthreads();
      if(tid < 128){
        float acc = __ldg(&bu1[j]);
        #pragma unroll 4
        for(int kk=0; kk<HH; kk++){
          acc = fmaf(sh[kk], __ldg(&Wu1[kk*HH + j]), acc);
          acc = fmaf(sm[kk], __ldg(&Wu1[(128+kk)*HH + j]), acc);
        }
        st[j] = siluf(acc);
      }
      __syncthreads();
      if(tid < 128){
        float o = __ldg(&bu2[j]);
        #pragma unroll 4
        for(int kk=0; kk<HH; kk++)
          o = fmaf(st[kk], __ldg(&Wu2[kk*HH + j]), o);
        g_h[row + j] = sh[j] + o;
      }
      __syncthreads();
    }
  }
}

// ------------------- readout -------------------
__global__ void k_readout(const float* __restrict__ W1, const float* __restrict__ b1,
                          const float* __restrict__ W2, const float* __restrict__ b2,
                          const int* __restrict__ ent, float* __restrict__ out){
  __shared__ float se[HH];
  __shared__ float sred[HH];
  int j = threadIdx.x;
  for(int b=0; b<BB; b++){
    int row = b*NN + ent[b];
    se[j] = g_h[(size_t)row*HH + j];
    __syncthreads();
    float acc = b1[j];
    #pragma unroll 4
    for(int i=0;i<HH;i++) acc = fmaf(se[i], W1[i*HH+j], acc);
    sred[j] = siluf(acc) * W2[j];
    __syncthreads();
    for(int s=64; s>0; s>>=1){
      if(j<s) sred[j] += sred[j+s];
      __syncthreads();
    }
    if(j==0) out[b] = sred[0] + b2[0];
    __syncthreads();
  }
}

// ------------------- launch -------------------
extern "C" void kernel_launch(void* const* d_in, const int* in_sizes, int n_in,
                              void* d_out, int out_size){
  (void)in_sizes; (void)n_in; (void)out_size;
  const float* x     = (const float*)d_in[0];
  const float* basef = (const float*)d_in[1];
  const float* basep = (const float*)d_in[2];
  const float* Win   = (const float*)d_in[3];
  const float* b_in  = (const float*)d_in[4];
  const float* mW1   = (const float*)d_in[5];
  const float* mb1   = (const float*)d_in[6];
  const float* mW2   = (const float*)d_in[7];
  const float* mb2   = (const float*)d_in[8];
  const float* pW1   = (const float*)d_in[9];
  const float* pb1   = (const float*)d_in[10];
  const float* pW2   = (const float*)d_in[11];
  const float* pb2   = (const float*)d_in[12];
  const float* uW1   = (const float*)d_in[13];
  const float* ub1   = (const float*)d_in[14];
  const float* uW2   = (const float*)d_in[15];
  const float* ub2   = (const float*)d_in[16];
  const float* oW1   = (const float*)d_in[17];
  const float* ob1   = (const float*)d_in[18];
  const float* oW2   = (const float*)d_in[19];
  const float* ob2   = (const float*)d_in[20];
  const int*   ent   = (const int*)d_in[21];
  const int*   esrc  = (const int*)d_in[22];
  const int*   edst  = (const int*)d_in[23];
  float* out = (float*)d_out;

  k_round<<<(30*HH*HH+255)/256, 256>>>(mW1, mW2, pW1, uW1, uW2);

  k_deg_zero <<<(NBB*NN+255)/256, 256>>>();
  k_deg_count<<<(NBB*EE+255)/256, 256>>>(edst);
  k_deg_fin  <<<(NBB*NN+255)/256, 256>>>(ent);
  k_build_dlist<<<(NN+255)/256, 256>>>();

  k_init_h <<<NN, 128>>>(basef, Win, b_in);
  k_add_dyn<<<1, 256>>>(x, Win, ent);
  k_init_p <<<(NN*3+255)/256, 256>>>(basep);

  for(int l=0; l<LL; l++){
    k_zerobuild<<<ZBLK + ABLK, 256>>>(esrc, edst);
    for(int k=0; k<NBB; k++){
      int lk = l*NBB + k;
      const float* W1lk = mW1 + (size_t)lk*257*HH;
      k_gagb_all2<<<NTILES + FIXG, 256>>>(lk, W1lk);
      k_edge_delta<<<ETILES + DELTA_GRID, 256>>>(
          W1lk + 256*HH,
          mb1 + (size_t)lk*HH,
          mW2 + (size_t)lk*HH*HH,
          mb2 + (size_t)lk*HH,
          pW1 + (size_t)lk*HH*HH,
          pb1 + (size_t)lk*HH,
          pW2 + (size_t)lk*HH,
          pb2 + lk,
          esrc + (size_t)k*EE,
          edst + (size_t)k*EE,
          lk, k);
    }
    k_merge<<<(NN*HH+255)/256, 256>>>();
    k_build_dlist<<<(NN+255)/256, 256>>>();
    k_update<<<NTILES, 256>>>(
        ub1 + (size_t)l*HH,
        ub2 + (size_t)l*HH,
        l);
    k_updfix_copy<<<CPB + FIXG, 256>>>(
        uW1 + (size_t)l*2*HH*HH,
        ub1 + (size_t)l*HH,
        uW2 + (size_t)l*HH*HH,
        ub2 + (size_t)l*HH);
    k_padd<<<(ROWS_TOT*3+255)/256, 256>>>();
  }

  k_readout<<<1, 128>>>(oW1, ob1, oW2, ob2, ent, out);
}

// round 15
// speedup vs baseline: 1.1380x; 1.0285x over previous
#include <cuda_runtime.h>
#include <math.h>

#define BB 2
#define NN 10000
#define EE 100000
#define HH 128
#define DINN 8
#define DBB 16
#define LL 2
#define NBB 3
#define ROWS_TOT (BB*NN)
#define ETILES ((EE+63)/64)
#define NTILES ((NN+63)/64)
#define DELTA_GRID 592
#define FIXG 128
#define ZBLK ((ROWS_TOT*HH+255)/256)
#define ABLK ((NBB*EE+255)/256)
#define PBLK ((ROWS_TOT*3+255)/256)
#define CPB ((NN*32+255)/256)

// -------- scratch (device globals; no allocation anywhere) --------
__device__ float g_h[ROWS_TOT*HH];
__device__ float g_msum[ROWS_TOT*HH];
__device__ float g_Ga[2*ROWS_TOT*HH];   // double-buffered by k parity
__device__ float g_Gb[2*ROWS_TOT*HH];
__device__ float g_p[ROWS_TOT*3];
__device__ float g_pd[ROWS_TOT*3];
__device__ float g_invdeg[NBB*NN];
__device__ int   g_dirty[NN];
__device__ int   g_newDirty[NN];
__device__ int   g_acnt[NBB];
__device__ int   g_alist[NBB*EE];
__device__ int   g_dcount;
__device__ int   g_dlist[NN];
// tf32-rounded weights, 30 slabs of 128x128:
//  0..5  mW2 | 6..11 pW1 | 12..23 mW1 (lk*2+half) | 24..27 uW1 (l*2+half) | 28..29 uW2
__device__ float g_Wt[30*HH*HH];

// silu(x) = 0.5*x*(1+tanh(x/2)) — 1 MUFU
__device__ __forceinline__ float siluf(float x){
  float t;
  asm("tanh.approx.f32 %0, %1;" : "=f"(t) : "f"(0.5f*x));
  return 0.5f*x*(1.0f+t);
}

__device__ __forceinline__ float tf32r(float x){
  unsigned u;
  asm("cvt.rna.tf32.f32 %0, %1;" : "=r"(u) : "f"(x));
  return __uint_as_float(u);
}

// m16n8k8 tf32 MMA, fp32 accumulate (base PTX, sm_80+)
__device__ __forceinline__ void mma8(float c[4],
    unsigned a0, unsigned a1, unsigned a2, unsigned a3,
    unsigned b0, unsigned b1){
  asm volatile(
    "mma.sync.aligned.m16n8k8.row.col.f32.tf32.tf32.f32 "
    "{%0,%1,%2,%3}, {%4,%5,%6,%7}, {%8,%9}, {%0,%1,%2,%3};"
    : "+f"(c[0]), "+f"(c[1]), "+f"(c[2]), "+f"(c[3])
    : "r"(a0), "r"(a1), "r"(a2), "r"(a3), "r"(b0), "r"(b1));
}

__device__ __forceinline__ void redv4(float* addr, float x, float y, float z, float w){
  asm volatile("red.global.add.v4.f32 [%0], {%1, %2, %3, %4};"
               :: "l"(addr), "f"(x), "f"(y), "f"(z), "f"(w) : "memory");
}

// 64x128 += sM(64xK=128, stride 132, tf32) @ B(128x128 row-major tf32), per-warp 64x16 slab
__device__ __forceinline__ void mma_accum64(const float* __restrict__ sM,
                                            const float* __restrict__ B,
                                            int w, int gid, int tig,
                                            float c[4][2][4]){
  #pragma unroll 4
  for(int k0=0; k0<HH; k0+=8){
    unsigned a[4][4];
    #pragma unroll
    for(int rt=0;rt<4;rt++){
      int r = rt*16;
      a[rt][0] = __float_as_uint(sM[(r+gid)*132   + k0+tig]);
      a[rt][1] = __float_as_uint(sM[(r+8+gid)*132 + k0+tig]);
      a[rt][2] = __float_as_uint(sM[(r+gid)*132   + k0+tig+4]);
      a[rt][3] = __float_as_uint(sM[(r+8+gid)*132 + k0+tig+4]);
    }
    #pragma unroll
    for(int ct=0;ct<2;ct++){
      int n = w*16 + ct*8 + gid;
      unsigned b0 = __float_as_uint(__ldg(&B[(k0+tig)*HH   + n]));
      unsigned b1r = __float_as_uint(__ldg(&B[(k0+tig+4)*HH + n]));
      #pragma unroll
      for(int rt=0;rt<4;rt++)
        mma8(c[rt][ct], a[rt][0],a[rt][1],a[rt][2],a[rt][3], b0,b1r);
    }
  }
}
__device__ __forceinline__ void frag_zero(float c[4][2][4]){
  #pragma unroll
  for(int rt=0;rt<4;rt++)
    #pragma unroll
    for(int ct=0;ct<2;ct++)
      #pragma unroll
      for(int q=0;q<4;q++) c[rt][ct][q]=0.f;
}

// shared gagb body: MMA blocks [0,NTILES) write slab rows <NN; fix blocks recompute dirty b1 rows
__device__ void gagb_body(int role_bid, int lk, const float* __restrict__ W1,
                          int slab, float* sM){
  int tid = threadIdx.x;
  float* Ga = g_Ga + (size_t)slab*ROWS_TOT*HH;
  float* Gb = g_Gb + (size_t)slab*ROWS_TOT*HH;
  if(role_bid < NTILES){
    int w = tid >> 5, lane = tid & 31;
    int gid = lane >> 2, tig = lane & 3;
    int base = role_bid*64;
    {
      int c4 = tid & 31, rs = tid >> 5;
      #pragma unroll
      for(int it=0; it<8; it++){
        int r = it*8 + rs;
        int rg = base + r;
        float4 v = make_float4(0.f,0.f,0.f,0.f);
        if(rg < NN){
          v = __ldg((const float4*)(g_h + (size_t)rg*HH) + c4);
          v.x = tf32r(v.x); v.y = tf32r(v.y); v.z = tf32r(v.z); v.w = tf32r(v.w);
        }
        *(float4*)(sM + r*132 + c4*4) = v;
      }
    }
    __syncthreads();

    const float* Wa = g_Wt + (size_t)(12 + lk*2    )*16384;
    const float* Wb = g_Wt + (size_t)(12 + lk*2 + 1)*16384;
    float c[4][2][4];
    #pragma unroll
    for(int half=0; half<2; half++){
      frag_zero(c);
      mma_accum64(sM, half ? Wb : Wa, w, gid, tig, c);
      float* out = half ? Gb : Ga;
      #pragma unroll
      for(int rt=0;rt<4;rt++){
        #pragma unroll
        for(int ct=0;ct<2;ct++){
          int col0 = w*16 + ct*8 + 2*tig;
          int r0 = base + rt*16 + gid, r1 = r0 + 8;
          if(r0 < NN) *(float2*)(out + (size_t)r0*HH + col0) = make_float2(c[rt][ct][0], c[rt][ct][1]);
          if(r1 < NN) *(float2*)(out + (size_t)r1*HH + col0) = make_float2(c[rt][ct][2], c[rt][ct][3]);
        }
      }
    }
  } else {
    float* sh = sM;
    int j = tid & 127;
    bool act = tid < 128;
    int cnt = g_dcount;
    for(int i = role_bid - NTILES; i < cnt; i += FIXG){
      int n = g_dlist[i];
      if(act) sh[j] = g_h[(size_t)(NN+n)*HH + j];
      __syncthreads();
      if(act){
        float a = 0.f, bv = 0.f;
        #pragma unroll 4
        for(int kk=0; kk<HH; kk++){
          float hv = sh[kk];
          a  = fmaf(hv, __ldg(&W1[kk*HH + j]), a);
          bv = fmaf(hv, __ldg(&W1[(128+kk)*HH + j]), bv);
        }
        Ga[(size_t)(NN+n)*HH + j] = a;
        Gb[(size_t)(NN+n)*HH + j] = bv;
      }
      __syncthreads();
    }
  }
}

// ------------------- weight rounding -------------------
__global__ void k_round(const float* __restrict__ mW1, const float* __restrict__ mW2,
                        const float* __restrict__ pW1, const float* __restrict__ uW1,
                        const float* __restrict__ uW2){
  int gi = blockIdx.x*blockDim.x + threadIdx.x;
  if(gi >= 30*HH*HH) return;
  int slot = gi >> 14;
  int e    = gi & 16383;
  float v;
  if      (slot < 6)  v = mW2[(size_t)slot*16384 + e];
  else if (slot < 12) v = pW1[(size_t)(slot-6)*16384 + e];
  else if (slot < 24){ int s = slot-12; v = mW1[(size_t)(s>>1)*257*HH + (size_t)(s&1)*16384 + e]; }
  else if (slot < 28){ int s = slot-24; v = uW1[(size_t)(s>>1)*2*16384 + (size_t)(s&1)*16384 + e]; }
  else                v = uW2[(size_t)(slot-28)*16384 + e];
  g_Wt[gi] = tf32r(v);
}

// ------------------- small setup kernels -------------------
__global__ void k_deg_zero(){
  int i = blockIdx.x*blockDim.x + threadIdx.x;
  if(i < NBB*NN) g_invdeg[i] = 0.f;
  if(i < NN) g_dirty[i] = 0;
}
__global__ void k_deg_count(const int* __restrict__ edst){
  int i = blockIdx.x*blockDim.x + threadIdx.x;
  if(i < NBB*EE){
    int k = i / EE;
    atomicAdd(&g_invdeg[k*NN + edst[i]], 1.f);
  }
}
__global__ void k_deg_fin(const int* __restrict__ ent){
  int i = blockIdx.x*blockDim.x + threadIdx.x;
  if(i < NBB*NN) g_invdeg[i] = 1.f / fmaxf(g_invdeg[i], 1.f);
  if(i < BB) g_dirty[ent[i]] = 1;
  if(i < NBB) g_acnt[i] = 0;
  if(i == 0) g_dcount = 0;
}

__global__ void k_build_dlist(){
  int i = blockIdx.x*blockDim.x + threadIdx.x;
  if(i < NN && g_dirty[i]){
    int p = atomicAdd(&g_dcount, 1);
    g_dlist[p] = i;
  }
}

__global__ void k_init_h(const float* __restrict__ base, const float* __restrict__ Win,
                         const float* __restrict__ b_in){
  int n = blockIdx.x, j = threadIdx.x;
  float acc = b_in[j];
  #pragma unroll
  for(int d=0; d<DBB; d++)
    acc = fmaf(__ldg(&base[n*DBB+d]), __ldg(&Win[d*HH+j]), acc);
  g_h[n*HH+j] = acc;
  g_h[(NN+n)*HH+j] = acc;
}

__global__ void k_add_dyn(const float* __restrict__ x, const float* __restrict__ Win,
                          const int* __restrict__ ent){
  int t = threadIdx.x;
  if(t < BB*HH){
    int b = t >> 7, j = t & (HH-1);
    float acc = 0.f;
    #pragma unroll
    for(int d=0; d<DINN; d++)
      acc = fmaf(x[b*DINN+d], Win[(DBB+d)*HH+j], acc);
    g_h[((size_t)b*NN + ent[b])*HH + j] += acc;
  }
}

__global__ void k_init_p(const float* __restrict__ bp){
  int i = blockIdx.x*blockDim.x + threadIdx.x;
  if(i < NN*3){ float v = bp[i]; g_p[i] = v; g_p[NN*3+i] = v; }
}

// fused: zero msum/pd/newDirty + build affected-edge lists (acnt zeroed by prior launch)
__global__ void k_zerobuild(const int* __restrict__ esrc, const int* __restrict__ edst){
  int bid = blockIdx.x, tid = threadIdx.x;
  if(bid < ZBLK){
    int i = bid*256 + tid;
    if(i < ROWS_TOT*HH) g_msum[i] = 0.f;
    if(i < ROWS_TOT*3)  g_pd[i]   = 0.f;
    if(i < NN)          g_newDirty[i] = 0;
  } else {
    int i = (bid - ZBLK)*256 + tid;
    if(i < NBB*EE){
      int k = i / EE;
      int e = i - k*EE;
      if(g_dirty[esrc[i]] | g_dirty[edst[i]]){
        int pos = atomicAdd(&g_acnt[k], 1);
        g_alist[k*EE + pos] = e;
      }
    }
  }
}

__global__ void k_merge(){
  int i = blockIdx.x*blockDim.x + threadIdx.x;
  if(i < NN*HH) g_msum[(size_t)NN*HH + i] += g_msum[i];
  if(i < NN*3)  g_pd[NN*3 + i] += g_pd[i];
  if(i < NN){ if(g_newDirty[i]) g_dirty[i] = 1; }
  if(i < NBB) g_acnt[i] = 0;
  if(i == 0) g_dcount = 0;
}

// standalone gagb (layer start, k=0)
__global__ void __launch_bounds__(256,2) k_gagb_all2(int lk, const float* __restrict__ W1, int slab){
  __shared__ float sM[64*132];
  gagb_body(blockIdx.x, lk, W1, slab, sM);
}

// ------------------- fused edge(k) + delta(k) + gagb(k+1) -------------------
__global__ void __launch_bounds__(256,2) k_edge_delta(
    const float* __restrict__ W1r, const float* __restrict__ b1,
    const float* __restrict__ W2f, const float* __restrict__ b2,
    const float* __restrict__ pW1f,const float* __restrict__ pb1,
    const float* __restrict__ pW2, const float* __restrict__ pb2,
    const int* __restrict__ esrc,  const int* __restrict__ edst,
    int lk, int kdeg, int slab,
    const float* __restrict__ nW1, int nlk){
  __shared__ float sM[64*132];
  __shared__ int   sDst[64];
  __shared__ int   sSrc[64];
  __shared__ float sInv[64];
  __shared__ float sD2[64];
  __shared__ float sRel[64*3];
  __shared__ float sCoef[64];
  __shared__ float sB2[HH];
  __shared__ float sPB1[HH];
  __shared__ float sPW2[HH];

  int tid = threadIdx.x;
  int bid = blockIdx.x;
  const float* Ga = g_Ga + (size_t)slab*ROWS_TOT*HH;
  const float* Gb = g_Gb + (size_t)slab*ROWS_TOT*HH;

  if(bid < ETILES){
    // ======== edge role ========
    int w = tid >> 5, lane = tid & 31;
    int gid = lane >> 2, tig = lane & 3;
    int base = bid*64;

    if(tid < 64){
      int e = base + tid;
      bool v = e < EE;
      int ee = v ? e : 0;
      int ds = edst[ee], sr = esrc[ee];
      float rx = g_p[ds*3+0] - g_p[sr*3+0];
      float ry = g_p[ds*3+1] - g_p[sr*3+1];
      float rz = g_p[ds*3+2] - g_p[sr*3+2];
      sRel[tid*3+0] = rx; sRel[tid*3+1] = ry; sRel[tid*3+2] = rz;
      sD2[tid]  = rx*rx + ry*ry + rz*rz;
      sInv[tid] = v ? g_invdeg[kdeg*NN + ds] : 0.f;
      sDst[tid] = ds;
      sSrc[tid] = sr;
      sCoef[tid] = 0.f;
    }
    if(tid < HH){
      sB2[tid]  = b2[tid];
      sPB1[tid] = pb1[tid];
      sPW2[tid] = pW2[tid];
    }
    __syncthreads();

    {
      int c4 = tid & 31, rs = tid >> 5;
      float4 w4 = __ldg((const float4*)W1r + c4);
      float4 bb = __ldg((const float4*)b1  + c4);
      #pragma unroll
      for(int it=0; it<8; it++){
        int r = it*8 + rs;
        float4 ga = __ldg((const float4*)(Ga + (size_t)sDst[r]*HH) + c4);
        float4 gb = __ldg((const float4*)(Gb + (size_t)sSrc[r]*HH) + c4);
        float d2 = sD2[r];
        float4 o;
        o.x = tf32r(siluf(ga.x + gb.x + d2*w4.x + bb.x));
        o.y = tf32r(siluf(ga.y + gb.y + d2*w4.y + bb.y));
        o.z = tf32r(siluf(ga.z + gb.z + d2*w4.z + bb.z));
        o.w = tf32r(siluf(ga.w + gb.w + d2*w4.w + bb.w));
        *(float4*)(sM + r*132 + c4*4) = o;
      }
    }
    __syncthreads();

    float c[4][2][4];
    frag_zero(c);
    mma_accum64(sM, g_Wt + (size_t)lk*16384, w, gid, tig, c);
    __syncthreads();

    #pragma unroll
    for(int rt=0;rt<4;rt++){
      #pragma unroll
      for(int ct=0;ct<2;ct++){
        int col0 = w*16 + ct*8 + 2*tig;
        int r0 = rt*16 + gid, r1 = r0 + 8;
        float v00 = siluf(c[rt][ct][0] + sB2[col0]);
        float v01 = siluf(c[rt][ct][1] + sB2[col0+1]);
        float v10 = siluf(c[rt][ct][2] + sB2[col0]);
        float v11 = siluf(c[rt][ct][3] + sB2[col0+1]);
        float i0 = sInv[r0], i1 = sInv[r1];
        float s00 = v00*i0, s01 = v01*i0;
        float s10 = v10*i1, s11 = v11*i1;
        float o00 = __shfl_xor_sync(0xffffffffu, s00, 1);
        float o01 = __shfl_xor_sync(0xffffffffu, s01, 1);
        float o10 = __shfl_xor_sync(0xffffffffu, s10, 1);
        float o11 = __shfl_xor_sync(0xffffffffu, s11, 1);
        if((tig & 1) == 0){
          int cb = w*16 + ct*8 + 4*(tig>>1);
          redv4(g_msum + (size_t)sDst[r0]*HH + cb, s00, s01, o00, o01);
          redv4(g_msum + (size_t)sDst[r1]*HH + cb, s10, s11, o10, o11);
        }
        *(float2*)(sM + r0*132 + col0) = make_float2(tf32r(v00), tf32r(v01));
        *(float2*)(sM + r1*132 + col0) = make_float2(tf32r(v10), tf32r(v11));
      }
    }
    __syncthreads();

    frag_zero(c);
    mma_accum64(sM, g_Wt + (size_t)(6+lk)*16384, w, gid, tig, c);

    float rsum[4][2];
    #pragma unroll
    for(int rt=0;rt<4;rt++){ rsum[rt][0]=0.f; rsum[rt][1]=0.f; }
    #pragma unroll
    for(int rt=0;rt<4;rt++){
      #pragma unroll
      for(int ct=0;ct<2;ct++){
        int col0 = w*16 + ct*8 + 2*tig;
        float w0 = sPW2[col0], w1 = sPW2[col0+1];
        float p0 = sPB1[col0], p1 = sPB1[col0+1];
        rsum[rt][0] = fmaf(siluf(c[rt][ct][0]+p0), w0,
                      fmaf(siluf(c[rt][ct][1]+p1), w1, rsum[rt][0]));
        rsum[rt][1] = fmaf(siluf(c[rt][ct][2]+p0), w0,
                      fmaf(siluf(c[rt][ct][3]+p1), w1, rsum[rt][1]));
      }
    }
    #pragma unroll
    for(int off=1; off<4; off<<=1){
      #pragma unroll
      for(int rt=0;rt<4;rt++){
        rsum[rt][0] += __shfl_xor_sync(0xffffffffu, rsum[rt][0], off);
        rsum[rt][1] += __shfl_xor_sync(0xffffffffu, rsum[rt][1], off);
      }
    }
    if(tig == 0){
      #pragma unroll
      for(int rt=0;rt<4;rt++){
        atomicAdd(&sCoef[rt*16 + gid],     rsum[rt][0]);
        atomicAdd(&sCoef[rt*16 + 8 + gid], rsum[rt][1]);
      }
    }
    __syncthreads();

    if(tid < 64){
      float s = (sCoef[tid] + __ldg(pb2)) * sInv[tid];
      int row = sDst[tid];
      atomicAdd(&g_pd[row*3+0], sRel[tid*3+0]*s);
      atomicAdd(&g_pd[row*3+1], sRel[tid*3+1]*s);
      atomicAdd(&g_pd[row*3+2], sRel[tid*3+2]*s);
    }
  } else if(bid < ETILES + DELTA_GRID){
    // ======== delta role (clean-node b1 reads redirected to b0 rows) ========
    float (*sm1)[HH] = (float(*)[HH])sM;
    float (*sm2)[HH] = (float(*)[HH])(sM + 2*HH);
    float* sred = sM + 4*HH;
    int j = tid & 127;
    bool act = tid < 128;
    int cnt = g_acnt[kdeg];
    const int* alist = g_alist + (size_t)kdeg*EE;
    for(int idx = bid - ETILES; idx < cnt; idx += DELTA_GRID){
      int ds=0, sr=0; float inv=0.f;
      float rel[2][3];
      if(act){
        int e = alist[idx];
        ds = edst[e]; sr = esrc[e];
        inv = g_invdeg[kdeg*NN + ds];
        int dDirty = g_dirty[ds], sDirty = g_dirty[sr];
        #pragma unroll
        for(int b=0;b<2;b++){
          int dr = b*NN + ds, srr = b*NN + sr;
          rel[b][0] = g_p[dr*3+0] - g_p[srr*3+0];
          rel[b][1] = g_p[dr*3+1] - g_p[srr*3+1];
          rel[b][2] = g_p[dr*3+2] - g_p[srr*3+2];
          float d2 = rel[b][0]*rel[b][0] + rel[b][1]*rel[b][1] + rel[b][2]*rel[b][2];
          int ga_row = (b==1 && !dDirty) ? ds : dr;
          int gb_row = (b==1 && !sDirty) ? sr : srr;
          sm1[b][j] = siluf(Ga[(size_t)ga_row*HH+j] + Gb[(size_t)gb_row*HH+j]
                            + d2*__ldg(&W1r[j]) + __ldg(&b1[j]));
        }
      }
      __syncthreads();
      if(act){
        float acc0 = 0.f, acc1 = 0.f;
        #pragma unroll 4
        for(int k=0;k<HH;k++){
          float w = __ldg(&W2f[k*HH+j]);
          acc0 = fmaf(sm1[0][k], w, acc0);
          acc1 = fmaf(sm1[1][k], w, acc1);
        }
        float bb = __ldg(&b2[j]);
        float m20 = siluf(acc0 + bb);
        float m21 = siluf(acc1 + bb);
        atomicAdd(&g_msum[(size_t)(NN+ds)*HH + j], (m21 - m20)*inv);
        sm2[0][j] = m20; sm2[1][j] = m21;
      }
      __syncthreads();
      if(act){
        float acc0 = 0.f, acc1 = 0.f;
        #pragma unroll 4
        for(int k=0;k<HH;k++){
          float w = __ldg(&pW1f[k*HH+j]);
          acc0 = fmaf(sm2[0][k], w, acc0);
          acc1 = fmaf(sm2[1][k], w, acc1);
        }
        float pb = __ldg(&pb1[j]);
        float w2 = __ldg(&pW2[j]);
        float c0 = siluf(acc0 + pb) * w2;
        float c1 = siluf(acc1 + pb) * w2;
        #pragma unroll
        for(int off=16; off; off>>=1){
          c0 += __shfl_xor_sync(0xffffffffu, c0, off);
          c1 += __shfl_xor_sync(0xffffffffu, c1, off);
        }
        int wwid = j >> 5;
        if((j & 31) == 0){ sred[wwid] = c0; sred[4+wwid] = c1; }
      }
      __syncthreads();
      if(tid == 0){
        float pb2v = __ldg(pb2);
        float coef0 = sred[0]+sred[1]+sred[2]+sred[3] + pb2v;
        float coef1 = sred[4]+sred[5]+sred[6]+sred[7] + pb2v;
        atomicAdd(&g_pd[(NN+ds)*3+0], (rel[1][0]*coef1 - rel[0][0]*coef0)*inv);
        atomicAdd(&g_pd[(NN+ds)*3+1], (rel[1][1]*coef1 - rel[0][1]*coef0)*inv);
        atomicAdd(&g_pd[(NN+ds)*3+2], (rel[1][2]*coef1 - rel[0][2]*coef0)*inv);
        g_newDirty[ds] = 1;
      }
      __syncthreads();
    }
  } else {
    // ======== gagb role for NEXT k (writes other slab — disjoint, race-free) ========
    gagb_body(bid - ETILES - DELTA_GRID, nlk, nW1, slab^1, sM);
  }
}

// ------------------- node update (tf32 MMA, batch-0 rows) + fused padd -------------------
__global__ void __launch_bounds__(256,2) k_update(
    const float* __restrict__ bu1, const float* __restrict__ bu2, int l){
  __shared__ float sM[64*132];
  __shared__ float sB1[HH];
  __shared__ float sB2v[HH];
  int tid = threadIdx.x;
  int bid = blockIdx.x;

  if(bid >= NTILES){
    // padd role: p += pd (pd finalized by merge; disjoint from h writes)
    int i = (bid - NTILES)*256 + tid;
    if(i < ROWS_TOT*3) g_p[i] += g_pd[i];
    return;
  }

  int w = tid >> 5, lane = tid & 31;
  int gid = lane >> 2, tig = lane & 3;
  int base = bid*64;
  int c4 = tid & 31, rs = tid >> 5;

  if(tid < HH){ sB1[tid] = bu1[tid]; sB2v[tid] = bu2[tid]; }

  float c[4][2][4];
  frag_zero(c);

  #pragma unroll
  for(int it=0; it<8; it++){
    int r = it*8 + rs;
    int rg = base + r;
    float4 v = make_float4(0.f,0.f,0.f,0.f);
    if(rg < NN){
      v = __ldg((const float4*)(g_h + (size_t)rg*HH) + c4);
      v.x = tf32r(v.x); v.y = tf32r(v.y); v.z = tf32r(v.z); v.w = tf32r(v.w);
    }
    *(float4*)(sM + r*132 + c4*4) = v;
  }
  __syncthreads();
  mma_accum64(sM, g_Wt + (size_t)(24 + l*2)*16384, w, gid, tig, c);
  __syncthreads();

  #pragma unroll
  for(int it=0; it<8; it++){
    int r = it*8 + rs;
    int rg = base + r;
    float4 v = make_float4(0.f,0.f,0.f,0.f);
    if(rg < NN){
      v = __ldg((const float4*)(g_msum + (size_t)rg*HH) + c4);
      v.x = tf32r(v.x); v.y = tf32r(v.y); v.z = tf32r(v.z); v.w = tf32r(v.w);
    }
    *(float4*)(sM + r*132 + c4*4) = v;
  }
  __syncthreads();
  mma_accum64(sM, g_Wt + (size_t)(24 + l*2 + 1)*16384, w, gid, tig, c);
  __syncthreads();

  #pragma unroll
  for(int rt=0;rt<4;rt++){
    #pragma unroll
    for(int ct=0;ct<2;ct++){
      int col0 = w*16 + ct*8 + 2*tig;
      int r0 = rt*16 + gid, r1 = r0 + 8;
      *(float2*)(sM + r0*132 + col0) = make_float2(
          tf32r(siluf(c[rt][ct][0] + sB1[col0])),
          tf32r(siluf(c[rt][ct][1] + sB1[col0+1])));
      *(float2*)(sM + r1*132 + col0) = make_float2(
          tf32r(siluf(c[rt][ct][2] + sB1[col0])),
          tf32r(siluf(c[rt][ct][3] + sB1[col0+1])));
    }
  }
  __syncthreads();

  frag_zero(c);
  mma_accum64(sM, g_Wt + (size_t)(28 + l)*16384, w, gid, tig, c);

  #pragma unroll
  for(int rt=0;rt<4;rt++){
    #pragma unroll
    for(int ct=0;ct<2;ct++){
      int col0 = w*16 + ct*8 + 2*tig;
      int r0 = base + rt*16 + gid, r1 = r0 + 8;
      if(r0 < NN){
        float2 hv = *(float2*)(g_h + (size_t)r0*HH + col0);
        hv.x += c[rt][ct][0] + sB2v[col0];
        hv.y += c[rt][ct][1] + sB2v[col0+1];
        *(float2*)(g_h + (size_t)r0*HH + col0) = hv;
      }
      if(r1 < NN){
        float2 hv = *(float2*)(g_h + (size_t)r1*HH + col0);
        hv.x += c[rt][ct][2] + sB2v[col0];
        hv.y += c[rt][ct][3] + sB2v[col0+1];
        *(float2*)(g_h + (size_t)r1*HH + col0) = hv;
      }
    }
  }
}

// ------------------- fused: clean b1 h copy + dirty b1 update fix -------------------
__global__ void __launch_bounds__(256) k_updfix_copy(
    const float* __restrict__ Wu1, const float* __restrict__ bu1,
    const float* __restrict__ Wu2, const float* __restrict__ bu2){
  __shared__ float sh[HH];
  __shared__ float sm[HH];
  __shared__ float st[HH];
  int tid = threadIdx.x;
  int bid = blockIdx.x;
  if(bid < CPB){
    int idx = bid*256 + tid;
    if(idx < NN*32){
      int c4 = idx & 31;
      int n  = idx >> 5;
      if(!g_dirty[n])
        ((float4*)(g_h + (size_t)(NN+n)*HH))[c4] = ((const float4*)(g_h + (size_t)n*HH))[c4];
    }
  } else {
    int j = tid & 127;
    int cnt = g_dcount;
    for(int i = bid - CPB; i < cnt; i += FIXG){
      int n = g_dlist[i];
      size_t row = (size_t)(NN+n)*HH;
      if(tid < 128){ sh[j] = g_h[row + j]; sm[j] = g_msum[row + j]; }
      __syncthreads();
      if(tid < 128){
        float acc = __ldg(&bu1[j]);
        #pragma unroll 4
        for(int kk=0; kk<HH; kk++){
          acc = fmaf(sh[kk], __ldg(&Wu1[kk*HH + j]), acc);
          acc = fmaf(sm[kk], __ldg(&Wu1[(128+kk)*HH + j]), acc);
        }
        st[j] = siluf(acc);
      }
      __syncthreads();
      if(tid < 128){
        float o = __ldg(&bu2[j]);
        #pragma unroll 4
        for(int kk=0; kk<HH; kk++)
          o = fmaf(st[kk], __ldg(&Wu2[kk*HH + j]), o);
        g_h[row + j] = sh[j] + o;
      }
      __syncthreads();
    }
  }
}

// ------------------- readout -------------------
__global__ void k_readout(const float* __restrict__ W1, const float* __restrict__ b1,
                          const float* __restrict__ W2, const float* __restrict__ b2,
                          const int* __restrict__ ent, float* __restrict__ out){
  __shared__ float se[HH];
  __shared__ float sred[HH];
  int j = threadIdx.x;
  for(int b=0; b<BB; b++){
    int row = b*NN + ent[b];
    se[j] = g_h[(size_t)row*HH + j];
    __syncthreads();
    float acc = b1[j];
    #pragma unroll 4
    for(int i=0;i<HH;i++) acc = fmaf(se[i], W1[i*HH+j], acc);
    sred[j] = siluf(acc) * W2[j];
    __syncthreads();
    for(int s=64; s>0; s>>=1){
      if(j<s) sred[j] += sred[j+s];
      __syncthreads();
    }
    if(j==0) out[b] = sred[0] + b2[0];
    __syncthreads();
  }
}

// ------------------- launch -------------------
extern "C" void kernel_launch(void* const* d_in, const int* in_sizes, int n_in,
                              void* d_out, int out_size){
  (void)in_sizes; (void)n_in; (void)out_size;
  const float* x     = (const float*)d_in[0];
  const float* basef = (const float*)d_in[1];
  const float* basep = (const float*)d_in[2];
  const float* Win   = (const float*)d_in[3];
  const float* b_in  = (const float*)d_in[4];
  const float* mW1   = (const float*)d_in[5];
  const float* mb1   = (const float*)d_in[6];
  const float* mW2   = (const float*)d_in[7];
  const float* mb2   = (const float*)d_in[8];
  const float* pW1   = (const float*)d_in[9];
  const float* pb1   = (const float*)d_in[10];
  const float* pW2   = (const float*)d_in[11];
  const float* pb2   = (const float*)d_in[12];
  const float* uW1   = (const float*)d_in[13];
  const float* ub1   = (const float*)d_in[14];
  const float* uW2   = (const float*)d_in[15];
  const float* ub2   = (const float*)d_in[16];
  const float* oW1   = (const float*)d_in[17];
  const float* ob1   = (const float*)d_in[18];
  const float* oW2   = (const float*)d_in[19];
  const float* ob2   = (const float*)d_in[20];
  const int*   ent   = (const int*)d_in[21];
  const int*   esrc  = (const int*)d_in[22];
  const int*   edst  = (const int*)d_in[23];
  float* out = (float*)d_out;

  k_round<<<(30*HH*HH+255)/256, 256>>>(mW1, mW2, pW1, uW1, uW2);

  k_deg_zero <<<(NBB*NN+255)/256, 256>>>();
  k_deg_count<<<(NBB*EE+255)/256, 256>>>(edst);
  k_deg_fin  <<<(NBB*NN+255)/256, 256>>>(ent);
  k_build_dlist<<<(NN+255)/256, 256>>>();

  k_init_h <<<NN, 128>>>(basef, Win, b_in);
  k_add_dyn<<<1, 256>>>(x, Win, ent);
  k_init_p <<<(NN*3+255)/256, 256>>>(basep);

  for(int l=0; l<LL; l++){
    k_zerobuild<<<ZBLK + ABLK, 256>>>(esrc, edst);
    k_gagb_all2<<<NTILES + FIXG, 256>>>(l*NBB, mW1 + (size_t)(l*NBB)*257*HH, 0);
    for(int k=0; k<NBB; k++){
      int lk = l*NBB + k;
      const float* W1lk = mW1 + (size_t)lk*257*HH;
      int have_next = (k+1 < NBB);
      int nlk = lk + 1;
      const float* nW1 = mW1 + (size_t)nlk*257*HH;
      int grid = ETILES + DELTA_GRID + (have_next ? (NTILES + FIXG) : 0);
      k_edge_delta<<<grid, 256>>>(
          W1lk + 256*HH,
          mb1 + (size_t)lk*HH,
          mW2 + (size_t)lk*HH*HH,
          mb2 + (size_t)lk*HH,
          pW1 + (size_t)lk*HH*HH,
          pb1 + (size_t)lk*HH,
          pW2 + (size_t)lk*HH,
          pb2 + lk,
          esrc + (size_t)k*EE,
          edst + (size_t)k*EE,
          lk, k, k & 1,
          nW1, nlk);
    }
    k_merge<<<(NN*HH+255)/256, 256>>>();
    k_build_dlist<<<(NN+255)/256, 256>>>();
    k_update<<<NTILES + PBLK, 256>>>(
        ub1 + (size_t)l*HH,
        ub2 + (size_t)l*HH,
        l);
    k_updfix_copy<<<CPB + FIXG, 256>>>(
        uW1 + (size_t)l*2*HH*HH,
        ub1 + (size_t)l*HH,
        uW2 + (size_t)l*HH*HH,
        ub2 + (size_t)l*HH);
  }

  k_readout<<<1, 128>>>(oW1, ob1, oW2, ob2, ent, out);
}

// round 16
// speedup vs baseline: 1.1941x; 1.0493x over previous
#include <cuda_runtime.h>
#include <math.h>

#define BB 2
#define NN 10000
#define EE 100000
#define HH 128
#define DINN 8
#define DBB 16
#define LL 2
#define NBB 3
#define ROWS_TOT (BB*NN)
#define ETILES ((EE+63)/64)
#define NTILES ((NN+63)/64)
#define DELTA_GRID 592
#define FIXG 128
#define ZBLK ((ROWS_TOT*HH+255)/256)
#define ABLK ((NBB*EE+255)/256)
#define PBLK ((ROWS_TOT*3+255)/256)
#define IPB  ((NN*3+255)/256)
#define CPB ((NN*32+255)/256)

// -------- scratch (device globals; no allocation anywhere) --------
__device__ float g_h[ROWS_TOT*HH];
__device__ float g_msum[ROWS_TOT*HH];
__device__ float g_Ga[2*ROWS_TOT*HH];   // double-buffered by k parity
__device__ float g_Gb[2*ROWS_TOT*HH];
__device__ float g_p[ROWS_TOT*3];
__device__ float g_pd[ROWS_TOT*3];
__device__ float g_invdeg[NBB*NN];
__device__ int   g_dirty[NN];
__device__ int   g_newDirty[NN];
__device__ int   g_acnt[NBB];
__device__ int   g_alist[NBB*EE];
__device__ int   g_dcount;          // monotone within a call; seeded by deg_fin
__device__ int   g_dlist[NN];
// tf32-rounded weights, 30 slabs of 128x128:
//  0..5  mW2 | 6..11 pW1 | 12..23 mW1 (lk*2+half) | 24..27 uW1 (l*2+half) | 28..29 uW2
__device__ float g_Wt[30*HH*HH];

// silu(x) = 0.5*x*(1+tanh(x/2)) — 1 MUFU
__device__ __forceinline__ float siluf(float x){
  float t;
  asm("tanh.approx.f32 %0, %1;" : "=f"(t) : "f"(0.5f*x));
  return 0.5f*x*(1.0f+t);
}

__device__ __forceinline__ float tf32r(float x){
  unsigned u;
  asm("cvt.rna.tf32.f32 %0, %1;" : "=r"(u) : "f"(x));
  return __uint_as_float(u);
}

// m16n8k8 tf32 MMA, fp32 accumulate (base PTX, sm_80+)
__device__ __forceinline__ void mma8(float c[4],
    unsigned a0, unsigned a1, unsigned a2, unsigned a3,
    unsigned b0, unsigned b1){
  asm volatile(
    "mma.sync.aligned.m16n8k8.row.col.f32.tf32.tf32.f32 "
    "{%0,%1,%2,%3}, {%4,%5,%6,%7}, {%8,%9}, {%0,%1,%2,%3};"
    : "+f"(c[0]), "+f"(c[1]), "+f"(c[2]), "+f"(c[3])
    : "r"(a0), "r"(a1), "r"(a2), "r"(a3), "r"(b0), "r"(b1));
}

__device__ __forceinline__ void redv4(float* addr, float x, float y, float z, float w){
  asm volatile("red.global.add.v4.f32 [%0], {%1, %2, %3, %4};"
               :: "l"(addr), "f"(x), "f"(y), "f"(z), "f"(w) : "memory");
}

// 64x128 += sM(64xK=128, stride 132, tf32) @ B(128x128 row-major tf32), per-warp 64x16 slab
__device__ __forceinline__ void mma_accum64(const float* __restrict__ sM,
                                            const float* __restrict__ B,
                                            int w, int gid, int tig,
                                            float c[4][2][4]){
  #pragma unroll 4
  for(int k0=0; k0<HH; k0+=8){
    unsigned a[4][4];
    #pragma unroll
    for(int rt=0;rt<4;rt++){
      int r = rt*16;
      a[rt][0] = __float_as_uint(sM[(r+gid)*132   + k0+tig]);
      a[rt][1] = __float_as_uint(sM[(r+8+gid)*132 + k0+tig]);
      a[rt][2] = __float_as_uint(sM[(r+gid)*132   + k0+tig+4]);
      a[rt][3] = __float_as_uint(sM[(r+8+gid)*132 + k0+tig+4]);
    }
    #pragma unroll
    for(int ct=0;ct<2;ct++){
      int n = w*16 + ct*8 + gid;
      unsigned b0 = __float_as_uint(__ldg(&B[(k0+tig)*HH   + n]));
      unsigned b1r = __float_as_uint(__ldg(&B[(k0+tig+4)*HH + n]));
      #pragma unroll
      for(int rt=0;rt<4;rt++)
        mma8(c[rt][ct], a[rt][0],a[rt][1],a[rt][2],a[rt][3], b0,b1r);
    }
  }
}
__device__ __forceinline__ void frag_zero(float c[4][2][4]){
  #pragma unroll
  for(int rt=0;rt<4;rt++)
    #pragma unroll
    for(int ct=0;ct<2;ct++)
      #pragma unroll
      for(int q=0;q<4;q++) c[rt][ct][q]=0.f;
}

// shared gagb body: MMA blocks [0,NTILES) write slab rows <NN; fix blocks recompute dirty b1 rows
__device__ void gagb_body(int role_bid, int lk, const float* __restrict__ W1,
                          int slab, float* sM){
  int tid = threadIdx.x;
  float* Ga = g_Ga + (size_t)slab*ROWS_TOT*HH;
  float* Gb = g_Gb + (size_t)slab*ROWS_TOT*HH;
  if(role_bid < NTILES){
    int w = tid >> 5, lane = tid & 31;
    int gid = lane >> 2, tig = lane & 3;
    int base = role_bid*64;
    {
      int c4 = tid & 31, rs = tid >> 5;
      #pragma unroll
      for(int it=0; it<8; it++){
        int r = it*8 + rs;
        int rg = base + r;
        float4 v = make_float4(0.f,0.f,0.f,0.f);
        if(rg < NN){
          v = __ldg((const float4*)(g_h + (size_t)rg*HH) + c4);
          v.x = tf32r(v.x); v.y = tf32r(v.y); v.z = tf32r(v.z); v.w = tf32r(v.w);
        }
        *(float4*)(sM + r*132 + c4*4) = v;
      }
    }
    __syncthreads();

    const float* Wa = g_Wt + (size_t)(12 + lk*2    )*16384;
    const float* Wb = g_Wt + (size_t)(12 + lk*2 + 1)*16384;
    float c[4][2][4];
    #pragma unroll
    for(int half=0; half<2; half++){
      frag_zero(c);
      mma_accum64(sM, half ? Wb : Wa, w, gid, tig, c);
      float* out = half ? Gb : Ga;
      #pragma unroll
      for(int rt=0;rt<4;rt++){
        #pragma unroll
        for(int ct=0;ct<2;ct++){
          int col0 = w*16 + ct*8 + 2*tig;
          int r0 = role_bid*64 + rt*16 + gid, r1 = r0 + 8;
          if(r0 < NN) *(float2*)(out + (size_t)r0*HH + col0) = make_float2(c[rt][ct][0], c[rt][ct][1]);
          if(r1 < NN) *(float2*)(out + (size_t)r1*HH + col0) = make_float2(c[rt][ct][2], c[rt][ct][3]);
        }
      }
    }
  } else {
    float* sh = sM;
    int j = tid & 127;
    bool act = tid < 128;
    int cnt = g_dcount;
    for(int i = role_bid - NTILES; i < cnt; i += FIXG){
      int n = g_dlist[i];
      if(act) sh[j] = g_h[(size_t)(NN+n)*HH + j];
      __syncthreads();
      if(act){
        float a = 0.f, bv = 0.f;
        #pragma unroll 4
        for(int kk=0; kk<HH; kk++){
          float hv = sh[kk];
          a  = fmaf(hv, __ldg(&W1[kk*HH + j]), a);
          bv = fmaf(hv, __ldg(&W1[(128+kk)*HH + j]), bv);
        }
        Ga[(size_t)(NN+n)*HH + j] = a;
        Gb[(size_t)(NN+n)*HH + j] = bv;
      }
      __syncthreads();
    }
  }
}

// ------------------- weight rounding -------------------
__global__ void k_round(const float* __restrict__ mW1, const float* __restrict__ mW2,
                        const float* __restrict__ pW1, const float* __restrict__ uW1,
                        const float* __restrict__ uW2){
  int gi = blockIdx.x*blockDim.x + threadIdx.x;
  if(gi >= 30*HH*HH) return;
  int slot = gi >> 14;
  int e    = gi & 16383;
  float v;
  if      (slot < 6)  v = mW2[(size_t)slot*16384 + e];
  else if (slot < 12) v = pW1[(size_t)(slot-6)*16384 + e];
  else if (slot < 24){ int s = slot-12; v = mW1[(size_t)(s>>1)*257*HH + (size_t)(s&1)*16384 + e]; }
  else if (slot < 28){ int s = slot-24; v = uW1[(size_t)(s>>1)*2*16384 + (size_t)(s&1)*16384 + e]; }
  else                v = uW2[(size_t)(slot-28)*16384 + e];
  g_Wt[gi] = tf32r(v);
}

// ------------------- prologue kernels -------------------
__global__ void k_deg_zero(){
  int i = blockIdx.x*blockDim.x + threadIdx.x;
  if(i < NBB*NN) g_invdeg[i] = 0.f;
  if(i < NN) g_dirty[i] = 0;
}

// fused: deg_count + init_h(+dynamic) + init_p  (mutually independent roles)
__global__ void k_prolog(const int* __restrict__ edst,
                         const float* __restrict__ base, const float* __restrict__ Win,
                         const float* __restrict__ b_in,
                         const float* __restrict__ x, const int* __restrict__ ent,
                         const float* __restrict__ bp){
  int bid = blockIdx.x, tid = threadIdx.x;
  if(bid < ABLK){
    int i = bid*256 + tid;
    if(i < NBB*EE){
      int k = i / EE;
      atomicAdd(&g_invdeg[k*NN + edst[i]], 1.f);
    }
  } else if(bid < ABLK + NN){
    int n = bid - ABLK;
    int j = tid;
    if(j < HH){
      float acc = __ldg(&b_in[j]);
      #pragma unroll
      for(int d=0; d<DBB; d++)
        acc = fmaf(__ldg(&base[n*DBB+d]), __ldg(&Win[d*HH+j]), acc);
      float h0 = acc, h1 = acc;
      int e0 = __ldg(&ent[0]), e1 = __ldg(&ent[1]);
      if(n == e0){
        float dv = 0.f;
        #pragma unroll
        for(int d=0; d<DINN; d++)
          dv = fmaf(__ldg(&x[d]), __ldg(&Win[(DBB+d)*HH+j]), dv);
        h0 += dv;
      }
      if(n == e1){
        float dv = 0.f;
        #pragma unroll
        for(int d=0; d<DINN; d++)
          dv = fmaf(__ldg(&x[DINN+d]), __ldg(&Win[(DBB+d)*HH+j]), dv);
        h1 += dv;
      }
      g_h[(size_t)n*HH + j] = h0;
      g_h[(size_t)(NN+n)*HH + j] = h1;
    }
  } else {
    int i = (bid - ABLK - NN)*256 + tid;
    if(i < NN*3){ float v = bp[i]; g_p[i] = v; g_p[NN*3+i] = v; }
  }
}

// finalize invdeg; seed dirty + dlist directly from ent (dup entries benign)
__global__ void k_deg_fin(const int* __restrict__ ent){
  int i = blockIdx.x*blockDim.x + threadIdx.x;
  if(i < NBB*NN) g_invdeg[i] = 1.f / fmaxf(g_invdeg[i], 1.f);
  if(i < BB){ g_dirty[ent[i]] = 1; g_dlist[i] = ent[i]; }
  if(i < NBB) g_acnt[i] = 0;
  if(i == 0) g_dcount = BB;
}

// fused: zero msum/pd/newDirty + build affected-edge lists (acnt zeroed by prior launch)
__global__ void k_zerobuild(const int* __restrict__ esrc, const int* __restrict__ edst){
  int bid = blockIdx.x, tid = threadIdx.x;
  if(bid < ZBLK){
    int i = bid*256 + tid;
    if(i < ROWS_TOT*HH) g_msum[i] = 0.f;
    if(i < ROWS_TOT*3)  g_pd[i]   = 0.f;
    if(i < NN)          g_newDirty[i] = 0;
  } else {
    int i = (bid - ZBLK)*256 + tid;
    if(i < NBB*EE){
      int k = i / EE;
      int e = i - k*EE;
      if(g_dirty[esrc[i]] | g_dirty[edst[i]]){
        int pos = atomicAdd(&g_acnt[k], 1);
        g_alist[k*EE + pos] = e;
      }
    }
  }
}

// merge b0 contributions into b1; append newly-dirty nodes to dlist (monotone dcount)
__global__ void k_merge(){
  int i = blockIdx.x*blockDim.x + threadIdx.x;
  if(i < NN*HH) g_msum[(size_t)NN*HH + i] += g_msum[i];
  if(i < NN*3)  g_pd[NN*3 + i] += g_pd[i];
  if(i < NN){
    if(g_newDirty[i] && !g_dirty[i]){
      g_dirty[i] = 1;
      int p = atomicAdd(&g_dcount, 1);
      g_dlist[p] = i;
    }
  }
  if(i < NBB) g_acnt[i] = 0;
}

// standalone gagb (layer start, k=0)
__global__ void __launch_bounds__(256,2) k_gagb_all2(int lk, const float* __restrict__ W1, int slab){
  __shared__ float sM[64*132];
  gagb_body(blockIdx.x, lk, W1, slab, sM);
}

// ------------------- fused edge(k) + delta(k) + gagb(k+1) -------------------
__global__ void __launch_bounds__(256,2) k_edge_delta(
    const float* __restrict__ W1r, const float* __restrict__ b1,
    const float* __restrict__ W2f, const float* __restrict__ b2,
    const float* __restrict__ pW1f,const float* __restrict__ pb1,
    const float* __restrict__ pW2, const float* __restrict__ pb2,
    const int* __restrict__ esrc,  const int* __restrict__ edst,
    int lk, int kdeg, int slab,
    const float* __restrict__ nW1, int nlk){
  __shared__ float sM[64*132];
  __shared__ int   sDst[64];
  __shared__ int   sSrc[64];
  __shared__ float sInv[64];
  __shared__ float sD2[64];
  __shared__ float sRel[64*3];
  __shared__ float sCoef[64];
  __shared__ float sB2[HH];
  __shared__ float sPB1[HH];
  __shared__ float sPW2[HH];

  int tid = threadIdx.x;
  int bid = blockIdx.x;
  const float* Ga = g_Ga + (size_t)slab*ROWS_TOT*HH;
  const float* Gb = g_Gb + (size_t)slab*ROWS_TOT*HH;

  if(bid < ETILES){
    // ======== edge role ========
    int w = tid >> 5, lane = tid & 31;
    int gid = lane >> 2, tig = lane & 3;
    int base = bid*64;

    if(tid < 64){
      int e = base + tid;
      bool v = e < EE;
      int ee = v ? e : 0;
      int ds = edst[ee], sr = esrc[ee];
      float rx = g_p[ds*3+0] - g_p[sr*3+0];
      float ry = g_p[ds*3+1] - g_p[sr*3+1];
      float rz = g_p[ds*3+2] - g_p[sr*3+2];
      sRel[tid*3+0] = rx; sRel[tid*3+1] = ry; sRel[tid*3+2] = rz;
      sD2[tid]  = rx*rx + ry*ry + rz*rz;
      sInv[tid] = v ? g_invdeg[kdeg*NN + ds] : 0.f;
      sDst[tid] = ds;
      sSrc[tid] = sr;
      sCoef[tid] = 0.f;
    }
    if(tid < HH){
      sB2[tid]  = b2[tid];
      sPB1[tid] = pb1[tid];
      sPW2[tid] = pW2[tid];
    }
    __syncthreads();

    {
      int c4 = tid & 31, rs = tid >> 5;
      float4 w4 = __ldg((const float4*)W1r + c4);
      float4 bb = __ldg((const float4*)b1  + c4);
      #pragma unroll
      for(int it=0; it<8; it++){
        int r = it*8 + rs;
        float4 ga = __ldg((const float4*)(Ga + (size_t)sDst[r]*HH) + c4);
        float4 gb = __ldg((const float4*)(Gb + (size_t)sSrc[r]*HH) + c4);
        float d2 = sD2[r];
        float4 o;
        o.x = tf32r(siluf(ga.x + gb.x + d2*w4.x + bb.x));
        o.y = tf32r(siluf(ga.y + gb.y + d2*w4.y + bb.y));
        o.z = tf32r(siluf(ga.z + gb.z + d2*w4.z + bb.z));
        o.w = tf32r(siluf(ga.w + gb.w + d2*w4.w + bb.w));
        *(float4*)(sM + r*132 + c4*4) = o;
      }
    }
    __syncthreads();

    float c[4][2][4];
    frag_zero(c);
    mma_accum64(sM, g_Wt + (size_t)lk*16384, w, gid, tig, c);
    __syncthreads();

    #pragma unroll
    for(int rt=0;rt<4;rt++){
      #pragma unroll
      for(int ct=0;ct<2;ct++){
        int col0 = w*16 + ct*8 + 2*tig;
        int r0 = rt*16 + gid, r1 = r0 + 8;
        float v00 = siluf(c[rt][ct][0] + sB2[col0]);
        float v01 = siluf(c[rt][ct][1] + sB2[col0+1]);
        float v10 = siluf(c[rt][ct][2] + sB2[col0]);
        float v11 = siluf(c[rt][ct][3] + sB2[col0+1]);
        float i0 = sInv[r0], i1 = sInv[r1];
        float s00 = v00*i0, s01 = v01*i0;
        float s10 = v10*i1, s11 = v11*i1;
        float o00 = __shfl_xor_sync(0xffffffffu, s00, 1);
        float o01 = __shfl_xor_sync(0xffffffffu, s01, 1);
        float o10 = __shfl_xor_sync(0xffffffffu, s10, 1);
        float o11 = __shfl_xor_sync(0xffffffffu, s11, 1);
        if((tig & 1) == 0){
          int cb = w*16 + ct*8 + 4*(tig>>1);
          redv4(g_msum + (size_t)sDst[r0]*HH + cb, s00, s01, o00, o01);
          redv4(g_msum + (size_t)sDst[r1]*HH + cb, s10, s11, o10, o11);
        }
        *(float2*)(sM + r0*132 + col0) = make_float2(tf32r(v00), tf32r(v01));
        *(float2*)(sM + r1*132 + col0) = make_float2(tf32r(v10), tf32r(v11));
      }
    }
    __syncthreads();

    frag_zero(c);
    mma_accum64(sM, g_Wt + (size_t)(6+lk)*16384, w, gid, tig, c);

    float rsum[4][2];
    #pragma unroll
    for(int rt=0;rt<4;rt++){ rsum[rt][0]=0.f; rsum[rt][1]=0.f; }
    #pragma unroll
    for(int rt=0;rt<4;rt++){
      #pragma unroll
      for(int ct=0;ct<2;ct++){
        int col0 = w*16 + ct*8 + 2*tig;
        float w0 = sPW2[col0], w1 = sPW2[col0+1];
        float p0 = sPB1[col0], p1 = sPB1[col0+1];
        rsum[rt][0] = fmaf(siluf(c[rt][ct][0]+p0), w0,
                      fmaf(siluf(c[rt][ct][1]+p1), w1, rsum[rt][0]));
        rsum[rt][1] = fmaf(siluf(c[rt][ct][2]+p0), w0,
                      fmaf(siluf(c[rt][ct][3]+p1), w1, rsum[rt][1]));
      }
    }
    #pragma unroll
    for(int off=1; off<4; off<<=1){
      #pragma unroll
      for(int rt=0;rt<4;rt++){
        rsum[rt][0] += __shfl_xor_sync(0xffffffffu, rsum[rt][0], off);
        rsum[rt][1] += __shfl_xor_sync(0xffffffffu, rsum[rt][1], off);
      }
    }
    if(tig == 0){
      #pragma unroll
      for(int rt=0;rt<4;rt++){
        atomicAdd(&sCoef[rt*16 + gid],     rsum[rt][0]);
        atomicAdd(&sCoef[rt*16 + 8 + gid], rsum[rt][1]);
      }
    }
    __syncthreads();

    if(tid < 64){
      float s = (sCoef[tid] + __ldg(pb2)) * sInv[tid];
      int row = sDst[tid];
      atomicAdd(&g_pd[row*3+0], sRel[tid*3+0]*s);
      atomicAdd(&g_pd[row*3+1], sRel[tid*3+1]*s);
      atomicAdd(&g_pd[row*3+2], sRel[tid*3+2]*s);
    }
  } else if(bid < ETILES + DELTA_GRID){
    // ======== delta role (clean-node b1 reads redirected to b0 rows) ========
    float (*sm1)[HH] = (float(*)[HH])sM;
    float (*sm2)[HH] = (float(*)[HH])(sM + 2*HH);
    float* sred = sM + 4*HH;
    int j = tid & 127;
    bool act = tid < 128;
    int cnt = g_acnt[kdeg];
    const int* alist = g_alist + (size_t)kdeg*EE;
    for(int idx = bid - ETILES; idx < cnt; idx += DELTA_GRID){
      int ds=0, sr=0; float inv=0.f;
      float rel[2][3];
      if(act){
        int e = alist[idx];
        ds = edst[e]; sr = esrc[e];
        inv = g_invdeg[kdeg*NN + ds];
        int dDirty = g_dirty[ds], sDirty = g_dirty[sr];
        #pragma unroll
        for(int b=0;b<2;b++){
          int dr = b*NN + ds, srr = b*NN + sr;
          rel[b][0] = g_p[dr*3+0] - g_p[srr*3+0];
          rel[b][1] = g_p[dr*3+1] - g_p[srr*3+1];
          rel[b][2] = g_p[dr*3+2] - g_p[srr*3+2];
          float d2 = rel[b][0]*rel[b][0] + rel[b][1]*rel[b][1] + rel[b][2]*rel[b][2];
          int ga_row = (b==1 && !dDirty) ? ds : dr;
          int gb_row = (b==1 && !sDirty) ? sr : srr;
          sm1[b][j] = siluf(Ga[(size_t)ga_row*HH+j] + Gb[(size_t)gb_row*HH+j]
                            + d2*__ldg(&W1r[j]) + __ldg(&b1[j]));
        }
      }
      __syncthreads();
      if(act){
        float acc0 = 0.f, acc1 = 0.f;
        #pragma unroll 4
        for(int k=0;k<HH;k++){
          float w = __ldg(&W2f[k*HH+j]);
          acc0 = fmaf(sm1[0][k], w, acc0);
          acc1 = fmaf(sm1[1][k], w, acc1);
        }
        float bb = __ldg(&b2[j]);
        float m20 = siluf(acc0 + bb);
        float m21 = siluf(acc1 + bb);
        atomicAdd(&g_msum[(size_t)(NN+ds)*HH + j], (m21 - m20)*inv);
        sm2[0][j] = m20; sm2[1][j] = m21;
      }
      __syncthreads();
      if(act){
        float acc0 = 0.f, acc1 = 0.f;
        #pragma unroll 4
        for(int k=0;k<HH;k++){
          float w = __ldg(&pW1f[k*HH+j]);
          acc0 = fmaf(sm2[0][k], w, acc0);
          acc1 = fmaf(sm2[1][k], w, acc1);
        }
        float pb = __ldg(&pb1[j]);
        float w2 = __ldg(&pW2[j]);
        float c0 = siluf(acc0 + pb) * w2;
        float c1 = siluf(acc1 + pb) * w2;
        #pragma unroll
        for(int off=16; off; off>>=1){
          c0 += __shfl_xor_sync(0xffffffffu, c0, off);
          c1 += __shfl_xor_sync(0xffffffffu, c1, off);
        }
        int wwid = j >> 5;
        if((j & 31) == 0){ sred[wwid] = c0; sred[4+wwid] = c1; }
      }
      __syncthreads();
      if(tid == 0){
        float pb2v = __ldg(pb2);
        float coef0 = sred[0]+sred[1]+sred[2]+sred[3] + pb2v;
        float coef1 = sred[4]+sred[5]+sred[6]+sred[7] + pb2v;
        atomicAdd(&g_pd[(NN+ds)*3+0], (rel[1][0]*coef1 - rel[0][0]*coef0)*inv);
        atomicAdd(&g_pd[(NN+ds)*3+1], (rel[1][1]*coef1 - rel[0][1]*coef0)*inv);
        atomicAdd(&g_pd[(NN+ds)*3+2], (rel[1][2]*coef1 - rel[0][2]*coef0)*inv);
        g_newDirty[ds] = 1;
      }
      __syncthreads();
    }
  } else {
    // ======== gagb role for NEXT k (writes other slab — disjoint, race-free) ========
    gagb_body(bid - ETILES - DELTA_GRID, nlk, nW1, slab^1, sM);
  }
}

// ------------------- node update (tf32 MMA b0) + padd + dirty-b1 update fix -------------------
__global__ void __launch_bounds__(256,2) k_update(
    const float* __restrict__ Wu1, const float* __restrict__ bu1,
    const float* __restrict__ Wu2, const float* __restrict__ bu2, int l){
  __shared__ float sM[64*132];
  __shared__ float sB1[HH];
  __shared__ float sB2v[HH];
  int tid = threadIdx.x;
  int bid = blockIdx.x;

  if(bid >= NTILES + PBLK){
    // updfix role: dirty b1 rows, exact fp32 (reads old b1 h + merged b1 msum — disjoint from b0 writes)
    float* sh = sM;
    float* sm = sM + HH;
    float* st = sM + 2*HH;
    int j = tid & 127;
    bool act = tid < 128;
    int cnt = g_dcount;
    for(int i = bid - NTILES - PBLK; i < cnt; i += FIXG){
      int n = g_dlist[i];
      size_t row = (size_t)(NN+n)*HH;
      if(act){ sh[j] = g_h[row + j]; sm[j] = g_msum[row + j]; }
      __syncthreads();
      if(act){
        float acc = __ldg(&bu1[j]);
        #pragma unroll 4
        for(int kk=0; kk<HH; kk++){
          acc = fmaf(sh[kk], __ldg(&Wu1[kk*HH + j]), acc);
          acc = fmaf(sm[kk], __ldg(&Wu1[(128+kk)*HH + j]), acc);
        }
        st[j] = siluf(acc);
      }
      __syncthreads();
      if(act){
        float o = __ldg(&bu2[j]);
        #pragma unroll 4
        for(int kk=0; kk<HH; kk++)
          o = fmaf(st[kk], __ldg(&Wu2[kk*HH + j]), o);
        g_h[row + j] = sh[j] + o;
      }
      __syncthreads();
    }
    return;
  }
  if(bid >= NTILES){
    // padd role: p += pd (pd finalized by merge; nobody reads p in this launch)
    int i = (bid - NTILES)*256 + tid;
    if(i < ROWS_TOT*3) g_p[i] += g_pd[i];
    return;
  }

  int w = tid >> 5, lane = tid & 31;
  int gid = lane >> 2, tig = lane & 3;
  int base = bid*64;
  int c4 = tid & 31, rs = tid >> 5;

  if(tid < HH){ sB1[tid] = bu1[tid]; sB2v[tid] = bu2[tid]; }

  float c[4][2][4];
  frag_zero(c);

  #pragma unroll
  for(int it=0; it<8; it++){
    int r = it*8 + rs;
    int rg = base + r;
    float4 v = make_float4(0.f,0.f,0.f,0.f);
    if(rg < NN){
      v = __ldg((const float4*)(g_h + (size_t)rg*HH) + c4);
      v.x = tf32r(v.x); v.y = tf32r(v.y); v.z = tf32r(v.z); v.w = tf32r(v.w);
    }
    *(float4*)(sM + r*132 + c4*4) = v;
  }
  __syncthreads();
  mma_accum64(sM, g_Wt + (size_t)(24 + l*2)*16384, w, gid, tig, c);
  __syncthreads();

  #pragma unroll
  for(int it=0; it<8; it++){
    int r = it*8 + rs;
    int rg = base + r;
    float4 v = make_float4(0.f,0.f,0.f,0.f);
    if(rg < NN){
      v = __ldg((const float4*)(g_msum + (size_t)rg*HH) + c4);
      v.x = tf32r(v.x); v.y = tf32r(v.y); v.z = tf32r(v.z); v.w = tf32r(v.w);
    }
    *(float4*)(sM + r*132 + c4*4) = v;
  }
  __syncthreads();
  mma_accum64(sM, g_Wt + (size_t)(24 + l*2 + 1)*16384, w, gid, tig, c);
  __syncthreads();

  #pragma unroll
  for(int rt=0;rt<4;rt++){
    #pragma unroll
    for(int ct=0;ct<2;ct++){
      int col0 = w*16 + ct*8 + 2*tig;
      int r0 = rt*16 + gid, r1 = r0 + 8;
      *(float2*)(sM + r0*132 + col0) = make_float2(
          tf32r(siluf(c[rt][ct][0] + sB1[col0])),
          tf32r(siluf(c[rt][ct][1] + sB1[col0+1])));
      *(float2*)(sM + r1*132 + col0) = make_float2(
          tf32r(siluf(c[rt][ct][2] + sB1[col0])),
          tf32r(siluf(c[rt][ct][3] + sB1[col0+1])));
    }
  }
  __syncthreads();

  frag_zero(c);
  mma_accum64(sM, g_Wt + (size_t)(28 + l)*16384, w, gid, tig, c);

  #pragma unroll
  for(int rt=0;rt<4;rt++){
    #pragma unroll
    for(int ct=0;ct<2;ct++){
      int col0 = w*16 + ct*8 + 2*tig;
      int r0 = base + rt*16 + gid, r1 = r0 + 8;
      if(r0 < NN){
        float2 hv = *(float2*)(g_h + (size_t)r0*HH + col0);
        hv.x += c[rt][ct][0] + sB2v[col0];
        hv.y += c[rt][ct][1] + sB2v[col0+1];
        *(float2*)(g_h + (size_t)r0*HH + col0) = hv;
      }
      if(r1 < NN){
        float2 hv = *(float2*)(g_h + (size_t)r1*HH + col0);
        hv.x += c[rt][ct][2] + sB2v[col0];
        hv.y += c[rt][ct][3] + sB2v[col0+1];
        *(float2*)(g_h + (size_t)r1*HH + col0) = hv;
      }
    }
  }
}

// clean b1 h rows: bitwise copy from updated b0 (must follow k_update)
__global__ void k_copy(){
  int idx = blockIdx.x*blockDim.x + threadIdx.x;
  if(idx >= NN*32) return;
  int c4 = idx & 31;
  int n  = idx >> 5;
  if(g_dirty[n]) return;
  ((float4*)(g_h + (size_t)(NN+n)*HH))[c4] = ((const float4*)(g_h + (size_t)n*HH))[c4];
}

// ------------------- readout -------------------
__global__ void k_readout(const float* __restrict__ W1, const float* __restrict__ b1,
                          const float* __restrict__ W2, const float* __restrict__ b2,
                          const int* __restrict__ ent, float* __restrict__ out){
  __shared__ float se[HH];
  __shared__ float sred[HH];
  int j = threadIdx.x;
  for(int b=0; b<BB; b++){
    int row = b*NN + ent[b];
    se[j] = g_h[(size_t)row*HH + j];
    __syncthreads();
    float acc = b1[j];
    #pragma unroll 4
    for(int i=0;i<HH;i++) acc = fmaf(se[i], W1[i*HH+j], acc);
    sred[j] = siluf(acc) * W2[j];
    __syncthreads();
    for(int s=64; s>0; s>>=1){
      if(j<s) sred[j] += sred[j+s];
      __syncthreads();
    }
    if(j==0) out[b] = sred[0] + b2[0];
    __syncthreads();
  }
}

// ------------------- launch -------------------
extern "C" void kernel_launch(void* const* d_in, const int* in_sizes, int n_in,
                              void* d_out, int out_size){
  (void)in_sizes; (void)n_in; (void)out_size;
  const float* x     = (const float*)d_in[0];
  const float* basef = (const float*)d_in[1];
  const float* basep = (const float*)d_in[2];
  const float* Win   = (const float*)d_in[3];
  const float* b_in  = (const float*)d_in[4];
  const float* mW1   = (const float*)d_in[5];
  const float* mb1   = (const float*)d_in[6];
  const float* mW2   = (const float*)d_in[7];
  const float* mb2   = (const float*)d_in[8];
  const float* pW1   = (const float*)d_in[9];
  const float* pb1   = (const float*)d_in[10];
  const float* pW2   = (const float*)d_in[11];
  const float* pb2   = (const float*)d_in[12];
  const float* uW1   = (const float*)d_in[13];
  const float* ub1   = (const float*)d_in[14];
  const float* uW2   = (const float*)d_in[15];
  const float* ub2   = (const float*)d_in[16];
  const float* oW1   = (const float*)d_in[17];
  const float* ob1   = (const float*)d_in[18];
  const float* oW2   = (const float*)d_in[19];
  const float* ob2   = (const float*)d_in[20];
  const int*   ent   = (const int*)d_in[21];
  const int*   esrc  = (const int*)d_in[22];
  const int*   edst  = (const int*)d_in[23];
  float* out = (float*)d_out;

  k_round<<<(30*HH*HH+255)/256, 256>>>(mW1, mW2, pW1, uW1, uW2);
  k_deg_zero<<<(NBB*NN+255)/256, 256>>>();
  k_prolog<<<ABLK + NN + IPB, 256>>>(edst, basef, Win, b_in, x, ent, basep);
  k_deg_fin<<<(NBB*NN+255)/256, 256>>>(ent);

  for(int l=0; l<LL; l++){
    k_zerobuild<<<ZBLK + ABLK, 256>>>(esrc, edst);
    k_gagb_all2<<<NTILES + FIXG, 256>>>(l*NBB, mW1 + (size_t)(l*NBB)*257*HH, 0);
    for(int k=0; k<NBB; k++){
      int lk = l*NBB + k;
      const float* W1lk = mW1 + (size_t)lk*257*HH;
      int have_next = (k+1 < NBB);
      int nlk = lk + 1;
      const float* nW1 = mW1 + (size_t)nlk*257*HH;
      int grid = ETILES + DELTA_GRID + (have_next ? (NTILES + FIXG) : 0);
      k_edge_delta<<<grid, 256>>>(
          W1lk + 256*HH,
          mb1 + (size_t)lk*HH,
          mW2 + (size_t)lk*HH*HH,
          mb2 + (size_t)lk*HH,
          pW1 + (size_t)lk*HH*HH,
          pb1 + (size_t)lk*HH,
          pW2 + (size_t)lk*HH,
          pb2 + lk,
          esrc + (size_t)k*EE,
          edst + (size_t)k*EE,
          lk, k, k & 1,
          nW1, nlk);
    }
    k_merge<<<(NN*HH+255)/256, 256>>>();
    k_update<<<NTILES + PBLK + FIXG, 256>>>(
        uW1 + (size_t)l*2*HH*HH,
        ub1 + (size_t)l*HH,
        uW2 + (size_t)l*HH*HH,
        ub2 + (size_t)l*HH,
        l);
    k_copy<<<CPB, 256>>>();
  }

  k_readout<<<1, 128>>>(oW1, ob1, oW2, ob2, ent, out);
}

// round 17
// speedup vs baseline: 1.2047x; 1.0088x over previous
#include <cuda_runtime.h>
#include <math.h>

#define BB 2
#define NN 10000
#define EE 100000
#define HH 128
#define DINN 8
#define DBB 16
#define LL 2
#define NBB 3
#define ROWS_TOT (BB*NN)
#define ETILES ((EE+63)/64)
#define NTILES ((NN+63)/64)
#define DELTA_GRID 592
#define FIXG 128
#define ZBLK ((ROWS_TOT*HH+255)/256)
#define ABLK ((NBB*EE+255)/256)
#define PBLK ((ROWS_TOT*3+255)/256)
#define IPB  ((NN*3+255)/256)

// -------- scratch (device globals; no allocation anywhere) --------
__device__ float g_h[ROWS_TOT*HH];
__device__ float g_msum[ROWS_TOT*HH];
__device__ float g_Ga[2*ROWS_TOT*HH];   // double-buffered by k parity
__device__ float g_Gb[2*ROWS_TOT*HH];
__device__ float g_p[ROWS_TOT*3];
__device__ float g_pd[ROWS_TOT*3];
__device__ float g_invdeg[NBB*NN];
__device__ int   g_dirty[NN];
__device__ int   g_newDirty[NN];    // set by delta ONLY for layer-start-clean nodes
__device__ int   g_acnt[NBB];
__device__ int   g_alist[NBB*EE];
__device__ int   g_dcount;          // monotone; seeded by deg_fin, appended by merge
__device__ int   g_dlist[NN];
// tf32-rounded weights, 30 slabs of 128x128:
//  0..5  mW2 | 6..11 pW1 | 12..23 mW1 (lk*2+half) | 24..27 uW1 (l*2+half) | 28..29 uW2
__device__ float g_Wt[30*HH*HH];

// silu(x) = 0.5*x*(1+tanh(x/2)) — 1 MUFU
__device__ __forceinline__ float siluf(float x){
  float t;
  asm("tanh.approx.f32 %0, %1;" : "=f"(t) : "f"(0.5f*x));
  return 0.5f*x*(1.0f+t);
}

__device__ __forceinline__ float tf32r(float x){
  unsigned u;
  asm("cvt.rna.tf32.f32 %0, %1;" : "=r"(u) : "f"(x));
  return __uint_as_float(u);
}

// m16n8k8 tf32 MMA, fp32 accumulate (base PTX, sm_80+)
__device__ __forceinline__ void mma8(float c[4],
    unsigned a0, unsigned a1, unsigned a2, unsigned a3,
    unsigned b0, unsigned b1){
  asm volatile(
    "mma.sync.aligned.m16n8k8.row.col.f32.tf32.tf32.f32 "
    "{%0,%1,%2,%3}, {%4,%5,%6,%7}, {%8,%9}, {%0,%1,%2,%3};"
    : "+f"(c[0]), "+f"(c[1]), "+f"(c[2]), "+f"(c[3])
    : "r"(a0), "r"(a1), "r"(a2), "r"(a3), "r"(b0), "r"(b1));
}

__device__ __forceinline__ void redv4(float* addr, float x, float y, float z, float w){
  asm volatile("red.global.add.v4.f32 [%0], {%1, %2, %3, %4};"
               :: "l"(addr), "f"(x), "f"(y), "f"(z), "f"(w) : "memory");
}

// 64x128 += sM(64xK=128, stride 132, tf32) @ B(128x128 row-major tf32), per-warp 64x16 slab
__device__ __forceinline__ void mma_accum64(const float* __restrict__ sM,
                                            const float* __restrict__ B,
                                            int w, int gid, int tig,
                                            float c[4][2][4]){
  #pragma unroll 4
  for(int k0=0; k0<HH; k0+=8){
    unsigned a[4][4];
    #pragma unroll
    for(int rt=0;rt<4;rt++){
      int r = rt*16;
      a[rt][0] = __float_as_uint(sM[(r+gid)*132   + k0+tig]);
      a[rt][1] = __float_as_uint(sM[(r+8+gid)*132 + k0+tig]);
      a[rt][2] = __float_as_uint(sM[(r+gid)*132   + k0+tig+4]);
      a[rt][3] = __float_as_uint(sM[(r+8+gid)*132 + k0+tig+4]);
    }
    #pragma unroll
    for(int ct=0;ct<2;ct++){
      int n = w*16 + ct*8 + gid;
      unsigned b0 = __float_as_uint(__ldg(&B[(k0+tig)*HH   + n]));
      unsigned b1r = __float_as_uint(__ldg(&B[(k0+tig+4)*HH + n]));
      #pragma unroll
      for(int rt=0;rt<4;rt++)
        mma8(c[rt][ct], a[rt][0],a[rt][1],a[rt][2],a[rt][3], b0,b1r);
    }
  }
}
__device__ __forceinline__ void frag_zero(float c[4][2][4]){
  #pragma unroll
  for(int rt=0;rt<4;rt++)
    #pragma unroll
    for(int ct=0;ct<2;ct++)
      #pragma unroll
      for(int q=0;q<4;q++) c[rt][ct][q]=0.f;
}

// shared gagb body: MMA blocks [0,NTILES) write slab rows <NN; fix blocks recompute dirty b1 rows
__device__ void gagb_body(int role_bid, int lk, const float* __restrict__ W1,
                          int slab, float* sM){
  int tid = threadIdx.x;
  float* Ga = g_Ga + (size_t)slab*ROWS_TOT*HH;
  float* Gb = g_Gb + (size_t)slab*ROWS_TOT*HH;
  if(role_bid < NTILES){
    int w = tid >> 5, lane = tid & 31;
    int gid = lane >> 2, tig = lane & 3;
    int base = role_bid*64;
    {
      int c4 = tid & 31, rs = tid >> 5;
      #pragma unroll
      for(int it=0; it<8; it++){
        int r = it*8 + rs;
        int rg = base + r;
        float4 v = make_float4(0.f,0.f,0.f,0.f);
        if(rg < NN){
          v = __ldg((const float4*)(g_h + (size_t)rg*HH) + c4);
          v.x = tf32r(v.x); v.y = tf32r(v.y); v.z = tf32r(v.z); v.w = tf32r(v.w);
        }
        *(float4*)(sM + r*132 + c4*4) = v;
      }
    }
    __syncthreads();

    const float* Wa = g_Wt + (size_t)(12 + lk*2    )*16384;
    const float* Wb = g_Wt + (size_t)(12 + lk*2 + 1)*16384;
    float c[4][2][4];
    #pragma unroll
    for(int half=0; half<2; half++){
      frag_zero(c);
      mma_accum64(sM, half ? Wb : Wa, w, gid, tig, c);
      float* out = half ? Gb : Ga;
      #pragma unroll
      for(int rt=0;rt<4;rt++){
        #pragma unroll
        for(int ct=0;ct<2;ct++){
          int col0 = w*16 + ct*8 + 2*tig;
          int r0 = role_bid*64 + rt*16 + gid, r1 = r0 + 8;
          if(r0 < NN) *(float2*)(out + (size_t)r0*HH + col0) = make_float2(c[rt][ct][0], c[rt][ct][1]);
          if(r1 < NN) *(float2*)(out + (size_t)r1*HH + col0) = make_float2(c[rt][ct][2], c[rt][ct][3]);
        }
      }
    }
  } else {
    float* sh = sM;
    int j = tid & 127;
    bool act = tid < 128;
    int cnt = g_dcount;
    for(int i = role_bid - NTILES; i < cnt; i += FIXG){
      int n = g_dlist[i];
      if(act) sh[j] = g_h[(size_t)(NN+n)*HH + j];
      __syncthreads();
      if(act){
        float a = 0.f, bv = 0.f;
        #pragma unroll 4
        for(int kk=0; kk<HH; kk++){
          float hv = sh[kk];
          a  = fmaf(hv, __ldg(&W1[kk*HH + j]), a);
          bv = fmaf(hv, __ldg(&W1[(128+kk)*HH + j]), bv);
        }
        Ga[(size_t)(NN+n)*HH + j] = a;
        Gb[(size_t)(NN+n)*HH + j] = bv;
      }
      __syncthreads();
    }
  }
}

// ------------------- weight rounding -------------------
__global__ void k_round(const float* __restrict__ mW1, const float* __restrict__ mW2,
                        const float* __restrict__ pW1, const float* __restrict__ uW1,
                        const float* __restrict__ uW2){
  int gi = blockIdx.x*blockDim.x + threadIdx.x;
  if(gi >= 30*HH*HH) return;
  int slot = gi >> 14;
  int e    = gi & 16383;
  float v;
  if      (slot < 6)  v = mW2[(size_t)slot*16384 + e];
  else if (slot < 12) v = pW1[(size_t)(slot-6)*16384 + e];
  else if (slot < 24){ int s = slot-12; v = mW1[(size_t)(s>>1)*257*HH + (size_t)(s&1)*16384 + e]; }
  else if (slot < 28){ int s = slot-24; v = uW1[(size_t)(s>>1)*2*16384 + (size_t)(s&1)*16384 + e]; }
  else                v = uW2[(size_t)(slot-28)*16384 + e];
  g_Wt[gi] = tf32r(v);
}

// ------------------- prologue kernels -------------------
__global__ void k_deg_zero(){
  int i = blockIdx.x*blockDim.x + threadIdx.x;
  if(i < NBB*NN) g_invdeg[i] = 0.f;
  if(i < NN){ g_dirty[i] = 0; g_newDirty[i] = 0; }
}

// fused: deg_count + init_h(+dynamic) + init_p  (mutually independent roles)
__global__ void k_prolog(const int* __restrict__ edst,
                         const float* __restrict__ base, const float* __restrict__ Win,
                         const float* __restrict__ b_in,
                         const float* __restrict__ x, const int* __restrict__ ent,
                         const float* __restrict__ bp){
  int bid = blockIdx.x, tid = threadIdx.x;
  if(bid < ABLK){
    int i = bid*256 + tid;
    if(i < NBB*EE){
      int k = i / EE;
      atomicAdd(&g_invdeg[k*NN + edst[i]], 1.f);
    }
  } else if(bid < ABLK + NN){
    int n = bid - ABLK;
    int j = tid;
    if(j < HH){
      float acc = __ldg(&b_in[j]);
      #pragma unroll
      for(int d=0; d<DBB; d++)
        acc = fmaf(__ldg(&base[n*DBB+d]), __ldg(&Win[d*HH+j]), acc);
      float h0 = acc, h1 = acc;
      int e0 = __ldg(&ent[0]), e1 = __ldg(&ent[1]);
      if(n == e0){
        float dv = 0.f;
        #pragma unroll
        for(int d=0; d<DINN; d++)
          dv = fmaf(__ldg(&x[d]), __ldg(&Win[(DBB+d)*HH+j]), dv);
        h0 += dv;
      }
      if(n == e1){
        float dv = 0.f;
        #pragma unroll
        for(int d=0; d<DINN; d++)
          dv = fmaf(__ldg(&x[DINN+d]), __ldg(&Win[(DBB+d)*HH+j]), dv);
        h1 += dv;
      }
      g_h[(size_t)n*HH + j] = h0;
      g_h[(size_t)(NN+n)*HH + j] = h1;
    }
  } else {
    int i = (bid - ABLK - NN)*256 + tid;
    if(i < NN*3){ float v = bp[i]; g_p[i] = v; g_p[NN*3+i] = v; }
  }
}

// finalize invdeg; seed dirty + dlist directly from ent (dup entries benign)
__global__ void k_deg_fin(const int* __restrict__ ent){
  int i = blockIdx.x*blockDim.x + threadIdx.x;
  if(i < NBB*NN) g_invdeg[i] = 1.f / fmaxf(g_invdeg[i], 1.f);
  if(i < BB){ g_dirty[ent[i]] = 1; g_dlist[i] = ent[i]; }
  if(i < NBB) g_acnt[i] = 0;
  if(i == 0) g_dcount = BB;
}

// merge b0 contributions into b1; snapshot h for newly-dirty nodes (newDirty set only
// for layer-start-clean nodes, so it's safe to read while dirty is being written);
// append newly-dirty nodes to dlist; reset acnt.
__global__ void k_merge(){
  int i = blockIdx.x*blockDim.x + threadIdx.x;
  if(i < NN*HH){
    g_msum[(size_t)NN*HH + i] += g_msum[i];
    int n = i >> 7;
    if(g_newDirty[n])
      g_h[(size_t)NN*HH + i] = g_h[i];   // b1 h was bitwise == b0 h; snapshot pre-update
  }
  if(i < NN*3)  g_pd[NN*3 + i] += g_pd[i];
  if(i < NN){
    if(g_newDirty[i]){
      g_dirty[i] = 1;
      int p = atomicAdd(&g_dcount, 1);
      g_dlist[p] = i;
    }
  }
  if(i < NBB) g_acnt[i] = 0;
}

// fused: gagb MMA + dirty-fix + zero msum/pd/newDirty + buildA (all-disjoint writes)
__global__ void __launch_bounds__(256,2) k_gagb_all2(int lk, const float* __restrict__ W1,
                                                     int slab,
                                                     const int* __restrict__ esrc,
                                                     const int* __restrict__ edst){
  __shared__ float sM[64*132];
  int bid = blockIdx.x, tid = threadIdx.x;
  if(bid < NTILES + FIXG){
    gagb_body(bid, lk, W1, slab, sM);
  } else if(bid < NTILES + FIXG + ZBLK){
    int i = (bid - NTILES - FIXG)*256 + tid;
    if(i < ROWS_TOT*HH) g_msum[i] = 0.f;
    if(i < ROWS_TOT*3)  g_pd[i]   = 0.f;
    if(i < NN)          g_newDirty[i] = 0;
  } else {
    int i = (bid - NTILES - FIXG - ZBLK)*256 + tid;
    if(i < NBB*EE){
      int k = i / EE;
      int e = i - k*EE;
      if(g_dirty[esrc[i]] | g_dirty[edst[i]]){
        int pos = atomicAdd(&g_acnt[k], 1);
        g_alist[k*EE + pos] = e;
      }
    }
  }
}

// ------------------- fused edge(k) + delta(k) + gagb(k+1) -------------------
__global__ void __launch_bounds__(256,2) k_edge_delta(
    const float* __restrict__ W1r, const float* __restrict__ b1,
    const float* __restrict__ W2f, const float* __restrict__ b2,
    const float* __restrict__ pW1f,const float* __restrict__ pb1,
    const float* __restrict__ pW2, const float* __restrict__ pb2,
    const int* __restrict__ esrc,  const int* __restrict__ edst,
    int lk, int kdeg, int slab,
    const float* __restrict__ nW1, int nlk){
  __shared__ float sM[64*132];
  __shared__ int   sDst[64];
  __shared__ int   sSrc[64];
  __shared__ float sInv[64];
  __shared__ float sD2[64];
  __shared__ float sRel[64*3];
  __shared__ float sCoef[64];
  __shared__ float sB2[HH];
  __shared__ float sPB1[HH];
  __shared__ float sPW2[HH];

  int tid = threadIdx.x;
  int bid = blockIdx.x;
  const float* Ga = g_Ga + (size_t)slab*ROWS_TOT*HH;
  const float* Gb = g_Gb + (size_t)slab*ROWS_TOT*HH;

  if(bid < ETILES){
    // ======== edge role ========
    int w = tid >> 5, lane = tid & 31;
    int gid = lane >> 2, tig = lane & 3;
    int base = bid*64;

    if(tid < 64){
      int e = base + tid;
      bool v = e < EE;
      int ee = v ? e : 0;
      int ds = edst[ee], sr = esrc[ee];
      float rx = g_p[ds*3+0] - g_p[sr*3+0];
      float ry = g_p[ds*3+1] - g_p[sr*3+1];
      float rz = g_p[ds*3+2] - g_p[sr*3+2];
      sRel[tid*3+0] = rx; sRel[tid*3+1] = ry; sRel[tid*3+2] = rz;
      sD2[tid]  = rx*rx + ry*ry + rz*rz;
      sInv[tid] = v ? g_invdeg[kdeg*NN + ds] : 0.f;
      sDst[tid] = ds;
      sSrc[tid] = sr;
      sCoef[tid] = 0.f;
    }
    if(tid < HH){
      sB2[tid]  = b2[tid];
      sPB1[tid] = pb1[tid];
      sPW2[tid] = pW2[tid];
    }
    __syncthreads();

    {
      int c4 = tid & 31, rs = tid >> 5;
      float4 w4 = __ldg((const float4*)W1r + c4);
      float4 bb = __ldg((const float4*)b1  + c4);
      #pragma unroll
      for(int it=0; it<8; it++){
        int r = it*8 + rs;
        float4 ga = __ldg((const float4*)(Ga + (size_t)sDst[r]*HH) + c4);
        float4 gb = __ldg((const float4*)(Gb + (size_t)sSrc[r]*HH) + c4);
        float d2 = sD2[r];
        float4 o;
        o.x = tf32r(siluf(ga.x + gb.x + d2*w4.x + bb.x));
        o.y = tf32r(siluf(ga.y + gb.y + d2*w4.y + bb.y));
        o.z = tf32r(siluf(ga.z + gb.z + d2*w4.z + bb.z));
        o.w = tf32r(siluf(ga.w + gb.w + d2*w4.w + bb.w));
        *(float4*)(sM + r*132 + c4*4) = o;
      }
    }
    __syncthreads();

    float c[4][2][4];
    frag_zero(c);
    mma_accum64(sM, g_Wt + (size_t)lk*16384, w, gid, tig, c);
    __syncthreads();

    #pragma unroll
    for(int rt=0;rt<4;rt++){
      #pragma unroll
      for(int ct=0;ct<2;ct++){
        int col0 = w*16 + ct*8 + 2*tig;
        int r0 = rt*16 + gid, r1 = r0 + 8;
        float v00 = siluf(c[rt][ct][0] + sB2[col0]);
        float v01 = siluf(c[rt][ct][1] + sB2[col0+1]);
        float v10 = siluf(c[rt][ct][2] + sB2[col0]);
        float v11 = siluf(c[rt][ct][3] + sB2[col0+1]);
        float i0 = sInv[r0], i1 = sInv[r1];
        float s00 = v00*i0, s01 = v01*i0;
        float s10 = v10*i1, s11 = v11*i1;
        float o00 = __shfl_xor_sync(0xffffffffu, s00, 1);
        float o01 = __shfl_xor_sync(0xffffffffu, s01, 1);
        float o10 = __shfl_xor_sync(0xffffffffu, s10, 1);
        float o11 = __shfl_xor_sync(0xffffffffu, s11, 1);
        if((tig & 1) == 0){
          int cb = w*16 + ct*8 + 4*(tig>>1);
          redv4(g_msum + (size_t)sDst[r0]*HH + cb, s00, s01, o00, o01);
          redv4(g_msum + (size_t)sDst[r1]*HH + cb, s10, s11, o10, o11);
        }
        *(float2*)(sM + r0*132 + col0) = make_float2(tf32r(v00), tf32r(v01));
        *(float2*)(sM + r1*132 + col0) = make_float2(tf32r(v10), tf32r(v11));
      }
    }
    __syncthreads();

    frag_zero(c);
    mma_accum64(sM, g_Wt + (size_t)(6+lk)*16384, w, gid, tig, c);

    float rsum[4][2];
    #pragma unroll
    for(int rt=0;rt<4;rt++){ rsum[rt][0]=0.f; rsum[rt][1]=0.f; }
    #pragma unroll
    for(int rt=0;rt<4;rt++){
      #pragma unroll
      for(int ct=0;ct<2;ct++){
        int col0 = w*16 + ct*8 + 2*tig;
        float w0 = sPW2[col0], w1 = sPW2[col0+1];
        float p0 = sPB1[col0], p1 = sPB1[col0+1];
        rsum[rt][0] = fmaf(siluf(c[rt][ct][0]+p0), w0,
                      fmaf(siluf(c[rt][ct][1]+p1), w1, rsum[rt][0]));
        rsum[rt][1] = fmaf(siluf(c[rt][ct][2]+p0), w0,
                      fmaf(siluf(c[rt][ct][3]+p1), w1, rsum[rt][1]));
      }
    }
    #pragma unroll
    for(int off=1; off<4; off<<=1){
      #pragma unroll
      for(int rt=0;rt<4;rt++){
        rsum[rt][0] += __shfl_xor_sync(0xffffffffu, rsum[rt][0], off);
        rsum[rt][1] += __shfl_xor_sync(0xffffffffu, rsum[rt][1], off);
      }
    }
    if(tig == 0){
      #pragma unroll
      for(int rt=0;rt<4;rt++){
        atomicAdd(&sCoef[rt*16 + gid],     rsum[rt][0]);
        atomicAdd(&sCoef[rt*16 + 8 + gid], rsum[rt][1]);
      }
    }
    __syncthreads();

    if(tid < 64){
      float s = (sCoef[tid] + __ldg(pb2)) * sInv[tid];
      int row = sDst[tid];
      atomicAdd(&g_pd[row*3+0], sRel[tid*3+0]*s);
      atomicAdd(&g_pd[row*3+1], sRel[tid*3+1]*s);
      atomicAdd(&g_pd[row*3+2], sRel[tid*3+2]*s);
    }
  } else if(bid < ETILES + DELTA_GRID){
    // ======== delta role (clean-node b1 reads redirected to b0 rows) ========
    float (*sm1)[HH] = (float(*)[HH])sM;
    float (*sm2)[HH] = (float(*)[HH])(sM + 2*HH);
    float* sred = sM + 4*HH;
    int j = tid & 127;
    bool act = tid < 128;
    int cnt = g_acnt[kdeg];
    const int* alist = g_alist + (size_t)kdeg*EE;
    for(int idx = bid - ETILES; idx < cnt; idx += DELTA_GRID){
      int ds=0, sr=0; float inv=0.f; int dDirty=0;
      float rel[2][3];
      if(act){
        int e = alist[idx];
        ds = edst[e]; sr = esrc[e];
        inv = g_invdeg[kdeg*NN + ds];
        dDirty = g_dirty[ds];
        int sDirty = g_dirty[sr];
        #pragma unroll
        for(int b=0;b<2;b++){
          int dr = b*NN + ds, srr = b*NN + sr;
          rel[b][0] = g_p[dr*3+0] - g_p[srr*3+0];
          rel[b][1] = g_p[dr*3+1] - g_p[srr*3+1];
          rel[b][2] = g_p[dr*3+2] - g_p[srr*3+2];
          float d2 = rel[b][0]*rel[b][0] + rel[b][1]*rel[b][1] + rel[b][2]*rel[b][2];
          int ga_row = (b==1 && !dDirty) ? ds : dr;
          int gb_row = (b==1 && !sDirty) ? sr : srr;
          sm1[b][j] = siluf(Ga[(size_t)ga_row*HH+j] + Gb[(size_t)gb_row*HH+j]
                            + d2*__ldg(&W1r[j]) + __ldg(&b1[j]));
        }
      }
      __syncthreads();
      if(act){
        float acc0 = 0.f, acc1 = 0.f;
        #pragma unroll 4
        for(int k=0;k<HH;k++){
          float w = __ldg(&W2f[k*HH+j]);
          acc0 = fmaf(sm1[0][k], w, acc0);
          acc1 = fmaf(sm1[1][k], w, acc1);
        }
        float bb = __ldg(&b2[j]);
        float m20 = siluf(acc0 + bb);
        float m21 = siluf(acc1 + bb);
        atomicAdd(&g_msum[(size_t)(NN+ds)*HH + j], (m21 - m20)*inv);
        sm2[0][j] = m20; sm2[1][j] = m21;
      }
      __syncthreads();
      if(act){
        float acc0 = 0.f, acc1 = 0.f;
        #pragma unroll 4
        for(int k=0;k<HH;k++){
          float w = __ldg(&pW1f[k*HH+j]);
          acc0 = fmaf(sm2[0][k], w, acc0);
          acc1 = fmaf(sm2[1][k], w, acc1);
        }
        float pb = __ldg(&pb1[j]);
        float w2 = __ldg(&pW2[j]);
        float c0 = siluf(acc0 + pb) * w2;
        float c1 = siluf(acc1 + pb) * w2;
        #pragma unroll
        for(int off=16; off; off>>=1){
          c0 += __shfl_xor_sync(0xffffffffu, c0, off);
          c1 += __shfl_xor_sync(0xffffffffu, c1, off);
        }
        int wwid = j >> 5;
        if((j & 31) == 0){ sred[wwid] = c0; sred[4+wwid] = c1; }
      }
      __syncthreads();
      if(tid == 0){
        float pb2v = __ldg(pb2);
        float coef0 = sred[0]+sred[1]+sred[2]+sred[3] + pb2v;
        float coef1 = sred[4]+sred[5]+sred[6]+sred[7] + pb2v;
        atomicAdd(&g_pd[(NN+ds)*3+0], (rel[1][0]*coef1 - rel[0][0]*coef0)*inv);
        atomicAdd(&g_pd[(NN+ds)*3+1], (rel[1][1]*coef1 - rel[0][1]*coef0)*inv);
        atomicAdd(&g_pd[(NN+ds)*3+2], (rel[1][2]*coef1 - rel[0][2]*coef0)*inv);
        if(!dDirty) g_newDirty[ds] = 1;   // only layer-start-clean nodes
      }
      __syncthreads();
    }
  } else {
    // ======== gagb role for NEXT k (writes other slab — disjoint, race-free) ========
    gagb_body(bid - ETILES - DELTA_GRID, nlk, nW1, slab^1, sM);
  }
}

// ------------------- node update (tf32 MMA b0) + padd + dirty-b1 update fix -------------------
__global__ void __launch_bounds__(256,2) k_update(
    const float* __restrict__ Wu1, const float* __restrict__ bu1,
    const float* __restrict__ Wu2, const float* __restrict__ bu2, int l){
  __shared__ float sM[64*132];
  __shared__ float sB1[HH];
  __shared__ float sB2v[HH];
  int tid = threadIdx.x;
  int bid = blockIdx.x;

  if(bid >= NTILES + PBLK){
    // updfix role: dirty b1 rows, exact fp32 (reads old/snapshotted b1 h + merged b1 msum)
    float* sh = sM;
    float* sm = sM + HH;
    float* st = sM + 2*HH;
    int j = tid & 127;
    bool act = tid < 128;
    int cnt = g_dcount;
    for(int i = bid - NTILES - PBLK; i < cnt; i += FIXG){
      int n = g_dlist[i];
      size_t row = (size_t)(NN+n)*HH;
      if(act){ sh[j] = g_h[row + j]; sm[j] = g_msum[row + j]; }
      __syncthreads();
      if(act){
        float acc = __ldg(&bu1[j]);
        #pragma unroll 4
        for(int kk=0; kk<HH; kk++){
          acc = fmaf(sh[kk], __ldg(&Wu1[kk*HH + j]), acc);
          acc = fmaf(sm[kk], __ldg(&Wu1[(128+kk)*HH + j]), acc);
        }
        st[j] = siluf(acc);
      }
      __syncthreads();
      if(act){
        float o = __ldg(&bu2[j]);
        #pragma unroll 4
        for(int kk=0; kk<HH; kk++)
          o = fmaf(st[kk], __ldg(&Wu2[kk*HH + j]), o);
        g_h[row + j] = sh[j] + o;
      }
      __syncthreads();
    }
    return;
  }
  if(bid >= NTILES){
    int i = (bid - NTILES)*256 + tid;
    if(i < ROWS_TOT*3) g_p[i] += g_pd[i];
    return;
  }

  int w = tid >> 5, lane = tid & 31;
  int gid = lane >> 2, tig = lane & 3;
  int base = bid*64;
  int c4 = tid & 31, rs = tid >> 5;

  if(tid < HH){ sB1[tid] = bu1[tid]; sB2v[tid] = bu2[tid]; }

  float c[4][2][4];
  frag_zero(c);

  #pragma unroll
  for(int it=0; it<8; it++){
    int r = it*8 + rs;
    int rg = base + r;
    float4 v = make_float4(0.f,0.f,0.f,0.f);
    if(rg < NN){
      v = __ldg((const float4*)(g_h + (size_t)rg*HH) + c4);
      v.x = tf32r(v.x); v.y = tf32r(v.y); v.z = tf32r(v.z); v.w = tf32r(v.w);
    }
    *(float4*)(sM + r*132 + c4*4) = v;
  }
  __syncthreads();
  mma_accum64(sM, g_Wt + (size_t)(24 + l*2)*16384, w, gid, tig, c);
  __syncthreads();

  #pragma unroll
  for(int it=0; it<8; it++){
    int r = it*8 + rs;
    int rg = base + r;
    float4 v = make_float4(0.f,0.f,0.f,0.f);
    if(rg < NN){
      v = __ldg((const float4*)(g_msum + (size_t)rg*HH) + c4);
      v.x = tf32r(v.x); v.y = tf32r(v.y); v.z = tf32r(v.z); v.w = tf32r(v.w);
    }
    *(float4*)(sM + r*132 + c4*4) = v;
  }
  __syncthreads();
  mma_accum64(sM, g_Wt + (size_t)(24 + l*2 + 1)*16384, w, gid, tig, c);
  __syncthreads();

  #pragma unroll
  for(int rt=0;rt<4;rt++){
    #pragma unroll
    for(int ct=0;ct<2;ct++){
      int col0 = w*16 + ct*8 + 2*tig;
      int r0 = rt*16 + gid, r1 = r0 + 8;
      *(float2*)(sM + r0*132 + col0) = make_float2(
          tf32r(siluf(c[rt][ct][0] + sB1[col0])),
          tf32r(siluf(c[rt][ct][1] + sB1[col0+1])));
      *(float2*)(sM + r1*132 + col0) = make_float2(
          tf32r(siluf(c[rt][ct][2] + sB1[col0])),
          tf32r(siluf(c[rt][ct][3] + sB1[col0+1])));
    }
  }
  __syncthreads();

  frag_zero(c);
  mma_accum64(sM, g_Wt + (size_t)(28 + l)*16384, w, gid, tig, c);

  #pragma unroll
  for(int rt=0;rt<4;rt++){
    #pragma unroll
    for(int ct=0;ct<2;ct++){
      int col0 = w*16 + ct*8 + 2*tig;
      int r0 = base + rt*16 + gid, r1 = r0 + 8;
      if(r0 < NN){
        float2 hv = *(float2*)(g_h + (size_t)r0*HH + col0);
        hv.x += c[rt][ct][0] + sB2v[col0];
        hv.y += c[rt][ct][1] + sB2v[col0+1];
        *(float2*)(g_h + (size_t)r0*HH + col0) = hv;
      }
      if(r1 < NN){
        float2 hv = *(float2*)(g_h + (size_t)r1*HH + col0);
        hv.x += c[rt][ct][2] + sB2v[col0];
        hv.y += c[rt][ct][3] + sB2v[col0+1];
        *(float2*)(g_h + (size_t)r1*HH + col0) = hv;
      }
    }
  }
}

// ------------------- readout -------------------
__global__ void k_readout(const float* __restrict__ W1, const float* __restrict__ b1,
                          const float* __restrict__ W2, const float* __restrict__ b2,
                          const int* __restrict__ ent, float* __restrict__ out){
  __shared__ float se[HH];
  __shared__ float sred[HH];
  int j = threadIdx.x;
  for(int b=0; b<BB; b++){
    int row = b*NN + ent[b];
    se[j] = g_h[(size_t)row*HH + j];
    __syncthreads();
    float acc = b1[j];
    #pragma unroll 4
    for(int i=0;i<HH;i++) acc = fmaf(se[i], W1[i*HH+j], acc);
    sred[j] = siluf(acc) * W2[j];
    __syncthreads();
    for(int s=64; s>0; s>>=1){
      if(j<s) sred[j] += sred[j+s];
      __syncthreads();
    }
    if(j==0) out[b] = sred[0] + b2[0];
    __syncthreads();
  }
}

// ------------------- launch -------------------
extern "C" void kernel_launch(void* const* d_in, const int* in_sizes, int n_in,
                              void* d_out, int out_size){
  (void)in_sizes; (void)n_in; (void)out_size;
  const float* x     = (const float*)d_in[0];
  const float* basef = (const float*)d_in[1];
  const float* basep = (const float*)d_in[2];
  const float* Win   = (const float*)d_in[3];
  const float* b_in  = (const float*)d_in[4];
  const float* mW1   = (const float*)d_in[5];
  const float* mb1   = (const float*)d_in[6];
  const float* mW2   = (const float*)d_in[7];
  const float* mb2   = (const float*)d_in[8];
  const float* pW1   = (const float*)d_in[9];
  const float* pb1   = (const float*)d_in[10];
  const float* pW2   = (const float*)d_in[11];
  const float* pb2   = (const float*)d_in[12];
  const float* uW1   = (const float*)d_in[13];
  const float* ub1   = (const float*)d_in[14];
  const float* uW2   = (const float*)d_in[15];
  const float* ub2   = (const float*)d_in[16];
  const float* oW1   = (const float*)d_in[17];
  const float* ob1   = (const float*)d_in[18];
  const float* oW2   = (const float*)d_in[19];
  const float* ob2   = (const float*)d_in[20];
  const int*   ent   = (const int*)d_in[21];
  const int*   esrc  = (const int*)d_in[22];
  const int*   edst  = (const int*)d_in[23];
  float* out = (float*)d_out;

  k_round<<<(30*HH*HH+255)/256, 256>>>(mW1, mW2, pW1, uW1, uW2);
  k_deg_zero<<<(NBB*NN+255)/256, 256>>>();
  k_prolog<<<ABLK + NN + IPB, 256>>>(edst, basef, Win, b_in, x, ent, basep);
  k_deg_fin<<<(NBB*NN+255)/256, 256>>>(ent);

  for(int l=0; l<LL; l++){
    k_gagb_all2<<<NTILES + FIXG + ZBLK + ABLK, 256>>>(
        l*NBB, mW1 + (size_t)(l*NBB)*257*HH, 0, esrc, edst);
    for(int k=0; k<NBB; k++){
      int lk = l*NBB + k;
      const float* W1lk = mW1 + (size_t)lk*257*HH;
      int have_next = (k+1 < NBB);
      int nlk = lk + 1;
      const float* nW1 = mW1 + (size_t)nlk*257*HH;
      int grid = ETILES + DELTA_GRID + (have_next ? (NTILES + FIXG) : 0);
      k_edge_delta<<<grid, 256>>>(
          W1lk + 256*HH,
          mb1 + (size_t)lk*HH,
          mW2 + (size_t)lk*HH*HH,
          mb2 + (size_t)lk*HH,
          pW1 + (size_t)lk*HH*HH,
          pb1 + (size_t)lk*HH,
          pW2 + (size_t)lk*HH,
          pb2 + lk,
          esrc + (size_t)k*EE,
          edst + (size_t)k*EE,
          lk, k, k & 1,
          nW1, nlk);
    }
    k_merge<<<(NN*HH+255)/256, 256>>>();
    k_update<<<NTILES + PBLK + FIXG, 256>>>(
        uW1 + (size_t)l*2*HH*HH,
        ub1 + (size_t)l*HH,
        uW2 + (size_t)l*HH*HH,
        ub2 + (size_t)l*HH,
        l);
  }

  k_readout<<<1, 128>>>(oW1, ob1, oW2, ob2, ent, out);
}